// round 2
// baseline (speedup 1.0000x reference)
#include <cuda_runtime.h>
#include <cstdint>

#define CB 96
#define DDIM 8
#define HDIM 56
#define WDIM 56
#define SP   (DDIM*HDIM*WDIM)   // 25088
#define HWs  (HDIM*WDIM)        // 3136
#define NT   392                // tokens per window
#define NWIN 128                // total windows (B=2, 64 per batch)
#define NTOK (NWIN*NT)          // 50176

// ---------------- scratch (device globals; no allocation) ----------------
__device__ float g_xw  [NTOK*CB];     // LN1 + roll + window partition, (tok, C)
__device__ float g_qkv0[NTOK*288];
__device__ float g_qkv1[NTOK*288];
__device__ float g_o0  [NTOK*CB];     // attention head-concat outputs
__device__ float g_o1  [NTOK*CB];
__device__ float g_p0  [NTOK*CB];     // proj outputs
__device__ float g_p1  [NTOK*CB];
__device__ float g_x1  [2*CB*SP];     // x + attn (channel-major)
__device__ float g_x2  [2*CB*SP];     // LN2(x1)  (channel-major)
__device__ float g_weff[9*CB*CB*3];   // layout [tt=td*3+th][ci][co][tw]
__device__ float g_beff[CB];

// ---------------- LN1 + shift-roll + window partition ----------------
__global__ void k_ln1(const float* __restrict__ x,
                      const float* __restrict__ lw, const float* __restrict__ lb) {
    __shared__ float row[CB*WDIM];
    int bid = blockIdx.x;
    int h = bid % HDIM; int t = bid / HDIM; int d = t & 7; int bb = t >> 3;
    const float* base = x + (size_t)bb*CB*SP + d*HWs + h*WDIM;
    for (int i = threadIdx.x; i < CB*WDIM; i += blockDim.x) {
        int c = i / WDIM, w = i % WDIM;
        row[i] = base[(size_t)c*SP + w];
    }
    __syncthreads();
    if (threadIdx.x < WDIM) {
        int w = threadIdx.x;
        float mu = 0.f;
        for (int c = 0; c < CB; c++) mu += row[c*WDIM + w];
        mu *= (1.0f/CB);
        float var = 0.f;
        for (int c = 0; c < CB; c++) { float dv = row[c*WDIM + w] - mu; var += dv*dv; }
        var *= (1.0f/CB);
        float inv = rsqrtf(var + 1e-5f);
        int ds = (d + 4) & 7;
        int hs = h - 3; if (hs < 0) hs += HDIM;
        int ws = w - 3; if (ws < 0) ws += WDIM;
        int win = bb*64 + (hs/7)*8 + (ws/7);
        int n   = ds*49 + (hs%7)*7 + (ws%7);
        float* op = g_xw + ((size_t)win*NT + n)*CB;
        for (int c = 0; c < CB; c++)
            op[c] = (row[c*WDIM + w] - mu) * inv * lw[c] + lb[c];
    }
}

// ---------------- generic GEMM: Out[M,Ntot] = A[M,96] * Bw[Ntot,96]^T + bias -----
// grid = (M/64, Ntot/96), block = 256
__global__ void k_gemm96(const float* __restrict__ A, const float* __restrict__ Bw,
                         const float* __restrict__ bias, float* __restrict__ Out, int Ntot) {
    __shared__ float As[64][49];
    __shared__ float Bs[96][49];
    int m0 = blockIdx.x * 64;
    int n0 = blockIdx.y * 96;
    int tx = threadIdx.x & 15, ty = threadIdx.x >> 4;
    float acc[4][6];
    #pragma unroll
    for (int r = 0; r < 4; r++)
        #pragma unroll
        for (int c = 0; c < 6; c++) acc[r][c] = 0.f;
    for (int kc = 0; kc < 2; kc++) {
        __syncthreads();
        for (int i = threadIdx.x; i < 64*48; i += 256) {
            int r = i/48, c = i%48;
            As[r][c] = A[(size_t)(m0 + r)*CB + kc*48 + c];
        }
        for (int i = threadIdx.x; i < 96*48; i += 256) {
            int r = i/48, c = i%48;
            Bs[r][c] = Bw[(size_t)(n0 + r)*CB + kc*48 + c];
        }
        __syncthreads();
        #pragma unroll 4
        for (int k = 0; k < 48; k++) {
            float a[4], b[6];
            #pragma unroll
            for (int r = 0; r < 4; r++) a[r] = As[ty*4 + r][k];
            #pragma unroll
            for (int c = 0; c < 6; c++) b[c] = Bs[tx*6 + c][k];
            #pragma unroll
            for (int r = 0; r < 4; r++)
                #pragma unroll
                for (int c = 0; c < 6; c++) acc[r][c] += a[r]*b[c];
        }
    }
    #pragma unroll
    for (int r = 0; r < 4; r++) {
        size_t orow = (size_t)(m0 + ty*4 + r)*Ntot + n0;
        #pragma unroll
        for (int c = 0; c < 6; c++)
            Out[orow + tx*6 + c] = acc[r][c] + bias[n0 + tx*6 + c];
    }
}

// ---------------- windowed attention, one (window, head) per block ----------------
template<int DH, int NH>
__global__ void k_attn(const float* __restrict__ qkv, const float* __restrict__ rpb,
                       float* __restrict__ outp) {
    extern __shared__ float sm[];
    float* Ks  = sm;                 // [DH][393] transposed, padded
    float* Vs  = Ks + DH*393;        // [DH][393]
    float* psm = Vs + DH*393;        // 8 warps * 392
    float* bsm = psm + 8*NT;         // 2535 bias entries for this head
    uchar4* lsm = (uchar4*)(bsm + 2535);  // per-token (d,h,w,label)

    int win = blockIdx.x / NH, hd = blockIdx.x % NH;
    const float* qb = qkv + (size_t)win*NT*288;
    for (int i = threadIdx.x; i < NT*DH; i += blockDim.x) {
        int n = i / DH, d2 = i % DH;
        Ks[d2*393 + n] = qb[n*288 +  96 + hd*DH + d2];
        Vs[d2*393 + n] = qb[n*288 + 192 + hd*DH + d2];
    }
    for (int i = threadIdx.x; i < 2535; i += blockDim.x) bsm[i] = rpb[i*NH + hd];
    int whi = (win & 63) >> 3, wwi = win & 7;
    for (int n = threadIdx.x; n < NT; n += blockDim.x) {
        int dz = n/49, r = n%49, hy = r/7, wl = r%7;
        int gh = whi*7 + hy, gw = wwi*7 + wl;
        int dreg = dz < 4 ? 0 : 1;
        int hreg = gh < 49 ? 0 : (gh < 53 ? 1 : 2);
        int wreg = gw < 49 ? 0 : (gw < 53 ? 1 : 2);
        lsm[n] = make_uchar4((unsigned char)dz, (unsigned char)hy, (unsigned char)wl,
                             (unsigned char)(dreg*9 + hreg*3 + wreg));
    }
    __syncthreads();

    const float scale = rsqrtf((float)DH);
    int warp = threadIdx.x >> 5, lane = threadIdx.x & 31;
    float* pw = psm + warp*NT;
    for (int i = warp; i < NT; i += 8) {
        float ql[DH];
        const float* qp = qb + i*288 + hd*DH;
        #pragma unroll
        for (int d2 = 0; d2 < DH; d2++) ql[d2] = qp[d2] * scale;
        uchar4 ci = lsm[i];
        float sc[13]; float mx = -1e30f;
        #pragma unroll
        for (int s = 0; s < 13; s++) {
            int j = lane + s*32;
            float v = -1e30f;
            if (j < NT) {
                uchar4 cj = lsm[j];
                float dotv = 0.f;
                #pragma unroll
                for (int d2 = 0; d2 < DH; d2++) dotv += ql[d2] * Ks[d2*393 + j];
                int idx = ((int)ci.x - cj.x + 7)*169 + ((int)ci.y - cj.y + 6)*13 + ((int)ci.z - cj.z + 6);
                v = dotv + bsm[idx];
                if (ci.w != cj.w) v -= 100.f;
            }
            sc[s] = v; mx = fmaxf(mx, v);
        }
        #pragma unroll
        for (int o = 16; o; o >>= 1) mx = fmaxf(mx, __shfl_xor_sync(0xffffffffu, mx, o));
        float sum = 0.f;
        #pragma unroll
        for (int s = 0; s < 13; s++) {
            int j = lane + s*32;
            float e = (j < NT) ? __expf(sc[s] - mx) : 0.f;
            sc[s] = e; sum += e;
        }
        #pragma unroll
        for (int o = 16; o; o >>= 1) sum += __shfl_xor_sync(0xffffffffu, sum, o);
        float inv = 1.f / sum;
        #pragma unroll
        for (int s = 0; s < 13; s++) {
            int j = lane + s*32;
            if (j < NT) pw[j] = sc[s] * inv;
        }
        __syncwarp();
        if (lane < DH) {
            float acc = 0.f;
            for (int j = 0; j < NT; j++) acc += pw[j] * Vs[lane*393 + j];
            outp[((size_t)win*NT + i)*CB + hd*DH + lane] = acc;
        }
        __syncwarp();
    }
}

// ---------------- NAS mix + window reverse + unroll + residual ----------------
__global__ void k_combine(const float* __restrict__ x, const float* __restrict__ alpha) {
    int tok = blockIdx.x, c = threadIdx.x;
    float a0 = alpha[0], a1 = alpha[1];
    float m  = fmaxf(a0, a1);
    float e0 = __expf(a0 - m), e1 = __expf(a1 - m);
    float inv = 1.f / (e0 + e1);
    float aw0 = e0*inv, aw1 = e1*inv;
    int win = tok / NT, n = tok % NT;
    int bb = win >> 6; int whi = (win & 63) >> 3, wwi = win & 7;
    int dz = n/49, r = n%49, hy = r/7, wl = r%7;
    int hs = whi*7 + hy, ws = wwi*7 + wl;
    int d0 = (dz + 4) & 7;
    int h0 = hs + 3; if (h0 >= HDIM) h0 -= HDIM;
    int w0 = ws + 3; if (w0 >= WDIM) w0 -= WDIM;
    size_t oi = ((size_t)(bb*CB + c)*DDIM + d0)*HWs + h0*WDIM + w0;
    size_t ti = (size_t)tok*CB + c;
    g_x1[oi] = x[oi] + aw0*g_p0[ti] + aw1*g_p1[ti];
}

// ---------------- LN2 (channel-major in, channel-major out) ----------------
__global__ void k_ln2(const float* __restrict__ lw, const float* __restrict__ lb) {
    __shared__ float row[CB*WDIM];
    __shared__ float s_mu[WDIM], s_inv[WDIM];
    int bid = blockIdx.x;
    int h = bid % HDIM; int t = bid / HDIM; int d = t & 7; int bb = t >> 3;
    size_t base = (size_t)bb*CB*SP + d*HWs + h*WDIM;
    for (int i = threadIdx.x; i < CB*WDIM; i += blockDim.x)
        row[i] = g_x1[base + (size_t)(i/WDIM)*SP + (i%WDIM)];
    __syncthreads();
    if (threadIdx.x < WDIM) {
        int w = threadIdx.x;
        float mu = 0.f;
        for (int c = 0; c < CB; c++) mu += row[c*WDIM + w];
        mu *= (1.0f/CB);
        float var = 0.f;
        for (int c = 0; c < CB; c++) { float dv = row[c*WDIM + w] - mu; var += dv*dv; }
        var *= (1.0f/CB);
        s_mu[w] = mu; s_inv[w] = rsqrtf(var + 1e-5f);
    }
    __syncthreads();
    for (int i = threadIdx.x; i < CB*WDIM; i += blockDim.x) {
        int c = i / WDIM, w = i % WDIM;
        g_x2[base + (size_t)c*SP + w] = (row[i] - s_mu[w]) * s_inv[w] * lw[c] + lb[c];
    }
}

// ---------------- build effective conv weights (NAS fold) ----------------
__global__ void k_weff(const float* __restrict__ c3w, const float* __restrict__ c3b,
                       const float* __restrict__ c1w, const float* __restrict__ c1b,
                       const float* __restrict__ dww, const float* __restrict__ dwb,
                       const float* __restrict__ alpha) {
    float a[4]; float m = -1e30f;
    #pragma unroll
    for (int i = 0; i < 4; i++) { a[i] = alpha[i]; m = fmaxf(m, a[i]); }
    float s = 0.f;
    #pragma unroll
    for (int i = 0; i < 4; i++) { a[i] = __expf(a[i] - m); s += a[i]; }
    float inv = 1.f / s;
    #pragma unroll
    for (int i = 0; i < 4; i++) a[i] *= inv;
    int total = CB*CB*27;
    for (int idx = blockIdx.x*blockDim.x + threadIdx.x; idx < total; idx += gridDim.x*blockDim.x) {
        int t = idx % 27; int rest = idx / 27; int ci = rest % CB; int co = rest / CB;
        float val = a[0] * c3w[idx];
        if (t == 13)            val += a[1] * c1w[co*CB + ci];
        if (ci == co)           val += a[2] * dww[co*27 + t];
        if (t == 13 && ci == co) val += a[3];
        int tt = t / 3, tw = t % 3;
        g_weff[(((size_t)tt*CB + ci)*CB + co)*3 + tw] = val;
    }
    int gid = blockIdx.x*blockDim.x + threadIdx.x;
    if (gid < CB) g_beff[gid] = a[0]*c3b[gid] + a[1]*c1b[gid] + a[2]*dwb[gid];
}

// ---------------- fused FFN conv (W_eff) + residual -> final output ----------------
// block per (b,d,h) row; 384 threads: co = tid>>2 (96), wg = tid&3 (14 w's each)
__global__ void k_ffn(float* __restrict__ out) {
    extern __shared__ float sm[];
    float* insm = sm;             // 96*58
    float* wsm  = sm + CB*58;     // 32*96*3
    int bid = blockIdx.x;
    int h = bid % HDIM; int t = bid / HDIM; int d = t & 7; int bb = t >> 3;
    int co = threadIdx.x >> 2, wg = threadIdx.x & 3, wbase = wg*14;
    float acc[14];
    float bv = g_beff[co];
    #pragma unroll
    for (int k = 0; k < 14; k++) acc[k] = bv;
    for (int td = 0; td < 3; td++) {
        int sd = d + td - 1;
        if (sd < 0 || sd >= DDIM) continue;
        for (int th = 0; th < 3; th++) {
            int sh = h + th - 1;
            if (sh < 0 || sh >= HDIM) continue;
            int tt = td*3 + th;
            __syncthreads();    // protect insm (block-uniform branch)
            size_t ibase = (size_t)bb*CB*SP + sd*HWs + sh*WDIM;
            for (int i = threadIdx.x; i < CB*58; i += blockDim.x) {
                int ci = i / 58, col = i % 58;
                insm[i] = (col == 0 || col == 57) ? 0.f
                        : g_x2[ibase + (size_t)ci*SP + (col - 1)];
            }
            const float* wg_base = g_weff + (size_t)tt*CB*CB*3;
            for (int cb2 = 0; cb2 < 3; cb2++) {
                __syncthreads();
                for (int i = threadIdx.x; i < 32*CB*3; i += blockDim.x)
                    wsm[i] = wg_base[(size_t)cb2*32*CB*3 + i];
                __syncthreads();
                #pragma unroll 4
                for (int cil = 0; cil < 32; cil++) {
                    int ci = cb2*32 + cil;
                    const float* ir = insm + ci*58 + wbase;
                    float rr[16];
                    #pragma unroll
                    for (int k = 0; k < 16; k++) rr[k] = ir[k];
                    const float* wp = wsm + (cil*CB + co)*3;
                    float w0 = wp[0], w1 = wp[1], w2 = wp[2];
                    #pragma unroll
                    for (int k = 0; k < 14; k++)
                        acc[k] += w0*rr[k] + w1*rr[k+1] + w2*rr[k+2];
                }
            }
        }
    }
    size_t obase = ((size_t)(bb*CB + co)*DDIM + d)*HWs + h*WDIM;
    #pragma unroll
    for (int k = 0; k < 14; k++)
        out[obase + wbase + k] = g_x1[obase + wbase + k] + acc[k];
}

// ---------------- host launch ----------------
extern "C" void kernel_launch(void* const* d_in, const int* in_sizes, int n_in,
                              void* d_out, int out_size) {
    (void)in_sizes; (void)n_in; (void)out_size;
    const float* x      = (const float*)d_in[0];
    const float* ln1w   = (const float*)d_in[1];
    const float* ln1b   = (const float*)d_in[2];
    const float* ln2w   = (const float*)d_in[3];
    const float* ln2b   = (const float*)d_in[4];
    const float* qkvw0  = (const float*)d_in[5];
    const float* qkvb0  = (const float*)d_in[6];
    const float* projw0 = (const float*)d_in[7];
    const float* projb0 = (const float*)d_in[8];
    const float* rpb0   = (const float*)d_in[9];
    const float* qkvw1  = (const float*)d_in[10];
    const float* qkvb1  = (const float*)d_in[11];
    const float* projw1 = (const float*)d_in[12];
    const float* projb1 = (const float*)d_in[13];
    const float* rpb1   = (const float*)d_in[14];
    const float* alphaA = (const float*)d_in[15];
    const float* c3w    = (const float*)d_in[16];
    const float* c3b    = (const float*)d_in[17];
    const float* c1w    = (const float*)d_in[18];
    const float* c1b    = (const float*)d_in[19];
    const float* dww    = (const float*)d_in[20];
    const float* dwb    = (const float*)d_in[21];
    const float* alphaF = (const float*)d_in[22];
    float* out = (float*)d_out;

    float *p_xw, *p_q0, *p_q1, *p_o0, *p_o1, *p_p0, *p_p1;
    cudaGetSymbolAddress((void**)&p_xw, g_xw);
    cudaGetSymbolAddress((void**)&p_q0, g_qkv0);
    cudaGetSymbolAddress((void**)&p_q1, g_qkv1);
    cudaGetSymbolAddress((void**)&p_o0, g_o0);
    cudaGetSymbolAddress((void**)&p_o1, g_o1);
    cudaGetSymbolAddress((void**)&p_p0, g_p0);
    cudaGetSymbolAddress((void**)&p_p1, g_p1);

    int smA0 = (2*32*393 + 8*NT + 2535 + NT) * 4;   // DH=32 attention
    int smA1 = (2*16*393 + 8*NT + 2535 + NT) * 4;   // DH=16 attention
    int smF  = (CB*58 + 32*CB*3) * 4;               // ffn conv
    cudaFuncSetAttribute(k_attn<32,3>, cudaFuncAttributeMaxDynamicSharedMemorySize, smA0);
    cudaFuncSetAttribute(k_attn<16,6>, cudaFuncAttributeMaxDynamicSharedMemorySize, smA1);
    cudaFuncSetAttribute(k_ffn,        cudaFuncAttributeMaxDynamicSharedMemorySize, smF);

    // 1) LN1 + roll + window partition
    k_ln1<<<2*DDIM*HDIM, 256>>>(x, ln1w, ln1b);

    // 2) QKV GEMMs (both NAS variants)
    dim3 gq(NTOK/64, 3);
    k_gemm96<<<gq, 256>>>(p_xw, qkvw0, qkvb0, p_q0, 288);
    k_gemm96<<<gq, 256>>>(p_xw, qkvw1, qkvb1, p_q1, 288);

    // 3) windowed attention
    k_attn<32,3><<<NWIN*3, 256, smA0>>>(p_q0, rpb0, p_o0);
    k_attn<16,6><<<NWIN*6, 256, smA1>>>(p_q1, rpb1, p_o1);

    // 4) output projections
    dim3 gp(NTOK/64, 1);
    k_gemm96<<<gp, 256>>>(p_o0, projw0, projb0, p_p0, 96);
    k_gemm96<<<gp, 256>>>(p_o1, projw1, projb1, p_p1, 96);

    // 5) NAS mix + window reverse + un-roll + residual
    k_combine<<<NTOK, CB>>>(x, alphaA);

    // 6) LN2
    k_ln2<<<2*DDIM*HDIM, 256>>>(ln2w, ln2b);

    // 7) fold NAS FFN into one effective conv, then run it + residual
    k_weff<<<128, 256>>>(c3w, c3b, c1w, c1b, dww, dwb, alphaF);
    k_ffn<<<2*DDIM*HDIM, 384, smF>>>(out);
}

// round 3
// speedup vs baseline: 1.1917x; 1.1917x over previous
#include <cuda_runtime.h>
#include <cstdint>

#define CB 96
#define DDIM 8
#define HDIM 56
#define WDIM 56
#define SP   (DDIM*HDIM*WDIM)   // 25088
#define HWs  (HDIM*WDIM)        // 3136
#define NT   392                // tokens per window
#define NWIN 128                // total windows (B=2, 64 per batch)
#define NTOK (NWIN*NT)          // 50176

// ---------------- scratch (device globals; no allocation) ----------------
__device__ float g_xw  [NTOK*CB];     // LN1 + roll + window partition, (tok, C)
__device__ float g_qkv0[NTOK*288];
__device__ float g_qkv1[NTOK*288];
__device__ float g_o0  [NTOK*CB];     // attention head-concat outputs
__device__ float g_o1  [NTOK*CB];
__device__ float g_p0  [NTOK*CB];     // proj outputs
__device__ float g_p1  [NTOK*CB];
__device__ float g_x1  [2*CB*SP];     // x + attn (channel-major)
__device__ float g_x2  [2*CB*SP];     // LN2(x1)  (channel-major)
__device__ float g_weff[9*CB*CB*3];   // layout [tt=td*3+th][ci][co][tw]
__device__ float g_beff[CB];

// ---------------- LN1 + shift-roll + window partition ----------------
__global__ void k_ln1(const float* __restrict__ x,
                      const float* __restrict__ lw, const float* __restrict__ lb) {
    __shared__ float row[CB*WDIM];
    int bid = blockIdx.x;
    int h = bid % HDIM; int t = bid / HDIM; int d = t & 7; int bb = t >> 3;
    const float* base = x + (size_t)bb*CB*SP + d*HWs + h*WDIM;
    for (int i = threadIdx.x; i < CB*WDIM; i += blockDim.x) {
        int c = i / WDIM, w = i % WDIM;
        row[i] = base[(size_t)c*SP + w];
    }
    __syncthreads();
    if (threadIdx.x < WDIM) {
        int w = threadIdx.x;
        float mu = 0.f;
        for (int c = 0; c < CB; c++) mu += row[c*WDIM + w];
        mu *= (1.0f/CB);
        float var = 0.f;
        for (int c = 0; c < CB; c++) { float dv = row[c*WDIM + w] - mu; var += dv*dv; }
        var *= (1.0f/CB);
        float inv = rsqrtf(var + 1e-5f);
        int ds = (d + 4) & 7;
        int hs = h - 3; if (hs < 0) hs += HDIM;
        int ws = w - 3; if (ws < 0) ws += WDIM;
        int win = bb*64 + (hs/7)*8 + (ws/7);
        int n   = ds*49 + (hs%7)*7 + (ws%7);
        float* op = g_xw + ((size_t)win*NT + n)*CB;
        for (int c = 0; c < CB; c++)
            op[c] = (row[c*WDIM + w] - mu) * inv * lw[c] + lb[c];
    }
}

// ---------------- generic GEMM: Out[M,Ntot] = A[M,96] * Bw[Ntot,96]^T + bias -----
__global__ void k_gemm96(const float* __restrict__ A, const float* __restrict__ Bw,
                         const float* __restrict__ bias, float* __restrict__ Out, int Ntot) {
    __shared__ float As[64][49];
    __shared__ float Bs[96][49];
    int m0 = blockIdx.x * 64;
    int n0 = blockIdx.y * 96;
    int tx = threadIdx.x & 15, ty = threadIdx.x >> 4;
    float acc[4][6];
    #pragma unroll
    for (int r = 0; r < 4; r++)
        #pragma unroll
        for (int c = 0; c < 6; c++) acc[r][c] = 0.f;
    for (int kc = 0; kc < 2; kc++) {
        __syncthreads();
        for (int i = threadIdx.x; i < 64*48; i += 256) {
            int r = i/48, c = i%48;
            As[r][c] = A[(size_t)(m0 + r)*CB + kc*48 + c];
        }
        for (int i = threadIdx.x; i < 96*48; i += 256) {
            int r = i/48, c = i%48;
            Bs[r][c] = Bw[(size_t)(n0 + r)*CB + kc*48 + c];
        }
        __syncthreads();
        #pragma unroll 4
        for (int k = 0; k < 48; k++) {
            float a[4], b[6];
            #pragma unroll
            for (int r = 0; r < 4; r++) a[r] = As[ty*4 + r][k];
            #pragma unroll
            for (int c = 0; c < 6; c++) b[c] = Bs[tx*6 + c][k];
            #pragma unroll
            for (int r = 0; r < 4; r++)
                #pragma unroll
                for (int c = 0; c < 6; c++) acc[r][c] += a[r]*b[c];
        }
    }
    #pragma unroll
    for (int r = 0; r < 4; r++) {
        size_t orow = (size_t)(m0 + ty*4 + r)*Ntot + n0;
        #pragma unroll
        for (int c = 0; c < 6; c++)
            Out[orow + tx*6 + c] = acc[r][c] + bias[n0 + tx*6 + c];
    }
}

// ---------------- windowed attention v2: vectorized + row-blocked ----------------
// One (window, head) per block. 8 warps, each warp processes 4 rows at a time.
// Lanes own 4 consecutive key tokens: j = s*128 + lane*4 + {0..3}, s in 0..3.
#define KS_STRIDE 396   // 16B-aligned, conflict-free for lane-consecutive-j LDS.128
#define VS_STRIDE 404   // 16B-aligned, conflict-free for lane-row LDS.128
#define PS_STRIDE 396

template<int DH, int NH>
__global__ void __launch_bounds__(256) k_attn2(const float* __restrict__ qkv,
                                               const float* __restrict__ rpb,
                                               float* __restrict__ outp) {
    extern __shared__ float sm[];
    float* Ks  = sm;                         // [DH][KS_STRIDE]
    float* Vs  = Ks + DH*KS_STRIDE;          // [DH][VS_STRIDE]
    float* psm = Vs + DH*VS_STRIDE;          // [8 warps][4][PS_STRIDE]
    float* bsm = psm + 8*4*PS_STRIDE;        // 2535 bias entries for this head
    unsigned int* lsm = (unsigned int*)(bsm + 2535);   // per-token packed (d,h,w,label)

    int win = blockIdx.x / NH, hd = blockIdx.x % NH;
    const float* qb = qkv + (size_t)win*NT*288;

    for (int i = threadIdx.x; i < NT*DH; i += 256) {
        int n = i / DH, d = i % DH;
        Ks[d*KS_STRIDE + n] = qb[n*288 +  96 + hd*DH + d];
        Vs[d*VS_STRIDE + n] = qb[n*288 + 192 + hd*DH + d];
    }
    for (int i = threadIdx.x; i < 2535; i += 256) bsm[i] = rpb[i*NH + hd];
    {
        int whi = (win & 63) >> 3, wwi = win & 7;
        for (int n = threadIdx.x; n < NT; n += 256) {
            int dz = n/49, r = n%49, hy = r/7, wl = r%7;
            int gh = whi*7 + hy, gw = wwi*7 + wl;
            int dreg = dz < 4 ? 0 : 1;
            int hreg = gh < 49 ? 0 : (gh < 53 ? 1 : 2);
            int wreg = gw < 49 ? 0 : (gw < 53 ? 1 : 2);
            lsm[n] = (unsigned)dz | ((unsigned)hy<<8) | ((unsigned)wl<<16)
                   | ((unsigned)(dreg*9 + hreg*3 + wreg)<<24);
        }
    }
    __syncthreads();

    const float scale = rsqrtf((float)DH);
    int warp = threadIdx.x >> 5, lane = threadIdx.x & 31;
    float* pw = psm + warp*(4*PS_STRIDE);

    for (int i0 = warp*4; i0 < NT; i0 += 32) {
        // -------- QK: sc[r][s*4+jj] = q[i0+r] . k[j] --------
        float sc[4][16];
        #pragma unroll
        for (int r = 0; r < 4; r++)
            #pragma unroll
            for (int t = 0; t < 16; t++) sc[r][t] = 0.f;

        #pragma unroll
        for (int d4 = 0; d4 < DH; d4 += 4) {
            float4 q4[4];
            #pragma unroll
            for (int r = 0; r < 4; r++)
                q4[r] = *(const float4*)(qb + (size_t)(i0+r)*288 + hd*DH + d4);
            #pragma unroll
            for (int s = 0; s < 4; s++) {
                int j = s*128 + lane*4;
                if (j < NT) {
                    float4 k0 = *(const float4*)(Ks + (d4+0)*KS_STRIDE + j);
                    float4 k1 = *(const float4*)(Ks + (d4+1)*KS_STRIDE + j);
                    float4 k2 = *(const float4*)(Ks + (d4+2)*KS_STRIDE + j);
                    float4 k3 = *(const float4*)(Ks + (d4+3)*KS_STRIDE + j);
                    #pragma unroll
                    for (int r = 0; r < 4; r++) {
                        sc[r][s*4+0] += q4[r].x*k0.x + q4[r].y*k1.x + q4[r].z*k2.x + q4[r].w*k3.x;
                        sc[r][s*4+1] += q4[r].x*k0.y + q4[r].y*k1.y + q4[r].z*k2.y + q4[r].w*k3.y;
                        sc[r][s*4+2] += q4[r].x*k0.z + q4[r].y*k1.z + q4[r].z*k2.z + q4[r].w*k3.z;
                        sc[r][s*4+3] += q4[r].x*k0.w + q4[r].y*k1.w + q4[r].z*k2.w + q4[r].w*k3.w;
                    }
                }
            }
        }

        // -------- bias + region mask + scale --------
        unsigned ci_[4];
        #pragma unroll
        for (int r = 0; r < 4; r++) ci_[r] = lsm[i0 + r];
        #pragma unroll
        for (int s = 0; s < 4; s++) {
            #pragma unroll
            for (int jj = 0; jj < 4; jj++) {
                int j = s*128 + lane*4 + jj;
                if (j < NT) {
                    unsigned cj = lsm[j];
                    int jx = (int)(cj & 255), jy = (int)((cj>>8)&255), jz = (int)((cj>>16)&255);
                    #pragma unroll
                    for (int r = 0; r < 4; r++) {
                        unsigned ci = ci_[r];
                        int dd = (int)(ci & 255)       - jx + 7;
                        int dh_= (int)((ci>>8)&255)    - jy + 6;
                        int dw = (int)((ci>>16)&255)   - jz + 6;
                        float b = bsm[dd*169 + dh_*13 + dw];
                        float v = sc[r][s*4+jj]*scale + b;
                        if ((ci ^ cj) >> 24) v -= 100.f;
                        sc[r][s*4+jj] = v;
                    }
                } else {
                    #pragma unroll
                    for (int r = 0; r < 4; r++) sc[r][s*4+jj] = -1e30f;
                }
            }
        }

        // -------- softmax (per row, across lanes) --------
        float inv_[4];
        #pragma unroll
        for (int r = 0; r < 4; r++) {
            float mx = -1e30f;
            #pragma unroll
            for (int t = 0; t < 16; t++) mx = fmaxf(mx, sc[r][t]);
            #pragma unroll
            for (int o = 16; o; o >>= 1) mx = fmaxf(mx, __shfl_xor_sync(0xffffffffu, mx, o));
            float sum = 0.f;
            #pragma unroll
            for (int t = 0; t < 16; t++) { float e = __expf(sc[r][t] - mx); sc[r][t] = e; sum += e; }
            #pragma unroll
            for (int o = 16; o; o >>= 1) sum += __shfl_xor_sync(0xffffffffu, sum, o);
            inv_[r] = 1.f / sum;
        }

        // -------- store P to per-warp smem --------
        #pragma unroll
        for (int r = 0; r < 4; r++) {
            #pragma unroll
            for (int s = 0; s < 4; s++) {
                int j = s*128 + lane*4;
                if (j < NT) {
                    float4 p4 = make_float4(sc[r][s*4+0]*inv_[r], sc[r][s*4+1]*inv_[r],
                                            sc[r][s*4+2]*inv_[r], sc[r][s*4+3]*inv_[r]);
                    *(float4*)(pw + r*PS_STRIDE + j) = p4;
                }
            }
        }
        __syncwarp();

        // -------- PV --------
        if (DH == 32) {
            float a0 = 0.f, a1 = 0.f, a2 = 0.f, a3 = 0.f;
            const float* vrow = Vs + lane*VS_STRIDE;
            #pragma unroll 2
            for (int j = 0; j < NT; j += 4) {
                float4 v  = *(const float4*)(vrow + j);
                float4 p0 = *(const float4*)(pw + 0*PS_STRIDE + j);
                float4 p1 = *(const float4*)(pw + 1*PS_STRIDE + j);
                float4 p2 = *(const float4*)(pw + 2*PS_STRIDE + j);
                float4 p3 = *(const float4*)(pw + 3*PS_STRIDE + j);
                a0 += p0.x*v.x + p0.y*v.y + p0.z*v.z + p0.w*v.w;
                a1 += p1.x*v.x + p1.y*v.y + p1.z*v.z + p1.w*v.w;
                a2 += p2.x*v.x + p2.y*v.y + p2.z*v.z + p2.w*v.w;
                a3 += p3.x*v.x + p3.y*v.y + p3.z*v.z + p3.w*v.w;
            }
            size_t ob = ((size_t)win*NT + i0)*CB + hd*32 + lane;
            outp[ob + 0*CB] = a0;
            outp[ob + 1*CB] = a1;
            outp[ob + 2*CB] = a2;
            outp[ob + 3*CB] = a3;
        } else {
            int half = lane >> 4, d = lane & 15;
            float aA = 0.f, aB = 0.f;     // rows 2*half, 2*half+1
            const float* vrow = Vs + d*VS_STRIDE;
            const float* pa = pw + (2*half + 0)*PS_STRIDE;
            const float* pb = pw + (2*half + 1)*PS_STRIDE;
            #pragma unroll 2
            for (int j = 0; j < NT; j += 4) {
                float4 v  = *(const float4*)(vrow + j);
                float4 p0 = *(const float4*)(pa + j);
                float4 p1 = *(const float4*)(pb + j);
                aA += p0.x*v.x + p0.y*v.y + p0.z*v.z + p0.w*v.w;
                aB += p1.x*v.x + p1.y*v.y + p1.z*v.z + p1.w*v.w;
            }
            size_t ob = ((size_t)win*NT + i0 + 2*half)*CB + hd*16 + d;
            outp[ob]      = aA;
            outp[ob + CB] = aB;
        }
        __syncwarp();
    }
}

// ---------------- NAS mix + window reverse + unroll + residual ----------------
__global__ void k_combine(const float* __restrict__ x, const float* __restrict__ alpha) {
    int tok = blockIdx.x, c = threadIdx.x;
    float a0 = alpha[0], a1 = alpha[1];
    float m  = fmaxf(a0, a1);
    float e0 = __expf(a0 - m), e1 = __expf(a1 - m);
    float inv = 1.f / (e0 + e1);
    float aw0 = e0*inv, aw1 = e1*inv;
    int win = tok / NT, n = tok % NT;
    int bb = win >> 6; int whi = (win & 63) >> 3, wwi = win & 7;
    int dz = n/49, r = n%49, hy = r/7, wl = r%7;
    int hs = whi*7 + hy, ws = wwi*7 + wl;
    int d0 = (dz + 4) & 7;
    int h0 = hs + 3; if (h0 >= HDIM) h0 -= HDIM;
    int w0 = ws + 3; if (w0 >= WDIM) w0 -= WDIM;
    size_t oi = ((size_t)(bb*CB + c)*DDIM + d0)*HWs + h0*WDIM + w0;
    size_t ti = (size_t)tok*CB + c;
    g_x1[oi] = x[oi] + aw0*g_p0[ti] + aw1*g_p1[ti];
}

// ---------------- LN2 (channel-major in, channel-major out) ----------------
__global__ void k_ln2(const float* __restrict__ lw, const float* __restrict__ lb) {
    __shared__ float row[CB*WDIM];
    __shared__ float s_mu[WDIM], s_inv[WDIM];
    int bid = blockIdx.x;
    int h = bid % HDIM; int t = bid / HDIM; int d = t & 7; int bb = t >> 3;
    size_t base = (size_t)bb*CB*SP + d*HWs + h*WDIM;
    for (int i = threadIdx.x; i < CB*WDIM; i += blockDim.x)
        row[i] = g_x1[base + (size_t)(i/WDIM)*SP + (i%WDIM)];
    __syncthreads();
    if (threadIdx.x < WDIM) {
        int w = threadIdx.x;
        float mu = 0.f;
        for (int c = 0; c < CB; c++) mu += row[c*WDIM + w];
        mu *= (1.0f/CB);
        float var = 0.f;
        for (int c = 0; c < CB; c++) { float dv = row[c*WDIM + w] - mu; var += dv*dv; }
        var *= (1.0f/CB);
        s_mu[w] = mu; s_inv[w] = rsqrtf(var + 1e-5f);
    }
    __syncthreads();
    for (int i = threadIdx.x; i < CB*WDIM; i += blockDim.x) {
        int c = i / WDIM, w = i % WDIM;
        g_x2[base + (size_t)c*SP + w] = (row[i] - s_mu[w]) * s_inv[w] * lw[c] + lb[c];
    }
}

// ---------------- build effective conv weights (NAS fold) ----------------
__global__ void k_weff(const float* __restrict__ c3w, const float* __restrict__ c3b,
                       const float* __restrict__ c1w, const float* __restrict__ c1b,
                       const float* __restrict__ dww, const float* __restrict__ dwb,
                       const float* __restrict__ alpha) {
    float a[4]; float m = -1e30f;
    #pragma unroll
    for (int i = 0; i < 4; i++) { a[i] = alpha[i]; m = fmaxf(m, a[i]); }
    float s = 0.f;
    #pragma unroll
    for (int i = 0; i < 4; i++) { a[i] = __expf(a[i] - m); s += a[i]; }
    float inv = 1.f / s;
    #pragma unroll
    for (int i = 0; i < 4; i++) a[i] *= inv;
    int total = CB*CB*27;
    for (int idx = blockIdx.x*blockDim.x + threadIdx.x; idx < total; idx += gridDim.x*blockDim.x) {
        int t = idx % 27; int rest = idx / 27; int ci = rest % CB; int co = rest / CB;
        float val = a[0] * c3w[idx];
        if (t == 13)            val += a[1] * c1w[co*CB + ci];
        if (ci == co)           val += a[2] * dww[co*27 + t];
        if (t == 13 && ci == co) val += a[3];
        int tt = t / 3, tw = t % 3;
        g_weff[(((size_t)tt*CB + ci)*CB + co)*3 + tw] = val;
    }
    int gid = blockIdx.x*blockDim.x + threadIdx.x;
    if (gid < CB) g_beff[gid] = a[0]*c3b[gid] + a[1]*c1b[gid] + a[2]*dwb[gid];
}

// ---------------- fused FFN conv (W_eff) + residual -> final output ----------------
__global__ void k_ffn(float* __restrict__ out) {
    extern __shared__ float sm[];
    float* insm = sm;             // 96*58
    float* wsm  = sm + CB*58;     // 32*96*3
    int bid = blockIdx.x;
    int h = bid % HDIM; int t = bid / HDIM; int d = t & 7; int bb = t >> 3;
    int co = threadIdx.x >> 2, wg = threadIdx.x & 3, wbase = wg*14;
    float acc[14];
    float bv = g_beff[co];
    #pragma unroll
    for (int k = 0; k < 14; k++) acc[k] = bv;
    for (int td = 0; td < 3; td++) {
        int sd = d + td - 1;
        if (sd < 0 || sd >= DDIM) continue;
        for (int th = 0; th < 3; th++) {
            int sh = h + th - 1;
            if (sh < 0 || sh >= HDIM) continue;
            int tt = td*3 + th;
            __syncthreads();    // protect insm (block-uniform branch)
            size_t ibase = (size_t)bb*CB*SP + sd*HWs + sh*WDIM;
            for (int i = threadIdx.x; i < CB*58; i += blockDim.x) {
                int ci = i / 58, col = i % 58;
                insm[i] = (col == 0 || col == 57) ? 0.f
                        : g_x2[ibase + (size_t)ci*SP + (col - 1)];
            }
            const float* wg_base = g_weff + (size_t)tt*CB*CB*3;
            for (int cb2 = 0; cb2 < 3; cb2++) {
                __syncthreads();
                for (int i = threadIdx.x; i < 32*CB*3; i += blockDim.x)
                    wsm[i] = wg_base[(size_t)cb2*32*CB*3 + i];
                __syncthreads();
                #pragma unroll 4
                for (int cil = 0; cil < 32; cil++) {
                    int ci = cb2*32 + cil;
                    const float* ir = insm + ci*58 + wbase;
                    float rr[16];
                    #pragma unroll
                    for (int k = 0; k < 16; k++) rr[k] = ir[k];
                    const float* wp = wsm + (cil*CB + co)*3;
                    float w0 = wp[0], w1 = wp[1], w2 = wp[2];
                    #pragma unroll
                    for (int k = 0; k < 14; k++)
                        acc[k] += w0*rr[k] + w1*rr[k+1] + w2*rr[k+2];
                }
            }
        }
    }
    size_t obase = ((size_t)(bb*CB + co)*DDIM + d)*HWs + h*WDIM;
    #pragma unroll
    for (int k = 0; k < 14; k++)
        out[obase + wbase + k] = g_x1[obase + wbase + k] + acc[k];
}

// ---------------- host launch ----------------
extern "C" void kernel_launch(void* const* d_in, const int* in_sizes, int n_in,
                              void* d_out, int out_size) {
    (void)in_sizes; (void)n_in; (void)out_size;
    const float* x      = (const float*)d_in[0];
    const float* ln1w   = (const float*)d_in[1];
    const float* ln1b   = (const float*)d_in[2];
    const float* ln2w   = (const float*)d_in[3];
    const float* ln2b   = (const float*)d_in[4];
    const float* qkvw0  = (const float*)d_in[5];
    const float* qkvb0  = (const float*)d_in[6];
    const float* projw0 = (const float*)d_in[7];
    const float* projb0 = (const float*)d_in[8];
    const float* rpb0   = (const float*)d_in[9];
    const float* qkvw1  = (const float*)d_in[10];
    const float* qkvb1  = (const float*)d_in[11];
    const float* projw1 = (const float*)d_in[12];
    const float* projb1 = (const float*)d_in[13];
    const float* rpb1   = (const float*)d_in[14];
    const float* alphaA = (const float*)d_in[15];
    const float* c3w    = (const float*)d_in[16];
    const float* c3b    = (const float*)d_in[17];
    const float* c1w    = (const float*)d_in[18];
    const float* c1b    = (const float*)d_in[19];
    const float* dww    = (const float*)d_in[20];
    const float* dwb    = (const float*)d_in[21];
    const float* alphaF = (const float*)d_in[22];
    float* out = (float*)d_out;

    float *p_xw, *p_q0, *p_q1, *p_o0, *p_o1, *p_p0, *p_p1;
    cudaGetSymbolAddress((void**)&p_xw, g_xw);
    cudaGetSymbolAddress((void**)&p_q0, g_qkv0);
    cudaGetSymbolAddress((void**)&p_q1, g_qkv1);
    cudaGetSymbolAddress((void**)&p_o0, g_o0);
    cudaGetSymbolAddress((void**)&p_o1, g_o1);
    cudaGetSymbolAddress((void**)&p_p0, g_p0);
    cudaGetSymbolAddress((void**)&p_p1, g_p1);

    int smA0 = (32*KS_STRIDE + 32*VS_STRIDE + 8*4*PS_STRIDE + 2535 + 392) * 4;  // ~161 KB
    int smA1 = (16*KS_STRIDE + 16*VS_STRIDE + 8*4*PS_STRIDE + 2535 + 392) * 4;  // ~111 KB
    int smF  = (CB*58 + 32*CB*3) * 4;
    cudaFuncSetAttribute(k_attn2<32,3>, cudaFuncAttributeMaxDynamicSharedMemorySize, smA0);
    cudaFuncSetAttribute(k_attn2<16,6>, cudaFuncAttributeMaxDynamicSharedMemorySize, smA1);
    cudaFuncSetAttribute(k_ffn,         cudaFuncAttributeMaxDynamicSharedMemorySize, smF);

    // 1) LN1 + roll + window partition
    k_ln1<<<2*DDIM*HDIM, 256>>>(x, ln1w, ln1b);

    // 2) QKV GEMMs (both NAS variants)
    dim3 gq(NTOK/64, 3);
    k_gemm96<<<gq, 256>>>(p_xw, qkvw0, qkvb0, p_q0, 288);
    k_gemm96<<<gq, 256>>>(p_xw, qkvw1, qkvb1, p_q1, 288);

    // 3) windowed attention (vectorized, row-blocked)
    k_attn2<32,3><<<NWIN*3, 256, smA0>>>(p_q0, rpb0, p_o0);
    k_attn2<16,6><<<NWIN*6, 256, smA1>>>(p_q1, rpb1, p_o1);

    // 4) output projections
    dim3 gp(NTOK/64, 1);
    k_gemm96<<<gp, 256>>>(p_o0, projw0, projb0, p_p0, 96);
    k_gemm96<<<gp, 256>>>(p_o1, projw1, projb1, p_p1, 96);

    // 5) NAS mix + window reverse + un-roll + residual
    k_combine<<<NTOK, CB>>>(x, alphaA);

    // 6) LN2
    k_ln2<<<2*DDIM*HDIM, 256>>>(ln2w, ln2b);

    // 7) fold NAS FFN into one effective conv, then run it + residual
    k_weff<<<128, 256>>>(c3w, c3b, c1w, c1b, dww, dwb, alphaF);
    k_ffn<<<2*DDIM*HDIM, 384, smF>>>(out);
}

// round 4
// speedup vs baseline: 1.2632x; 1.0600x over previous
#include <cuda_runtime.h>
#include <cstdint>

#define CB 96
#define DDIM 8
#define HDIM 56
#define WDIM 56
#define SP   (DDIM*HDIM*WDIM)   // 25088
#define HWs  (HDIM*WDIM)        // 3136
#define NT   392                // tokens per window
#define NWIN 128                // total windows (B=2, 64 per batch)
#define NTOK (NWIN*NT)          // 50176

typedef unsigned long long u64;

// ---------------- packed f32x2 helpers ----------------
__device__ __forceinline__ u64 pk2(float lo, float hi) {
    u64 r;
    asm("mov.b64 %0, {%1, %2};" : "=l"(r)
        : "r"(__float_as_uint(lo)), "r"(__float_as_uint(hi)));
    return r;
}
__device__ __forceinline__ void upk(u64 v, float& lo, float& hi) {
    unsigned a, b;
    asm("mov.b64 {%0, %1}, %2;" : "=r"(a), "=r"(b) : "l"(v));
    lo = __uint_as_float(a); hi = __uint_as_float(b);
}
__device__ __forceinline__ void fma2(u64& d, u64 a, u64 b) {
    asm("fma.rn.f32x2 %0, %1, %2, %0;" : "+l"(d) : "l"(a), "l"(b));
}
__device__ __forceinline__ u64 add2(u64 a, u64 b) {
    u64 d; asm("add.rn.f32x2 %0, %1, %2;" : "=l"(d) : "l"(a), "l"(b)); return d;
}

// ---------------- scratch (device globals; no allocation) ----------------
__device__ float g_xw  [NTOK*CB];
__device__ float g_qkv0[NTOK*288];
__device__ float g_qkv1[NTOK*288];
__device__ float g_o0  [NTOK*CB];
__device__ float g_o1  [NTOK*CB];
__device__ float g_p0  [NTOK*CB];
__device__ float g_p1  [NTOK*CB];
__device__ float g_x1  [2*CB*SP];
__device__ float g_x2  [2*CB*SP];
__device__ float g_weff[9*CB*3*CB];   // layout [tt][ci][tw][co]
__device__ float g_beff[CB];

// ---------------- LN1 + shift-roll + window partition ----------------
__global__ void k_ln1(const float* __restrict__ x,
                      const float* __restrict__ lw, const float* __restrict__ lb) {
    __shared__ float row[CB*WDIM];
    int bid = blockIdx.x;
    int h = bid % HDIM; int t = bid / HDIM; int d = t & 7; int bb = t >> 3;
    const float* base = x + (size_t)bb*CB*SP + d*HWs + h*WDIM;
    for (int i = threadIdx.x; i < CB*WDIM; i += blockDim.x) {
        int c = i / WDIM, w = i % WDIM;
        row[i] = base[(size_t)c*SP + w];
    }
    __syncthreads();
    if (threadIdx.x < WDIM) {
        int w = threadIdx.x;
        float mu = 0.f;
        for (int c = 0; c < CB; c++) mu += row[c*WDIM + w];
        mu *= (1.0f/CB);
        float var = 0.f;
        for (int c = 0; c < CB; c++) { float dv = row[c*WDIM + w] - mu; var += dv*dv; }
        var *= (1.0f/CB);
        float inv = rsqrtf(var + 1e-5f);
        int ds = (d + 4) & 7;
        int hs = h - 3; if (hs < 0) hs += HDIM;
        int ws = w - 3; if (ws < 0) ws += WDIM;
        int win = bb*64 + (hs/7)*8 + (ws/7);
        int n   = ds*49 + (hs%7)*7 + (ws%7);
        float* op = g_xw + ((size_t)win*NT + n)*CB;
        for (int c = 0; c < CB; c++)
            op[c] = (row[c*WDIM + w] - mu) * inv * lw[c] + lb[c];
    }
}

// ---------------- GEMM (f32x2): Out[M,Ntot] = A[M,96]*Bw[Ntot,96]^T + bias ----
__global__ void k_gemm96(const float* __restrict__ A, const float* __restrict__ Bw,
                         const float* __restrict__ bias, float* __restrict__ Out, int Ntot) {
    __shared__ float As[64][49];
    __shared__ float Bt[48][100];    // k-major, padded
    int m0 = blockIdx.x * 64;
    int n0 = blockIdx.y * 96;
    int tx = threadIdx.x & 15, ty = threadIdx.x >> 4;
    u64 acc2[4][3];
    #pragma unroll
    for (int r = 0; r < 4; r++)
        #pragma unroll
        for (int c = 0; c < 3; c++) acc2[r][c] = 0ULL;
    for (int kc = 0; kc < 2; kc++) {
        __syncthreads();
        for (int i = threadIdx.x; i < 64*48; i += 256) {
            int r = i/48, c = i%48;
            As[r][c] = A[(size_t)(m0 + r)*CB + kc*48 + c];
        }
        for (int i = threadIdx.x; i < 96*48; i += 256) {
            int r = i%96, c = i/96;
            Bt[c][r] = Bw[(size_t)(n0 + r)*CB + kc*48 + c];
        }
        __syncthreads();
        #pragma unroll 4
        for (int k = 0; k < 48; k++) {
            u64 ap[4];
            #pragma unroll
            for (int r = 0; r < 4; r++) {
                float a = As[ty*4 + r][k];
                ap[r] = pk2(a, a);
            }
            u64 b0 = *(const u64*)(&Bt[k][tx*6 + 0]);
            u64 b1 = *(const u64*)(&Bt[k][tx*6 + 2]);
            u64 b2 = *(const u64*)(&Bt[k][tx*6 + 4]);
            #pragma unroll
            for (int r = 0; r < 4; r++) {
                fma2(acc2[r][0], ap[r], b0);
                fma2(acc2[r][1], ap[r], b1);
                fma2(acc2[r][2], ap[r], b2);
            }
        }
    }
    const float* bp = bias + n0 + tx*6;
    u64 bb0 = *(const u64*)(bp + 0);
    u64 bb1 = *(const u64*)(bp + 2);
    u64 bb2 = *(const u64*)(bp + 4);
    #pragma unroll
    for (int r = 0; r < 4; r++) {
        float* op = Out + (size_t)(m0 + ty*4 + r)*Ntot + n0 + tx*6;
        *(u64*)(op + 0) = add2(acc2[r][0], bb0);
        *(u64*)(op + 2) = add2(acc2[r][1], bb1);
        *(u64*)(op + 4) = add2(acc2[r][2], bb2);
    }
}

// ---------------- windowed attention v3: f32x2 packed ----------------
#define KS_STRIDE 396
#define VS_STRIDE 404
#define PS_STRIDE 396

template<int DH, int NH>
__global__ void __launch_bounds__(256, 1) k_attn3(const float* __restrict__ qkv,
                                                  const float* __restrict__ rpb,
                                                  float* __restrict__ outp) {
    extern __shared__ float sm[];
    float* Ks  = sm;                         // [DH][KS_STRIDE]
    float* Vs  = Ks + DH*KS_STRIDE;          // [DH][VS_STRIDE]
    float* psm = Vs + DH*VS_STRIDE;          // [8 warps][4][PS_STRIDE]
    float* bsm = psm + 8*4*PS_STRIDE;        // 2535 bias entries
    unsigned int* lsm = (unsigned int*)(bsm + 2535);

    int win = blockIdx.x / NH, hd = blockIdx.x % NH;
    const float* qb = qkv + (size_t)win*NT*288;

    for (int i = threadIdx.x; i < NT*DH; i += 256) {
        int n = i / DH, d = i % DH;
        Ks[d*KS_STRIDE + n] = qb[n*288 +  96 + hd*DH + d];
        Vs[d*VS_STRIDE + n] = qb[n*288 + 192 + hd*DH + d];
    }
    for (int i = threadIdx.x; i < 2535; i += 256) bsm[i] = rpb[i*NH + hd];
    {
        int whi = (win & 63) >> 3, wwi = win & 7;
        for (int n = threadIdx.x; n < NT; n += 256) {
            int dz = n/49, r = n%49, hy = r/7, wl = r%7;
            int gh = whi*7 + hy, gw = wwi*7 + wl;
            int dreg = dz < 4 ? 0 : 1;
            int hreg = gh < 49 ? 0 : (gh < 53 ? 1 : 2);
            int wreg = gw < 49 ? 0 : (gw < 53 ? 1 : 2);
            lsm[n] = (unsigned)dz | ((unsigned)hy<<8) | ((unsigned)wl<<16)
                   | ((unsigned)(dreg*9 + hreg*3 + wreg)<<24);
        }
    }
    __syncthreads();

    const float scale = rsqrtf((float)DH);
    int warp = threadIdx.x >> 5, lane = threadIdx.x & 31;
    float* pw = psm + warp*(4*PS_STRIDE);

    for (int i0 = warp*4; i0 < NT; i0 += 32) {
        // -------- QK (packed pairs along j) --------
        u64 sc2[4][8];
        #pragma unroll
        for (int r = 0; r < 4; r++)
            #pragma unroll
            for (int t = 0; t < 8; t++) sc2[r][t] = 0ULL;

        #pragma unroll
        for (int d4 = 0; d4 < DH; d4 += 4) {
            u64 qp[4][4];
            #pragma unroll
            for (int r = 0; r < 4; r++) {
                float4 q = *(const float4*)(qb + (size_t)(i0+r)*288 + hd*DH + d4);
                qp[r][0] = pk2(q.x, q.x);
                qp[r][1] = pk2(q.y, q.y);
                qp[r][2] = pk2(q.z, q.z);
                qp[r][3] = pk2(q.w, q.w);
            }
            #pragma unroll
            for (int s = 0; s < 4; s++) {
                int j = s*128 + lane*4;
                if (j < NT) {
                    ulonglong2 k0 = *(const ulonglong2*)(Ks + (d4+0)*KS_STRIDE + j);
                    ulonglong2 k1 = *(const ulonglong2*)(Ks + (d4+1)*KS_STRIDE + j);
                    ulonglong2 k2 = *(const ulonglong2*)(Ks + (d4+2)*KS_STRIDE + j);
                    ulonglong2 k3 = *(const ulonglong2*)(Ks + (d4+3)*KS_STRIDE + j);
                    #pragma unroll
                    for (int r = 0; r < 4; r++) {
                        fma2(sc2[r][s*2+0], qp[r][0], k0.x); fma2(sc2[r][s*2+1], qp[r][0], k0.y);
                        fma2(sc2[r][s*2+0], qp[r][1], k1.x); fma2(sc2[r][s*2+1], qp[r][1], k1.y);
                        fma2(sc2[r][s*2+0], qp[r][2], k2.x); fma2(sc2[r][s*2+1], qp[r][2], k2.y);
                        fma2(sc2[r][s*2+0], qp[r][3], k3.x); fma2(sc2[r][s*2+1], qp[r][3], k3.y);
                    }
                }
            }
        }

        // unpack to scalars
        float sc[4][16];
        #pragma unroll
        for (int r = 0; r < 4; r++)
            #pragma unroll
            for (int t = 0; t < 8; t++)
                upk(sc2[r][t], sc[r][2*t], sc[r][2*t+1]);

        // -------- bias + region mask + scale --------
        unsigned ci_[4];
        #pragma unroll
        for (int r = 0; r < 4; r++) ci_[r] = lsm[i0 + r];
        #pragma unroll
        for (int s = 0; s < 4; s++) {
            #pragma unroll
            for (int jj = 0; jj < 4; jj++) {
                int j = s*128 + lane*4 + jj;
                if (j < NT) {
                    unsigned cj = lsm[j];
                    int jx = (int)(cj & 255), jy = (int)((cj>>8)&255), jz = (int)((cj>>16)&255);
                    #pragma unroll
                    for (int r = 0; r < 4; r++) {
                        unsigned ci = ci_[r];
                        int dd = (int)(ci & 255)       - jx + 7;
                        int dh_= (int)((ci>>8)&255)    - jy + 6;
                        int dw = (int)((ci>>16)&255)   - jz + 6;
                        float b = bsm[dd*169 + dh_*13 + dw];
                        float v = sc[r][s*4+jj]*scale + b;
                        if ((ci ^ cj) >> 24) v -= 100.f;
                        sc[r][s*4+jj] = v;
                    }
                } else {
                    #pragma unroll
                    for (int r = 0; r < 4; r++) sc[r][s*4+jj] = -1e30f;
                }
            }
        }

        // -------- softmax --------
        float inv_[4];
        #pragma unroll
        for (int r = 0; r < 4; r++) {
            float mx = -1e30f;
            #pragma unroll
            for (int t = 0; t < 16; t++) mx = fmaxf(mx, sc[r][t]);
            #pragma unroll
            for (int o = 16; o; o >>= 1) mx = fmaxf(mx, __shfl_xor_sync(0xffffffffu, mx, o));
            float sum = 0.f;
            #pragma unroll
            for (int t = 0; t < 16; t++) { float e = __expf(sc[r][t] - mx); sc[r][t] = e; sum += e; }
            #pragma unroll
            for (int o = 16; o; o >>= 1) sum += __shfl_xor_sync(0xffffffffu, sum, o);
            inv_[r] = 1.f / sum;
        }

        // -------- store P --------
        #pragma unroll
        for (int r = 0; r < 4; r++) {
            #pragma unroll
            for (int s = 0; s < 4; s++) {
                int j = s*128 + lane*4;
                if (j < NT) {
                    float4 p4 = make_float4(sc[r][s*4+0]*inv_[r], sc[r][s*4+1]*inv_[r],
                                            sc[r][s*4+2]*inv_[r], sc[r][s*4+3]*inv_[r]);
                    *(float4*)(pw + r*PS_STRIDE + j) = p4;
                }
            }
        }
        __syncwarp();

        // -------- PV (packed pairs along j) --------
        if (DH == 32) {
            u64 a2[4] = {0ULL, 0ULL, 0ULL, 0ULL};
            const float* vrow = Vs + lane*VS_STRIDE;
            #pragma unroll 2
            for (int j = 0; j < NT; j += 4) {
                ulonglong2 v  = *(const ulonglong2*)(vrow + j);
                ulonglong2 p0 = *(const ulonglong2*)(pw + 0*PS_STRIDE + j);
                ulonglong2 p1 = *(const ulonglong2*)(pw + 1*PS_STRIDE + j);
                ulonglong2 p2 = *(const ulonglong2*)(pw + 2*PS_STRIDE + j);
                ulonglong2 p3 = *(const ulonglong2*)(pw + 3*PS_STRIDE + j);
                fma2(a2[0], p0.x, v.x); fma2(a2[0], p0.y, v.y);
                fma2(a2[1], p1.x, v.x); fma2(a2[1], p1.y, v.y);
                fma2(a2[2], p2.x, v.x); fma2(a2[2], p2.y, v.y);
                fma2(a2[3], p3.x, v.x); fma2(a2[3], p3.y, v.y);
            }
            size_t ob = ((size_t)win*NT + i0)*CB + hd*32 + lane;
            #pragma unroll
            for (int r = 0; r < 4; r++) {
                float lo, hi; upk(a2[r], lo, hi);
                outp[ob + (size_t)r*CB] = lo + hi;
            }
        } else {
            int half = lane >> 4, d = lane & 15;
            u64 aA = 0ULL, aB = 0ULL;
            const float* vrow = Vs + d*VS_STRIDE;
            const float* pa = pw + (2*half + 0)*PS_STRIDE;
            const float* pb = pw + (2*half + 1)*PS_STRIDE;
            #pragma unroll 2
            for (int j = 0; j < NT; j += 4) {
                ulonglong2 v  = *(const ulonglong2*)(vrow + j);
                ulonglong2 p0 = *(const ulonglong2*)(pa + j);
                ulonglong2 p1 = *(const ulonglong2*)(pb + j);
                fma2(aA, p0.x, v.x); fma2(aA, p0.y, v.y);
                fma2(aB, p1.x, v.x); fma2(aB, p1.y, v.y);
            }
            size_t ob = ((size_t)win*NT + i0 + 2*half)*CB + hd*16 + d;
            float lo, hi;
            upk(aA, lo, hi); outp[ob]      = lo + hi;
            upk(aB, lo, hi); outp[ob + CB] = lo + hi;
        }
        __syncwarp();
    }
}

// ---------------- NAS mix + window reverse + unroll + residual ----------------
__global__ void k_combine(const float* __restrict__ x, const float* __restrict__ alpha) {
    int tok = blockIdx.x, c = threadIdx.x;
    float a0 = alpha[0], a1 = alpha[1];
    float m  = fmaxf(a0, a1);
    float e0 = __expf(a0 - m), e1 = __expf(a1 - m);
    float inv = 1.f / (e0 + e1);
    float aw0 = e0*inv, aw1 = e1*inv;
    int win = tok / NT, n = tok % NT;
    int bb = win >> 6; int whi = (win & 63) >> 3, wwi = win & 7;
    int dz = n/49, r = n%49, hy = r/7, wl = r%7;
    int hs = whi*7 + hy, ws = wwi*7 + wl;
    int d0 = (dz + 4) & 7;
    int h0 = hs + 3; if (h0 >= HDIM) h0 -= HDIM;
    int w0 = ws + 3; if (w0 >= WDIM) w0 -= WDIM;
    size_t oi = ((size_t)(bb*CB + c)*DDIM + d0)*HWs + h0*WDIM + w0;
    size_t ti = (size_t)tok*CB + c;
    g_x1[oi] = x[oi] + aw0*g_p0[ti] + aw1*g_p1[ti];
}

// ---------------- LN2 ----------------
__global__ void k_ln2(const float* __restrict__ lw, const float* __restrict__ lb) {
    __shared__ float row[CB*WDIM];
    __shared__ float s_mu[WDIM], s_inv[WDIM];
    int bid = blockIdx.x;
    int h = bid % HDIM; int t = bid / HDIM; int d = t & 7; int bb = t >> 3;
    size_t base = (size_t)bb*CB*SP + d*HWs + h*WDIM;
    for (int i = threadIdx.x; i < CB*WDIM; i += blockDim.x)
        row[i] = g_x1[base + (size_t)(i/WDIM)*SP + (i%WDIM)];
    __syncthreads();
    if (threadIdx.x < WDIM) {
        int w = threadIdx.x;
        float mu = 0.f;
        for (int c = 0; c < CB; c++) mu += row[c*WDIM + w];
        mu *= (1.0f/CB);
        float var = 0.f;
        for (int c = 0; c < CB; c++) { float dv = row[c*WDIM + w] - mu; var += dv*dv; }
        var *= (1.0f/CB);
        s_mu[w] = mu; s_inv[w] = rsqrtf(var + 1e-5f);
    }
    __syncthreads();
    for (int i = threadIdx.x; i < CB*WDIM; i += blockDim.x) {
        int c = i / WDIM, w = i % WDIM;
        g_x2[base + (size_t)c*SP + w] = (row[i] - s_mu[w]) * s_inv[w] * lw[c] + lb[c];
    }
}

// ---------------- build effective conv weights (NAS fold) ----------------
// new layout: g_weff[tt][ci][tw][co]
__global__ void k_weff(const float* __restrict__ c3w, const float* __restrict__ c3b,
                       const float* __restrict__ c1w, const float* __restrict__ c1b,
                       const float* __restrict__ dww, const float* __restrict__ dwb,
                       const float* __restrict__ alpha) {
    float a[4]; float m = -1e30f;
    #pragma unroll
    for (int i = 0; i < 4; i++) { a[i] = alpha[i]; m = fmaxf(m, a[i]); }
    float s = 0.f;
    #pragma unroll
    for (int i = 0; i < 4; i++) { a[i] = __expf(a[i] - m); s += a[i]; }
    float inv = 1.f / s;
    #pragma unroll
    for (int i = 0; i < 4; i++) a[i] *= inv;
    int total = CB*CB*27;
    for (int idx = blockIdx.x*blockDim.x + threadIdx.x; idx < total; idx += gridDim.x*blockDim.x) {
        int t = idx % 27; int rest = idx / 27; int ci = rest % CB; int co = rest / CB;
        float val = a[0] * c3w[idx];
        if (t == 13)            val += a[1] * c1w[co*CB + ci];
        if (ci == co)           val += a[2] * dww[co*27 + t];
        if (t == 13 && ci == co) val += a[3];
        int tt = t / 3, tw = t % 3;
        g_weff[(((size_t)tt*CB + ci)*3 + tw)*CB + co] = val;
    }
    int gid = blockIdx.x*blockDim.x + threadIdx.x;
    if (gid < CB) g_beff[gid] = a[0]*c3b[gid] + a[1]*c1b[gid] + a[2]*dwb[gid];
}

// ---------------- fused FFN conv (f32x2, 4 channels/thread) + residual -------
// 96 threads: co4 = tid>>2 (24 quads), wg = tid&3 (14 w each)
__global__ void __launch_bounds__(96) k_ffn(float* __restrict__ out) {
    extern __shared__ float sm[];
    float* insm = sm;             // 96*58
    float* wsm  = sm + CB*58;     // 16*3*96 (per-chunk weights)
    int bid = blockIdx.x;
    int h = bid % HDIM; int t = bid / HDIM; int d = t & 7; int bb = t >> 3;
    int co4 = threadIdx.x >> 2, wg = threadIdx.x & 3, wbase = wg*14;
    int co = co4*4;

    u64 acc[2][14];
    u64 bv01 = *(const u64*)(g_beff + co);
    u64 bv23 = *(const u64*)(g_beff + co + 2);
    #pragma unroll
    for (int k = 0; k < 14; k++) { acc[0][k] = bv01; acc[1][k] = bv23; }

    for (int td = 0; td < 3; td++) {
        int sd = d + td - 1;
        if (sd < 0 || sd >= DDIM) continue;
        for (int th = 0; th < 3; th++) {
            int sh = h + th - 1;
            if (sh < 0 || sh >= HDIM) continue;
            int tt = td*3 + th;
            __syncthreads();
            size_t ibase = (size_t)bb*CB*SP + sd*HWs + sh*WDIM;
            for (int i = threadIdx.x; i < CB*58; i += 96) {
                int ci = i / 58, col = i % 58;
                insm[i] = (col == 0 || col == 57) ? 0.f
                        : g_x2[ibase + (size_t)ci*SP + (col - 1)];
            }
            const float* wg_base = g_weff + (size_t)tt*CB*3*CB;
            for (int cb2 = 0; cb2 < 6; cb2++) {
                __syncthreads();
                for (int i = threadIdx.x; i < 16*3*CB; i += 96)
                    wsm[i] = wg_base[(size_t)cb2*16*3*CB + i];
                __syncthreads();
                #pragma unroll 2
                for (int cil = 0; cil < 16; cil++) {
                    int ci = cb2*16 + cil;
                    const float* ir = insm + ci*58 + wbase;
                    u64 rb[16];
                    #pragma unroll
                    for (int k = 0; k < 16; k++) { float v = ir[k]; rb[k] = pk2(v, v); }
                    const float* wp = wsm + cil*3*CB;
                    #pragma unroll
                    for (int tw = 0; tw < 3; tw++) {
                        u64 w01 = *(const u64*)(wp + tw*CB + co);
                        u64 w23 = *(const u64*)(wp + tw*CB + co + 2);
                        #pragma unroll
                        for (int k = 0; k < 14; k++) {
                            fma2(acc[0][k], w01, rb[k+tw]);
                            fma2(acc[1][k], w23, rb[k+tw]);
                        }
                    }
                }
            }
        }
    }
    size_t ob0 = ((size_t)(bb*CB + co + 0)*DDIM + d)*HWs + h*WDIM + wbase;
    size_t ob1 = ((size_t)(bb*CB + co + 1)*DDIM + d)*HWs + h*WDIM + wbase;
    size_t ob2 = ((size_t)(bb*CB + co + 2)*DDIM + d)*HWs + h*WDIM + wbase;
    size_t ob3 = ((size_t)(bb*CB + co + 3)*DDIM + d)*HWs + h*WDIM + wbase;
    #pragma unroll
    for (int k = 0; k < 14; k++) {
        float v0, v1, v2, v3;
        upk(acc[0][k], v0, v1);
        upk(acc[1][k], v2, v3);
        out[ob0 + k] = g_x1[ob0 + k] + v0;
        out[ob1 + k] = g_x1[ob1 + k] + v1;
        out[ob2 + k] = g_x1[ob2 + k] + v2;
        out[ob3 + k] = g_x1[ob3 + k] + v3;
    }
}

// ---------------- host launch ----------------
extern "C" void kernel_launch(void* const* d_in, const int* in_sizes, int n_in,
                              void* d_out, int out_size) {
    (void)in_sizes; (void)n_in; (void)out_size;
    const float* x      = (const float*)d_in[0];
    const float* ln1w   = (const float*)d_in[1];
    const float* ln1b   = (const float*)d_in[2];
    const float* ln2w   = (const float*)d_in[3];
    const float* ln2b   = (const float*)d_in[4];
    const float* qkvw0  = (const float*)d_in[5];
    const float* qkvb0  = (const float*)d_in[6];
    const float* projw0 = (const float*)d_in[7];
    const float* projb0 = (const float*)d_in[8];
    const float* rpb0   = (const float*)d_in[9];
    const float* qkvw1  = (const float*)d_in[10];
    const float* qkvb1  = (const float*)d_in[11];
    const float* projw1 = (const float*)d_in[12];
    const float* projb1 = (const float*)d_in[13];
    const float* rpb1   = (const float*)d_in[14];
    const float* alphaA = (const float*)d_in[15];
    const float* c3w    = (const float*)d_in[16];
    const float* c3b    = (const float*)d_in[17];
    const float* c1w    = (const float*)d_in[18];
    const float* c1b    = (const float*)d_in[19];
    const float* dww    = (const float*)d_in[20];
    const float* dwb    = (const float*)d_in[21];
    const float* alphaF = (const float*)d_in[22];
    float* out = (float*)d_out;

    float *p_xw, *p_q0, *p_q1, *p_o0, *p_o1, *p_p0, *p_p1;
    cudaGetSymbolAddress((void**)&p_xw, g_xw);
    cudaGetSymbolAddress((void**)&p_q0, g_qkv0);
    cudaGetSymbolAddress((void**)&p_q1, g_qkv1);
    cudaGetSymbolAddress((void**)&p_o0, g_o0);
    cudaGetSymbolAddress((void**)&p_o1, g_o1);
    cudaGetSymbolAddress((void**)&p_p0, g_p0);
    cudaGetSymbolAddress((void**)&p_p1, g_p1);

    int smA0 = (32*KS_STRIDE + 32*VS_STRIDE + 8*4*PS_STRIDE + 2535 + 392) * 4;
    int smA1 = (16*KS_STRIDE + 16*VS_STRIDE + 8*4*PS_STRIDE + 2535 + 392) * 4;
    int smF  = (CB*58 + 16*3*CB) * 4;
    cudaFuncSetAttribute(k_attn3<32,3>, cudaFuncAttributeMaxDynamicSharedMemorySize, smA0);
    cudaFuncSetAttribute(k_attn3<16,6>, cudaFuncAttributeMaxDynamicSharedMemorySize, smA1);
    cudaFuncSetAttribute(k_ffn,         cudaFuncAttributeMaxDynamicSharedMemorySize, smF);

    // 1) LN1 + roll + window partition
    k_ln1<<<2*DDIM*HDIM, 256>>>(x, ln1w, ln1b);

    // 2) QKV GEMMs
    dim3 gq(NTOK/64, 3);
    k_gemm96<<<gq, 256>>>(p_xw, qkvw0, qkvb0, p_q0, 288);
    k_gemm96<<<gq, 256>>>(p_xw, qkvw1, qkvb1, p_q1, 288);

    // 3) windowed attention
    k_attn3<32,3><<<NWIN*3, 256, smA0>>>(p_q0, rpb0, p_o0);
    k_attn3<16,6><<<NWIN*6, 256, smA1>>>(p_q1, rpb1, p_o1);

    // 4) output projections
    dim3 gp(NTOK/64, 1);
    k_gemm96<<<gp, 256>>>(p_o0, projw0, projb0, p_p0, 96);
    k_gemm96<<<gp, 256>>>(p_o1, projw1, projb1, p_p1, 96);

    // 5) NAS mix + window reverse + un-roll + residual
    k_combine<<<NTOK, CB>>>(x, alphaA);

    // 6) LN2
    k_ln2<<<2*DDIM*HDIM, 256>>>(ln2w, ln2b);

    // 7) effective conv + residual
    k_weff<<<128, 256>>>(c3w, c3b, c1w, c1b, dww, dwb, alphaF);
    k_ffn<<<2*DDIM*HDIM, 96, smF>>>(out);
}

// round 8
// speedup vs baseline: 1.6637x; 1.3171x over previous
#include <cuda_runtime.h>
#include <cstdint>

#define CB 96
#define DDIM 8
#define HDIM 56
#define WDIM 56
#define SP   (DDIM*HDIM*WDIM)   // 25088
#define HWs  (HDIM*WDIM)        // 3136
#define NT   392                // tokens per window
#define NWIN 128                // total windows (B=2, 64 per batch)
#define NTOK (NWIN*NT)          // 50176

typedef unsigned long long u64;

// ---------------- packed f32x2 helpers ----------------
__device__ __forceinline__ u64 pk2(float lo, float hi) {
    u64 r;
    asm("mov.b64 %0, {%1, %2};" : "=l"(r)
        : "r"(__float_as_uint(lo)), "r"(__float_as_uint(hi)));
    return r;
}
__device__ __forceinline__ void upk(u64 v, float& lo, float& hi) {
    unsigned a, b;
    asm("mov.b64 {%0, %1}, %2;" : "=r"(a), "=r"(b) : "l"(v));
    lo = __uint_as_float(a); hi = __uint_as_float(b);
}
__device__ __forceinline__ void fma2(u64& d, u64 a, u64 b) {
    asm("fma.rn.f32x2 %0, %1, %2, %0;" : "+l"(d) : "l"(a), "l"(b));
}
__device__ __forceinline__ u64 add2(u64 a, u64 b) {
    u64 d; asm("add.rn.f32x2 %0, %1, %2;" : "=l"(d) : "l"(a), "l"(b)); return d;
}
__device__ __forceinline__ float to_tf32(float x) {
    unsigned u;
    asm("cvt.rna.tf32.f32 %0, %1;" : "=r"(u) : "f"(x));
    return __uint_as_float(u);
}

// ---------------- scratch (device globals; no allocation) ----------------
__device__ float g_xw  [NTOK*CB];
__device__ float g_qkv0[NTOK*288];
__device__ float g_qkv1[NTOK*288];
__device__ float g_o0  [NTOK*CB];
__device__ float g_o1  [NTOK*CB];
__device__ float g_p0  [NTOK*CB];
__device__ float g_p1  [NTOK*CB];
__device__ float g_x1  [2*CB*SP];
__device__ float g_x2  [2*CB*SP];     // LN2(x1), tf32-rounded
__device__ float g_weff[9*CB*3*CB];   // [k = (tt*96+ci)*3+tw][co], tf32-rounded
__device__ float g_beff[CB];

// ---------------- LN1 + shift-roll + window partition ----------------
__global__ void k_ln1(const float* __restrict__ x,
                      const float* __restrict__ lw, const float* __restrict__ lb) {
    __shared__ float row[CB*WDIM];
    int bid = blockIdx.x;
    int h = bid % HDIM; int t = bid / HDIM; int d = t & 7; int bb = t >> 3;
    const float* base = x + (size_t)bb*CB*SP + d*HWs + h*WDIM;
    for (int i = threadIdx.x; i < CB*WDIM; i += blockDim.x) {
        int c = i / WDIM, w = i % WDIM;
        row[i] = base[(size_t)c*SP + w];
    }
    __syncthreads();
    if (threadIdx.x < WDIM) {
        int w = threadIdx.x;
        float mu = 0.f;
        for (int c = 0; c < CB; c++) mu += row[c*WDIM + w];
        mu *= (1.0f/CB);
        float var = 0.f;
        for (int c = 0; c < CB; c++) { float dv = row[c*WDIM + w] - mu; var += dv*dv; }
        var *= (1.0f/CB);
        float inv = rsqrtf(var + 1e-5f);
        int ds = (d + 4) & 7;
        int hs = h - 3; if (hs < 0) hs += HDIM;
        int ws = w - 3; if (ws < 0) ws += WDIM;
        int win = bb*64 + (hs/7)*8 + (ws/7);
        int n   = ds*49 + (hs%7)*7 + (ws%7);
        float* op = g_xw + ((size_t)win*NT + n)*CB;
        for (int c = 0; c < CB; c++)
            op[c] = (row[c*WDIM + w] - mu) * inv * lw[c] + lb[c];
    }
}

// ---------------- GEMM (f32x2): Out[M,Ntot] = A[M,96]*Bw[Ntot,96]^T + bias ----
__global__ void k_gemm96(const float* __restrict__ A, const float* __restrict__ Bw,
                         const float* __restrict__ bias, float* __restrict__ Out, int Ntot) {
    __shared__ float As[64][49];
    __shared__ float Bt[48][100];    // k-major, padded
    int m0 = blockIdx.x * 64;
    int n0 = blockIdx.y * 96;
    int tx = threadIdx.x & 15, ty = threadIdx.x >> 4;
    u64 acc2[4][3];
    #pragma unroll
    for (int r = 0; r < 4; r++)
        #pragma unroll
        for (int c = 0; c < 3; c++) acc2[r][c] = 0ULL;
    for (int kc = 0; kc < 2; kc++) {
        __syncthreads();
        for (int i = threadIdx.x; i < 64*48; i += 256) {
            int r = i/48, c = i%48;
            As[r][c] = A[(size_t)(m0 + r)*CB + kc*48 + c];
        }
        for (int i = threadIdx.x; i < 96*48; i += 256) {
            int r = i%96, c = i/96;
            Bt[c][r] = Bw[(size_t)(n0 + r)*CB + kc*48 + c];
        }
        __syncthreads();
        #pragma unroll 4
        for (int k = 0; k < 48; k++) {
            u64 ap[4];
            #pragma unroll
            for (int r = 0; r < 4; r++) {
                float a = As[ty*4 + r][k];
                ap[r] = pk2(a, a);
            }
            u64 b0 = *(const u64*)(&Bt[k][tx*6 + 0]);
            u64 b1 = *(const u64*)(&Bt[k][tx*6 + 2]);
            u64 b2 = *(const u64*)(&Bt[k][tx*6 + 4]);
            #pragma unroll
            for (int r = 0; r < 4; r++) {
                fma2(acc2[r][0], ap[r], b0);
                fma2(acc2[r][1], ap[r], b1);
                fma2(acc2[r][2], ap[r], b2);
            }
        }
    }
    const float* bp = bias + n0 + tx*6;
    u64 bb0 = *(const u64*)(bp + 0);
    u64 bb1 = *(const u64*)(bp + 2);
    u64 bb2 = *(const u64*)(bp + 4);
    #pragma unroll
    for (int r = 0; r < 4; r++) {
        float* op = Out + (size_t)(m0 + ty*4 + r)*Ntot + n0 + tx*6;
        *(u64*)(op + 0) = add2(acc2[r][0], bb0);
        *(u64*)(op + 2) = add2(acc2[r][1], bb1);
        *(u64*)(op + 4) = add2(acc2[r][2], bb2);
    }
}

// ---------------- windowed attention v3: f32x2 packed ----------------
#define KS_STRIDE 396
#define VS_STRIDE 404
#define PS_STRIDE 396

template<int DH, int NH>
__global__ void __launch_bounds__(256, 1) k_attn3(const float* __restrict__ qkv,
                                                  const float* __restrict__ rpb,
                                                  float* __restrict__ outp) {
    extern __shared__ float sm[];
    float* Ks  = sm;                         // [DH][KS_STRIDE]
    float* Vs  = Ks + DH*KS_STRIDE;          // [DH][VS_STRIDE]
    float* psm = Vs + DH*VS_STRIDE;          // [8 warps][4][PS_STRIDE]
    float* bsm = psm + 8*4*PS_STRIDE;        // 2535 bias entries
    unsigned int* lsm = (unsigned int*)(bsm + 2535);

    int win = blockIdx.x / NH, hd = blockIdx.x % NH;
    const float* qb = qkv + (size_t)win*NT*288;

    for (int i = threadIdx.x; i < NT*DH; i += 256) {
        int n = i / DH, d = i % DH;
        Ks[d*KS_STRIDE + n] = qb[n*288 +  96 + hd*DH + d];
        Vs[d*VS_STRIDE + n] = qb[n*288 + 192 + hd*DH + d];
    }
    for (int i = threadIdx.x; i < 2535; i += 256) bsm[i] = rpb[i*NH + hd];
    {
        int whi = (win & 63) >> 3, wwi = win & 7;
        for (int n = threadIdx.x; n < NT; n += 256) {
            int dz = n/49, r = n%49, hy = r/7, wl = r%7;
            int gh = whi*7 + hy, gw = wwi*7 + wl;
            int dreg = dz < 4 ? 0 : 1;
            int hreg = gh < 49 ? 0 : (gh < 53 ? 1 : 2);
            int wreg = gw < 49 ? 0 : (gw < 53 ? 1 : 2);
            lsm[n] = (unsigned)dz | ((unsigned)hy<<8) | ((unsigned)wl<<16)
                   | ((unsigned)(dreg*9 + hreg*3 + wreg)<<24);
        }
    }
    __syncthreads();

    const float scale = rsqrtf((float)DH);
    int warp = threadIdx.x >> 5, lane = threadIdx.x & 31;
    float* pw = psm + warp*(4*PS_STRIDE);

    for (int i0 = warp*4; i0 < NT; i0 += 32) {
        u64 sc2[4][8];
        #pragma unroll
        for (int r = 0; r < 4; r++)
            #pragma unroll
            for (int t = 0; t < 8; t++) sc2[r][t] = 0ULL;

        #pragma unroll
        for (int d4 = 0; d4 < DH; d4 += 4) {
            u64 qp[4][4];
            #pragma unroll
            for (int r = 0; r < 4; r++) {
                float4 q = *(const float4*)(qb + (size_t)(i0+r)*288 + hd*DH + d4);
                qp[r][0] = pk2(q.x, q.x);
                qp[r][1] = pk2(q.y, q.y);
                qp[r][2] = pk2(q.z, q.z);
                qp[r][3] = pk2(q.w, q.w);
            }
            #pragma unroll
            for (int s = 0; s < 4; s++) {
                int j = s*128 + lane*4;
                if (j < NT) {
                    ulonglong2 k0 = *(const ulonglong2*)(Ks + (d4+0)*KS_STRIDE + j);
                    ulonglong2 k1 = *(const ulonglong2*)(Ks + (d4+1)*KS_STRIDE + j);
                    ulonglong2 k2 = *(const ulonglong2*)(Ks + (d4+2)*KS_STRIDE + j);
                    ulonglong2 k3 = *(const ulonglong2*)(Ks + (d4+3)*KS_STRIDE + j);
                    #pragma unroll
                    for (int r = 0; r < 4; r++) {
                        fma2(sc2[r][s*2+0], qp[r][0], k0.x); fma2(sc2[r][s*2+1], qp[r][0], k0.y);
                        fma2(sc2[r][s*2+0], qp[r][1], k1.x); fma2(sc2[r][s*2+1], qp[r][1], k1.y);
                        fma2(sc2[r][s*2+0], qp[r][2], k2.x); fma2(sc2[r][s*2+1], qp[r][2], k2.y);
                        fma2(sc2[r][s*2+0], qp[r][3], k3.x); fma2(sc2[r][s*2+1], qp[r][3], k3.y);
                    }
                }
            }
        }

        float sc[4][16];
        #pragma unroll
        for (int r = 0; r < 4; r++)
            #pragma unroll
            for (int t = 0; t < 8; t++)
                upk(sc2[r][t], sc[r][2*t], sc[r][2*t+1]);

        unsigned ci_[4];
        #pragma unroll
        for (int r = 0; r < 4; r++) ci_[r] = lsm[i0 + r];
        #pragma unroll
        for (int s = 0; s < 4; s++) {
            #pragma unroll
            for (int jj = 0; jj < 4; jj++) {
                int j = s*128 + lane*4 + jj;
                if (j < NT) {
                    unsigned cj = lsm[j];
                    int jx = (int)(cj & 255), jy = (int)((cj>>8)&255), jz = (int)((cj>>16)&255);
                    #pragma unroll
                    for (int r = 0; r < 4; r++) {
                        unsigned ci = ci_[r];
                        int dd = (int)(ci & 255)       - jx + 7;
                        int dh_= (int)((ci>>8)&255)    - jy + 6;
                        int dw = (int)((ci>>16)&255)   - jz + 6;
                        float b = bsm[dd*169 + dh_*13 + dw];
                        float v = sc[r][s*4+jj]*scale + b;
                        if ((ci ^ cj) >> 24) v -= 100.f;
                        sc[r][s*4+jj] = v;
                    }
                } else {
                    #pragma unroll
                    for (int r = 0; r < 4; r++) sc[r][s*4+jj] = -1e30f;
                }
            }
        }

        float inv_[4];
        #pragma unroll
        for (int r = 0; r < 4; r++) {
            float mx = -1e30f;
            #pragma unroll
            for (int t = 0; t < 16; t++) mx = fmaxf(mx, sc[r][t]);
            #pragma unroll
            for (int o = 16; o; o >>= 1) mx = fmaxf(mx, __shfl_xor_sync(0xffffffffu, mx, o));
            float sum = 0.f;
            #pragma unroll
            for (int t = 0; t < 16; t++) { float e = __expf(sc[r][t] - mx); sc[r][t] = e; sum += e; }
            #pragma unroll
            for (int o = 16; o; o >>= 1) sum += __shfl_xor_sync(0xffffffffu, sum, o);
            inv_[r] = 1.f / sum;
        }

        #pragma unroll
        for (int r = 0; r < 4; r++) {
            #pragma unroll
            for (int s = 0; s < 4; s++) {
                int j = s*128 + lane*4;
                if (j < NT) {
                    float4 p4 = make_float4(sc[r][s*4+0]*inv_[r], sc[r][s*4+1]*inv_[r],
                                            sc[r][s*4+2]*inv_[r], sc[r][s*4+3]*inv_[r]);
                    *(float4*)(pw + r*PS_STRIDE + j) = p4;
                }
            }
        }
        __syncwarp();

        if (DH == 32) {
            u64 a2[4] = {0ULL, 0ULL, 0ULL, 0ULL};
            const float* vrow = Vs + lane*VS_STRIDE;
            #pragma unroll 2
            for (int j = 0; j < NT; j += 4) {
                ulonglong2 v  = *(const ulonglong2*)(vrow + j);
                ulonglong2 p0 = *(const ulonglong2*)(pw + 0*PS_STRIDE + j);
                ulonglong2 p1 = *(const ulonglong2*)(pw + 1*PS_STRIDE + j);
                ulonglong2 p2 = *(const ulonglong2*)(pw + 2*PS_STRIDE + j);
                ulonglong2 p3 = *(const ulonglong2*)(pw + 3*PS_STRIDE + j);
                fma2(a2[0], p0.x, v.x); fma2(a2[0], p0.y, v.y);
                fma2(a2[1], p1.x, v.x); fma2(a2[1], p1.y, v.y);
                fma2(a2[2], p2.x, v.x); fma2(a2[2], p2.y, v.y);
                fma2(a2[3], p3.x, v.x); fma2(a2[3], p3.y, v.y);
            }
            size_t ob = ((size_t)win*NT + i0)*CB + hd*32 + lane;
            #pragma unroll
            for (int r = 0; r < 4; r++) {
                float lo, hi; upk(a2[r], lo, hi);
                outp[ob + (size_t)r*CB] = lo + hi;
            }
        } else {
            int half = lane >> 4, d = lane & 15;
            u64 aA = 0ULL, aB = 0ULL;
            const float* vrow = Vs + d*VS_STRIDE;
            const float* pa = pw + (2*half + 0)*PS_STRIDE;
            const float* pb = pw + (2*half + 1)*PS_STRIDE;
            #pragma unroll 2
            for (int j = 0; j < NT; j += 4) {
                ulonglong2 v  = *(const ulonglong2*)(vrow + j);
                ulonglong2 p0 = *(const ulonglong2*)(pa + j);
                ulonglong2 p1 = *(const ulonglong2*)(pb + j);
                fma2(aA, p0.x, v.x); fma2(aA, p0.y, v.y);
                fma2(aB, p1.x, v.x); fma2(aB, p1.y, v.y);
            }
            size_t ob = ((size_t)win*NT + i0 + 2*half)*CB + hd*16 + d;
            float lo, hi;
            upk(aA, lo, hi); outp[ob]      = lo + hi;
            upk(aB, lo, hi); outp[ob + CB] = lo + hi;
        }
        __syncwarp();
    }
}

// ---------------- NAS mix + window reverse + unroll + residual ----------------
__global__ void k_combine(const float* __restrict__ x, const float* __restrict__ alpha) {
    int tok = blockIdx.x, c = threadIdx.x;
    float a0 = alpha[0], a1 = alpha[1];
    float m  = fmaxf(a0, a1);
    float e0 = __expf(a0 - m), e1 = __expf(a1 - m);
    float inv = 1.f / (e0 + e1);
    float aw0 = e0*inv, aw1 = e1*inv;
    int win = tok / NT, n = tok % NT;
    int bb = win >> 6; int whi = (win & 63) >> 3, wwi = win & 7;
    int dz = n/49, r = n%49, hy = r/7, wl = r%7;
    int hs = whi*7 + hy, ws = wwi*7 + wl;
    int d0 = (dz + 4) & 7;
    int h0 = hs + 3; if (h0 >= HDIM) h0 -= HDIM;
    int w0 = ws + 3; if (w0 >= WDIM) w0 -= WDIM;
    size_t oi = ((size_t)(bb*CB + c)*DDIM + d0)*HWs + h0*WDIM + w0;
    size_t ti = (size_t)tok*CB + c;
    g_x1[oi] = x[oi] + aw0*g_p0[ti] + aw1*g_p1[ti];
}

// ---------------- LN2 (writes tf32-rounded x2) ----------------
__global__ void k_ln2(const float* __restrict__ lw, const float* __restrict__ lb) {
    __shared__ float row[CB*WDIM];
    __shared__ float s_mu[WDIM], s_inv[WDIM];
    int bid = blockIdx.x;
    int h = bid % HDIM; int t = bid / HDIM; int d = t & 7; int bb = t >> 3;
    size_t base = (size_t)bb*CB*SP + d*HWs + h*WDIM;
    for (int i = threadIdx.x; i < CB*WDIM; i += blockDim.x)
        row[i] = g_x1[base + (size_t)(i/WDIM)*SP + (i%WDIM)];
    __syncthreads();
    if (threadIdx.x < WDIM) {
        int w = threadIdx.x;
        float mu = 0.f;
        for (int c = 0; c < CB; c++) mu += row[c*WDIM + w];
        mu *= (1.0f/CB);
        float var = 0.f;
        for (int c = 0; c < CB; c++) { float dv = row[c*WDIM + w] - mu; var += dv*dv; }
        var *= (1.0f/CB);
        s_mu[w] = mu; s_inv[w] = rsqrtf(var + 1e-5f);
    }
    __syncthreads();
    for (int i = threadIdx.x; i < CB*WDIM; i += blockDim.x) {
        int c = i / WDIM, w = i % WDIM;
        g_x2[base + (size_t)c*SP + w] =
            to_tf32((row[i] - s_mu[w]) * s_inv[w] * lw[c] + lb[c]);
    }
}

// ---------------- build effective conv weights (NAS fold, tf32-rounded) ------
__global__ void k_weff(const float* __restrict__ c3w, const float* __restrict__ c3b,
                       const float* __restrict__ c1w, const float* __restrict__ c1b,
                       const float* __restrict__ dww, const float* __restrict__ dwb,
                       const float* __restrict__ alpha) {
    float a[4]; float m = -1e30f;
    #pragma unroll
    for (int i = 0; i < 4; i++) { a[i] = alpha[i]; m = fmaxf(m, a[i]); }
    float s = 0.f;
    #pragma unroll
    for (int i = 0; i < 4; i++) { a[i] = __expf(a[i] - m); s += a[i]; }
    float inv = 1.f / s;
    #pragma unroll
    for (int i = 0; i < 4; i++) a[i] *= inv;
    int total = CB*CB*27;
    for (int idx = blockIdx.x*blockDim.x + threadIdx.x; idx < total; idx += gridDim.x*blockDim.x) {
        int t = idx % 27; int rest = idx / 27; int ci = rest % CB; int co = rest / CB;
        float val = a[0] * c3w[idx];
        if (t == 13)            val += a[1] * c1w[co*CB + ci];
        if (ci == co)           val += a[2] * dww[co*27 + t];
        if (t == 13 && ci == co) val += a[3];
        int tt = t / 3, tw = t % 3;
        g_weff[(((size_t)tt*CB + ci)*3 + tw)*CB + co] = to_tf32(val);
    }
    int gid = blockIdx.x*blockDim.x + threadIdx.x;
    if (gid < CB) g_beff[gid] = a[0]*c3b[gid] + a[1]*c1b[gid] + a[2]*dwb[gid];
}

// ---------------- FFN as tf32 implicit-GEMM mma + residual -------------------
// block: 96 co (M) x 224 pixels (N = 4 h-rows x 56 w), K = 2592 = 81 chunks of 32.
// 8 warps: wm = warp/4 (2 M-halves of 48), wn = warp%4 (h-row). Warp tile 48x56.
#define KCH 32
#define AST 104   // A smem stride [k][co]
#define BST 232   // B smem stride [k][n]

__device__ __forceinline__ void mma_tf32(float* c, const unsigned* a, unsigned b0, unsigned b1) {
    asm volatile(
        "mma.sync.aligned.m16n8k8.row.col.f32.tf32.tf32.f32 "
        "{%0,%1,%2,%3}, {%4,%5,%6,%7}, {%8,%9}, {%0,%1,%2,%3};\n"
        : "+f"(c[0]), "+f"(c[1]), "+f"(c[2]), "+f"(c[3])
        : "r"(a[0]), "r"(a[1]), "r"(a[2]), "r"(a[3]), "r"(b0), "r"(b1));
}

__global__ void __launch_bounds__(256) k_ffn_mma(float* __restrict__ out) {
    __shared__ float As[KCH*AST];
    __shared__ float Bs[KCH*BST];

    int bid = blockIdx.x;                   // 224 = 2*8*14
    int h4 = bid % 14; int t = bid / 14; int d = t & 7; int bb = t >> 3;
    int h0 = h4*4;
    int tid = threadIdx.x;
    int warp = tid >> 5, lane = tid & 31;
    int wm = warp >> 2, wn = warp & 3;
    int lg = lane >> 2, lq = lane & 3;      // groupID, threadID_in_group

    float acc[3][7][4];
    #pragma unroll
    for (int mt = 0; mt < 3; mt++) {
        int m = wm*48 + mt*16 + lg;
        float b0 = g_beff[m], b8 = g_beff[m + 8];
        #pragma unroll
        for (int nt = 0; nt < 7; nt++) {
            acc[mt][nt][0] = b0; acc[mt][nt][1] = b0;
            acc[mt][nt][2] = b8; acc[mt][nt][3] = b8;
        }
    }

    // B-staging thread mapping: kk = tid/8 (0..31), nlane = tid%8
    int kk = tid >> 3, nlane = tid & 7;

    for (int kc = 0; kc < 81; kc++) {
        __syncthreads();
        // ---- stage A chunk: W_eff rows k = kc*32..+31, all 96 co ----
        #pragma unroll
        for (int s = 0; s < 12; s++) {
            int i = tid + s*256;
            int k = i / 96, co = i % 96;
            As[k*AST + co] = g_weff[(size_t)(kc*KCH + k)*CB + co];
        }
        // ---- stage B chunk (im2col) ----
        {
            int kg = kc*KCH + kk;
            int tt = kg / 288; int r = kg % 288; int ci = r / 3; int tw = r % 3;
            int td = tt / 3, th = tt % 3;
            int sd = d + td - 1;
            bool dok = (unsigned)sd < 8u;
            const float* rowp[4]; bool rok[4];
            #pragma unroll
            for (int hr = 0; hr < 4; hr++) {
                int sh = h0 + hr + th - 1;
                rok[hr] = dok && (unsigned)sh < 56u;
                rowp[hr] = g_x2 + ((size_t)(bb*CB + ci)*DDIM + sd)*HWs + sh*WDIM + (tw - 1);
            }
            float* bdst = Bs + kk*BST;
            #pragma unroll
            for (int j = 0; j < 28; j++) {
                const int hr = (j*8) / 56;
                const int wb = (j*8) % 56;
                int w = wb + nlane;
                // source col = w + tw - 1 (rowp already shifted by tw-1)
                bool ok = rok[hr] && ((unsigned)(w + tw - 1) < 56u);
                bdst[j*8 + nlane] = ok ? rowp[hr][w] : 0.f;
            }
        }
        __syncthreads();
        // ---- mma over 4 k8 steps ----
        #pragma unroll
        for (int k8 = 0; k8 < 4; k8++) {
            int kb = k8*8;
            unsigned a[3][4];
            #pragma unroll
            for (int mt = 0; mt < 3; mt++) {
                const float* ap = As + (kb + lq)*AST + wm*48 + mt*16 + lg;
                a[mt][0] = __float_as_uint(ap[0]);
                a[mt][1] = __float_as_uint(ap[8]);
                a[mt][2] = __float_as_uint(ap[4*AST]);
                a[mt][3] = __float_as_uint(ap[4*AST + 8]);
            }
            #pragma unroll
            for (int nt = 0; nt < 7; nt++) {
                const float* bp = Bs + (kb + lq)*BST + wn*56 + nt*8 + lg;
                unsigned b0 = __float_as_uint(bp[0]);
                unsigned b1 = __float_as_uint(bp[4*BST]);
                mma_tf32(acc[0][nt], a[0], b0, b1);
                mma_tf32(acc[1][nt], a[1], b0, b1);
                mma_tf32(acc[2][nt], a[2], b0, b1);
            }
        }
    }

    // ---- epilogue: residual + store (hr of this warp = wn) ----
    int hrow = h0 + wn;
    #pragma unroll
    for (int mt = 0; mt < 3; mt++) {
        int m = wm*48 + mt*16 + lg;
        size_t base = ((size_t)(bb*CB + m)*DDIM + d)*HWs + hrow*WDIM;
        #pragma unroll
        for (int nt = 0; nt < 7; nt++) {
            int w0 = nt*8 + lq*2;
            size_t i0 = base + w0;
            size_t i1 = i0 + (size_t)8*SP;   // channel m+8: stride DDIM*HWs = SP
            float2 r0 = *(const float2*)(g_x1 + i0);
            float2 r1 = *(const float2*)(g_x1 + i1);
            float2 o0 = make_float2(r0.x + acc[mt][nt][0], r0.y + acc[mt][nt][1]);
            float2 o1 = make_float2(r1.x + acc[mt][nt][2], r1.y + acc[mt][nt][3]);
            *(float2*)(out + i0) = o0;
            *(float2*)(out + i1) = o1;
        }
    }
}

// ---------------- host launch ----------------
extern "C" void kernel_launch(void* const* d_in, const int* in_sizes, int n_in,
                              void* d_out, int out_size) {
    (void)in_sizes; (void)n_in; (void)out_size;
    const float* x      = (const float*)d_in[0];
    const float* ln1w   = (const float*)d_in[1];
    const float* ln1b   = (const float*)d_in[2];
    const float* ln2w   = (const float*)d_in[3];
    const float* ln2b   = (const float*)d_in[4];
    const float* qkvw0  = (const float*)d_in[5];
    const float* qkvb0  = (const float*)d_in[6];
    const float* projw0 = (const float*)d_in[7];
    const float* projb0 = (const float*)d_in[8];
    const float* rpb0   = (const float*)d_in[9];
    const float* qkvw1  = (const float*)d_in[10];
    const float* qkvb1  = (const float*)d_in[11];
    const float* projw1 = (const float*)d_in[12];
    const float* projb1 = (const float*)d_in[13];
    const float* rpb1   = (const float*)d_in[14];
    const float* alphaA = (const float*)d_in[15];
    const float* c3w    = (const float*)d_in[16];
    const float* c3b    = (const float*)d_in[17];
    const float* c1w    = (const float*)d_in[18];
    const float* c1b    = (const float*)d_in[19];
    const float* dww    = (const float*)d_in[20];
    const float* dwb    = (const float*)d_in[21];
    const float* alphaF = (const float*)d_in[22];
    float* out = (float*)d_out;

    float *p_xw, *p_q0, *p_q1, *p_o0, *p_o1, *p_p0, *p_p1;
    cudaGetSymbolAddress((void**)&p_xw, g_xw);
    cudaGetSymbolAddress((void**)&p_q0, g_qkv0);
    cudaGetSymbolAddress((void**)&p_q1, g_qkv1);
    cudaGetSymbolAddress((void**)&p_o0, g_o0);
    cudaGetSymbolAddress((void**)&p_o1, g_o1);
    cudaGetSymbolAddress((void**)&p_p0, g_p0);
    cudaGetSymbolAddress((void**)&p_p1, g_p1);

    int smA0 = (32*KS_STRIDE + 32*VS_STRIDE + 8*4*PS_STRIDE + 2535 + 392) * 4;
    int smA1 = (16*KS_STRIDE + 16*VS_STRIDE + 8*4*PS_STRIDE + 2535 + 392) * 4;
    cudaFuncSetAttribute(k_attn3<32,3>, cudaFuncAttributeMaxDynamicSharedMemorySize, smA0);
    cudaFuncSetAttribute(k_attn3<16,6>, cudaFuncAttributeMaxDynamicSharedMemorySize, smA1);

    // 1) LN1 + roll + window partition
    k_ln1<<<2*DDIM*HDIM, 256>>>(x, ln1w, ln1b);

    // 2) QKV GEMMs
    dim3 gq(NTOK/64, 3);
    k_gemm96<<<gq, 256>>>(p_xw, qkvw0, qkvb0, p_q0, 288);
    k_gemm96<<<gq, 256>>>(p_xw, qkvw1, qkvb1, p_q1, 288);

    // 3) windowed attention
    k_attn3<32,3><<<NWIN*3, 256, smA0>>>(p_q0, rpb0, p_o0);
    k_attn3<16,6><<<NWIN*6, 256, smA1>>>(p_q1, rpb1, p_o1);

    // 4) output projections
    dim3 gp(NTOK/64, 1);
    k_gemm96<<<gp, 256>>>(p_o0, projw0, projb0, p_p0, 96);
    k_gemm96<<<gp, 256>>>(p_o1, projw1, projb1, p_p1, 96);

    // 5) NAS mix + window reverse + un-roll + residual
    k_combine<<<NTOK, CB>>>(x, alphaA);

    // 6) LN2 (tf32-rounded output)
    k_ln2<<<2*DDIM*HDIM, 256>>>(ln2w, ln2b);

    // 7) effective conv weights (tf32) + tensor-core FFN + residual
    k_weff<<<128, 256>>>(c3w, c3b, c1w, c1b, dww, dwb, alphaF);
    k_ffn_mma<<<2*DDIM*(HDIM/4), 256>>>(out);
}

// round 9
// speedup vs baseline: 2.3241x; 1.3970x over previous
#include <cuda_runtime.h>
#include <cstdint>

#define CB 96
#define DDIM 8
#define HDIM 56
#define WDIM 56
#define SP   (DDIM*HDIM*WDIM)   // 25088
#define HWs  (HDIM*WDIM)        // 3136
#define NT   392                // tokens per window
#define NTP  400                // padded tokens (25 m16 tiles, 50 n8 tiles)
#define NWIN 128                // total windows (B=2, 64 per batch)
#define NTOK (NWIN*NT)          // 50176

typedef unsigned long long u64;

// ---------------- packed f32x2 helpers ----------------
__device__ __forceinline__ u64 pk2(float lo, float hi) {
    u64 r;
    asm("mov.b64 %0, {%1, %2};" : "=l"(r)
        : "r"(__float_as_uint(lo)), "r"(__float_as_uint(hi)));
    return r;
}
__device__ __forceinline__ void upk(u64 v, float& lo, float& hi) {
    unsigned a, b;
    asm("mov.b64 {%0, %1}, %2;" : "=r"(a), "=r"(b) : "l"(v));
    lo = __uint_as_float(a); hi = __uint_as_float(b);
}
__device__ __forceinline__ void fma2(u64& d, u64 a, u64 b) {
    asm("fma.rn.f32x2 %0, %1, %2, %0;" : "+l"(d) : "l"(a), "l"(b));
}
__device__ __forceinline__ u64 add2(u64 a, u64 b) {
    u64 d; asm("add.rn.f32x2 %0, %1, %2;" : "=l"(d) : "l"(a), "l"(b)); return d;
}
__device__ __forceinline__ float to_tf32(float x) {
    unsigned u;
    asm("cvt.rna.tf32.f32 %0, %1;" : "=r"(u) : "f"(x));
    return __uint_as_float(u);
}

__device__ __forceinline__ void mma_tf32(float* c, const unsigned* a, unsigned b0, unsigned b1) {
    asm volatile(
        "mma.sync.aligned.m16n8k8.row.col.f32.tf32.tf32.f32 "
        "{%0,%1,%2,%3}, {%4,%5,%6,%7}, {%8,%9}, {%0,%1,%2,%3};\n"
        : "+f"(c[0]), "+f"(c[1]), "+f"(c[2]), "+f"(c[3])
        : "r"(a[0]), "r"(a[1]), "r"(a[2]), "r"(a[3]), "r"(b0), "r"(b1));
}

// ---------------- scratch (device globals; no allocation) ----------------
__device__ float g_xw  [NTOK*CB];
__device__ float g_qkv0[NTOK*288];
__device__ float g_qkv1[NTOK*288];
__device__ float g_o0  [NTOK*CB];
__device__ float g_o1  [NTOK*CB];
__device__ float g_p0  [NTOK*CB];
__device__ float g_p1  [NTOK*CB];
__device__ float g_x1  [2*CB*SP];
__device__ float g_x2  [2*CB*SP];     // LN2(x1), tf32-rounded
__device__ float g_weff[9*CB*3*CB];   // [k][co], tf32-rounded
__device__ float g_beff[CB];
__device__ float g_bias[4*9*NTP*NTP]; // [class][head(9)][i][j]: rpb bias + mask, -1e9 padding

// ---------------- LN1 + shift-roll + window partition ----------------
__global__ void k_ln1(const float* __restrict__ x,
                      const float* __restrict__ lw, const float* __restrict__ lb) {
    __shared__ float row[CB*WDIM];
    int bid = blockIdx.x;
    int h = bid % HDIM; int t = bid / HDIM; int d = t & 7; int bb = t >> 3;
    const float* base = x + (size_t)bb*CB*SP + d*HWs + h*WDIM;
    for (int i = threadIdx.x; i < CB*WDIM; i += blockDim.x) {
        int c = i / WDIM, w = i % WDIM;
        row[i] = base[(size_t)c*SP + w];
    }
    __syncthreads();
    if (threadIdx.x < WDIM) {
        int w = threadIdx.x;
        float mu = 0.f;
        for (int c = 0; c < CB; c++) mu += row[c*WDIM + w];
        mu *= (1.0f/CB);
        float var = 0.f;
        for (int c = 0; c < CB; c++) { float dv = row[c*WDIM + w] - mu; var += dv*dv; }
        var *= (1.0f/CB);
        float inv = rsqrtf(var + 1e-5f);
        int ds = (d + 4) & 7;
        int hs = h - 3; if (hs < 0) hs += HDIM;
        int ws = w - 3; if (ws < 0) ws += WDIM;
        int win = bb*64 + (hs/7)*8 + (ws/7);
        int n   = ds*49 + (hs%7)*7 + (ws%7);
        float* op = g_xw + ((size_t)win*NT + n)*CB;
        for (int c = 0; c < CB; c++)
            op[c] = (row[c*WDIM + w] - mu) * inv * lw[c] + lb[c];
    }
}

// ---------------- GEMM (f32x2): Out[M,Ntot] = A[M,96]*Bw[Ntot,96]^T + bias ----
__global__ void k_gemm96(const float* __restrict__ A, const float* __restrict__ Bw,
                         const float* __restrict__ bias, float* __restrict__ Out, int Ntot) {
    __shared__ float As[64][49];
    __shared__ float Bt[48][100];
    int m0 = blockIdx.x * 64;
    int n0 = blockIdx.y * 96;
    int tx = threadIdx.x & 15, ty = threadIdx.x >> 4;
    u64 acc2[4][3];
    #pragma unroll
    for (int r = 0; r < 4; r++)
        #pragma unroll
        for (int c = 0; c < 3; c++) acc2[r][c] = 0ULL;
    for (int kc = 0; kc < 2; kc++) {
        __syncthreads();
        for (int i = threadIdx.x; i < 64*48; i += 256) {
            int r = i/48, c = i%48;
            As[r][c] = A[(size_t)(m0 + r)*CB + kc*48 + c];
        }
        for (int i = threadIdx.x; i < 96*48; i += 256) {
            int r = i%96, c = i/96;
            Bt[c][r] = Bw[(size_t)(n0 + r)*CB + kc*48 + c];
        }
        __syncthreads();
        #pragma unroll 4
        for (int k = 0; k < 48; k++) {
            u64 ap[4];
            #pragma unroll
            for (int r = 0; r < 4; r++) {
                float a = As[ty*4 + r][k];
                ap[r] = pk2(a, a);
            }
            u64 b0 = *(const u64*)(&Bt[k][tx*6 + 0]);
            u64 b1 = *(const u64*)(&Bt[k][tx*6 + 2]);
            u64 b2 = *(const u64*)(&Bt[k][tx*6 + 4]);
            #pragma unroll
            for (int r = 0; r < 4; r++) {
                fma2(acc2[r][0], ap[r], b0);
                fma2(acc2[r][1], ap[r], b1);
                fma2(acc2[r][2], ap[r], b2);
            }
        }
    }
    const float* bp = bias + n0 + tx*6;
    u64 bb0 = *(const u64*)(bp + 0);
    u64 bb1 = *(const u64*)(bp + 2);
    u64 bb2 = *(const u64*)(bp + 4);
    #pragma unroll
    for (int r = 0; r < 4; r++) {
        float* op = Out + (size_t)(m0 + ty*4 + r)*Ntot + n0 + tx*6;
        *(u64*)(op + 0) = add2(acc2[r][0], bb0);
        *(u64*)(op + 2) = add2(acc2[r][1], bb1);
        *(u64*)(op + 4) = add2(acc2[r][2], bb2);
    }
}

// ---------------- bias+mask table precompute ----------------
// g_bias[class][head9][i][j]; class = (whi==7)*2 + (wwi==7)
__global__ void k_bias(const float* __restrict__ rpb0, const float* __restrict__ rpb1) {
    int bid = blockIdx.x;
    int i = bid % NTP; int rest = bid / NTP;
    int head = rest % 9; int cls = rest / 9;
    int j = threadIdx.x;
    float v;
    if (i >= NT || j >= NT) {
        v = -1e9f;
    } else {
        int dzi = i/49, ri = i%49, hyi = ri/7, wli = ri%7;
        int dzj = j/49, rj = j%49, hyj = rj/7, wlj = rj%7;
        int idx = (dzi - dzj + 7)*169 + (hyi - hyj + 6)*13 + (wli - wlj + 6);
        float b = (head < 3) ? rpb0[idx*3 + head] : rpb1[idx*6 + head - 3];
        int ha = cls >> 1, wa = cls & 1;
        int hri = ha ? (hyi < 4 ? 1 : 2) : 0;
        int wri = wa ? (wli < 4 ? 1 : 2) : 0;
        int hrj = ha ? (hyj < 4 ? 1 : 2) : 0;
        int wrj = wa ? (wlj < 4 ? 1 : 2) : 0;
        int li = (dzi < 4 ? 0 : 1)*9 + hri*3 + wri;
        int lj = (dzj < 4 ? 0 : 1)*9 + hrj*3 + wrj;
        v = b + ((li != lj) ? -100.f : 0.f);
    }
    g_bias[((size_t)(cls*9 + head)*NTP + i)*NTP + j] = v;
}

// ---------------- windowed attention v4: tf32 mma + flash softmax ------------
// One (win, head) per block, 8 warps. Tokens padded 392->400.
// Warp handles m16 tile rows tr = warp, warp+8, ... (25 total).
// Per tile row: 5 column chunks of 80; online softmax; P chunk in per-warp smem.
template<int DH, int NH, int HOFF, int MAXB>
__global__ void __launch_bounds__(256, MAXB) k_attn_mma(const float* __restrict__ qkv,
                                                        float* __restrict__ outp) {
    constexpr int KST = 408;                 // Ksm [DH][KST], 408%32=24 -> conflict-free B-frags
    constexpr int VST = (DH == 32) ? 40 : 24;// Vsm [400][VST]
    constexpr int PST = 84;                  // Psm [16][PST] per warp (lg*20+lq covers 32 banks)
    constexpr int NKS = DH/8;                // k8 steps in QK
    constexpr int NVT = DH/8;                // n8 tiles in PV
    extern __shared__ float sm[];
    float* Ksm = sm;                         // DH*KST
    float* Vsm = Ksm + DH*KST;               // 400*VST
    float* Psm = Vsm + NTP*VST;              // 8 * 16*PST

    int win = blockIdx.x / NH, hd = blockIdx.x % NH;
    const float* qb = qkv + (size_t)win*NT*288;
    int tid = threadIdx.x, warp = tid >> 5, lane = tid & 31;
    int lg = lane >> 2, lq = lane & 3;
    const float scale = rsqrtf((float)DH);

    // stage K transposed [d][n] (tf32), zero padding
    for (int idx = tid; idx < NTP*(DH/4); idx += 256) {
        int n = idx / (DH/4), d4 = (idx % (DH/4))*4;
        if (n < NT) {
            float4 kv = *(const float4*)(qb + (size_t)n*288 + 96 + hd*DH + d4);
            Ksm[(d4+0)*KST + n] = to_tf32(kv.x);
            Ksm[(d4+1)*KST + n] = to_tf32(kv.y);
            Ksm[(d4+2)*KST + n] = to_tf32(kv.z);
            Ksm[(d4+3)*KST + n] = to_tf32(kv.w);
        } else {
            Ksm[(d4+0)*KST + n] = 0.f;
            Ksm[(d4+1)*KST + n] = 0.f;
            Ksm[(d4+2)*KST + n] = 0.f;
            Ksm[(d4+3)*KST + n] = 0.f;
        }
    }
    // stage V [j][d] (tf32), zero padding
    for (int idx = tid; idx < NTP*(DH/4); idx += 256) {
        int j = idx / (DH/4), d4 = (idx % (DH/4))*4;
        float4 vv = make_float4(0.f, 0.f, 0.f, 0.f);
        if (j < NT) {
            float4 t4 = *(const float4*)(qb + (size_t)j*288 + 192 + hd*DH + d4);
            vv = make_float4(to_tf32(t4.x), to_tf32(t4.y), to_tf32(t4.z), to_tf32(t4.w));
        }
        *(float4*)(Vsm + j*VST + d4) = vv;
    }
    __syncthreads();

    int cls = ((((win & 63) >> 3) == 7) ? 2 : 0) | (((win & 7) == 7) ? 1 : 0);
    const float* bias = g_bias + (size_t)(cls*9 + HOFF + hd)*(NTP*NTP);
    float* pwarp = Psm + warp*(16*PST);

    for (int tr = warp; tr < 25; tr += 8) {
        int i0 = tr*16;
        int r0 = i0 + lg;
        int r1 = min(i0 + lg + 8, NT - 1);   // clamp padded rows (output guarded)
        // Q fragments (held for whole tile row)
        unsigned qa[NKS][4];
        #pragma unroll
        for (int ks = 0; ks < NKS; ks++) {
            int d = ks*8 + lq;
            qa[ks][0] = __float_as_uint(to_tf32(qb[(size_t)r0*288 + hd*DH + d]     * scale));
            qa[ks][1] = __float_as_uint(to_tf32(qb[(size_t)r1*288 + hd*DH + d]     * scale));
            qa[ks][2] = __float_as_uint(to_tf32(qb[(size_t)r0*288 + hd*DH + d + 4] * scale));
            qa[ks][3] = __float_as_uint(to_tf32(qb[(size_t)r1*288 + hd*DH + d + 4] * scale));
        }
        float m0 = -1e30f, m1 = -1e30f, l0 = 0.f, l1 = 0.f;
        float O[NVT][4];
        #pragma unroll
        for (int nt = 0; nt < NVT; nt++) { O[nt][0]=0.f; O[nt][1]=0.f; O[nt][2]=0.f; O[nt][3]=0.f; }

        #pragma unroll
        for (int ch = 0; ch < 5; ch++) {
            int j0 = ch*80;
            float c[10][4];
            #pragma unroll
            for (int nt = 0; nt < 10; nt++) { c[nt][0]=0.f; c[nt][1]=0.f; c[nt][2]=0.f; c[nt][3]=0.f; }
            // ---- S = Q K^T (tile row x 80 cols) ----
            #pragma unroll
            for (int ks = 0; ks < NKS; ks++) {
                #pragma unroll
                for (int nt = 0; nt < 10; nt++) {
                    const float* bp = Ksm + (ks*8 + lq)*KST + j0 + nt*8 + lg;
                    unsigned b0 = __float_as_uint(bp[0]);
                    unsigned b1 = __float_as_uint(bp[4*KST]);
                    mma_tf32(c[nt], qa[ks], b0, b1);
                }
            }
            // ---- add bias+mask (precomputed table) ----
            #pragma unroll
            for (int nt = 0; nt < 10; nt++) {
                const float* br0 = bias + (size_t)(i0 + lg)*NTP + j0 + nt*8 + lq*2;
                float2 b0v = *(const float2*)br0;
                float2 b1v = *(const float2*)(br0 + 8*NTP);
                c[nt][0] += b0v.x; c[nt][1] += b0v.y;
                c[nt][2] += b1v.x; c[nt][3] += b1v.y;
            }
            // ---- online softmax ----
            float cm0 = -1e30f, cm1 = -1e30f;
            #pragma unroll
            for (int nt = 0; nt < 10; nt++) {
                cm0 = fmaxf(cm0, fmaxf(c[nt][0], c[nt][1]));
                cm1 = fmaxf(cm1, fmaxf(c[nt][2], c[nt][3]));
            }
            cm0 = fmaxf(cm0, __shfl_xor_sync(0xffffffffu, cm0, 1));
            cm0 = fmaxf(cm0, __shfl_xor_sync(0xffffffffu, cm0, 2));
            cm1 = fmaxf(cm1, __shfl_xor_sync(0xffffffffu, cm1, 1));
            cm1 = fmaxf(cm1, __shfl_xor_sync(0xffffffffu, cm1, 2));
            float mn0 = fmaxf(m0, cm0), mn1 = fmaxf(m1, cm1);
            float s0 = __expf(m0 - mn0), s1 = __expf(m1 - mn1);
            m0 = mn0; m1 = mn1;
            l0 *= s0; l1 *= s1;
            #pragma unroll
            for (int nt = 0; nt < NVT; nt++) {
                O[nt][0] *= s0; O[nt][1] *= s0;
                O[nt][2] *= s1; O[nt][3] *= s1;
            }
            float sum0 = 0.f, sum1 = 0.f;
            #pragma unroll
            for (int nt = 0; nt < 10; nt++) {
                c[nt][0] = to_tf32(__expf(c[nt][0] - m0)); sum0 += c[nt][0];
                c[nt][1] = to_tf32(__expf(c[nt][1] - m0)); sum0 += c[nt][1];
                c[nt][2] = to_tf32(__expf(c[nt][2] - m1)); sum1 += c[nt][2];
                c[nt][3] = to_tf32(__expf(c[nt][3] - m1)); sum1 += c[nt][3];
            }
            sum0 += __shfl_xor_sync(0xffffffffu, sum0, 1);
            sum0 += __shfl_xor_sync(0xffffffffu, sum0, 2);
            sum1 += __shfl_xor_sync(0xffffffffu, sum1, 1);
            sum1 += __shfl_xor_sync(0xffffffffu, sum1, 2);
            l0 += sum0; l1 += sum1;
            // ---- store P chunk [i][j] ----
            #pragma unroll
            for (int nt = 0; nt < 10; nt++) {
                int jl = nt*8 + lq*2;
                *(float2*)(pwarp + lg*PST + jl)     = make_float2(c[nt][0], c[nt][1]);
                *(float2*)(pwarp + (lg+8)*PST + jl) = make_float2(c[nt][2], c[nt][3]);
            }
            __syncwarp();
            // ---- O += P V ----
            #pragma unroll
            for (int ks = 0; ks < 10; ks++) {
                unsigned pa[4];
                const float* pp = pwarp + lg*PST + ks*8 + lq;
                pa[0] = __float_as_uint(pp[0]);
                pa[1] = __float_as_uint(pp[8*PST]);
                pa[2] = __float_as_uint(pp[4]);
                pa[3] = __float_as_uint(pp[8*PST + 4]);
                #pragma unroll
                for (int nt = 0; nt < NVT; nt++) {
                    const float* vp = Vsm + (j0 + ks*8 + lq)*VST + nt*8 + lg;
                    unsigned b0 = __float_as_uint(vp[0]);
                    unsigned b1 = __float_as_uint(vp[4*VST]);
                    mma_tf32(O[nt], pa, b0, b1);
                }
            }
            __syncwarp();
        }
        // ---- epilogue ----
        float li0 = 1.f / l0, li1 = 1.f / l1;
        int ir0 = i0 + lg, ir1 = i0 + lg + 8;
        #pragma unroll
        for (int nt = 0; nt < NVT; nt++) {
            *(float2*)(outp + ((size_t)win*NT + ir0)*CB + hd*DH + nt*8 + lq*2)
                = make_float2(O[nt][0]*li0, O[nt][1]*li0);
            if (ir1 < NT)
                *(float2*)(outp + ((size_t)win*NT + ir1)*CB + hd*DH + nt*8 + lq*2)
                    = make_float2(O[nt][2]*li1, O[nt][3]*li1);
        }
    }
}

// ---------------- NAS mix + window reverse + unroll + residual ----------------
__global__ void k_combine(const float* __restrict__ x, const float* __restrict__ alpha) {
    int tok = blockIdx.x, c = threadIdx.x;
    float a0 = alpha[0], a1 = alpha[1];
    float m  = fmaxf(a0, a1);
    float e0 = __expf(a0 - m), e1 = __expf(a1 - m);
    float inv = 1.f / (e0 + e1);
    float aw0 = e0*inv, aw1 = e1*inv;
    int win = tok / NT, n = tok % NT;
    int bb = win >> 6; int whi = (win & 63) >> 3, wwi = win & 7;
    int dz = n/49, r = n%49, hy = r/7, wl = r%7;
    int hs = whi*7 + hy, ws = wwi*7 + wl;
    int d0 = (dz + 4) & 7;
    int h0 = hs + 3; if (h0 >= HDIM) h0 -= HDIM;
    int w0 = ws + 3; if (w0 >= WDIM) w0 -= WDIM;
    size_t oi = ((size_t)(bb*CB + c)*DDIM + d0)*HWs + h0*WDIM + w0;
    size_t ti = (size_t)tok*CB + c;
    g_x1[oi] = x[oi] + aw0*g_p0[ti] + aw1*g_p1[ti];
}

// ---------------- LN2 (writes tf32-rounded x2) ----------------
__global__ void k_ln2(const float* __restrict__ lw, const float* __restrict__ lb) {
    __shared__ float row[CB*WDIM];
    __shared__ float s_mu[WDIM], s_inv[WDIM];
    int bid = blockIdx.x;
    int h = bid % HDIM; int t = bid / HDIM; int d = t & 7; int bb = t >> 3;
    size_t base = (size_t)bb*CB*SP + d*HWs + h*WDIM;
    for (int i = threadIdx.x; i < CB*WDIM; i += blockDim.x)
        row[i] = g_x1[base + (size_t)(i/WDIM)*SP + (i%WDIM)];
    __syncthreads();
    if (threadIdx.x < WDIM) {
        int w = threadIdx.x;
        float mu = 0.f;
        for (int c = 0; c < CB; c++) mu += row[c*WDIM + w];
        mu *= (1.0f/CB);
        float var = 0.f;
        for (int c = 0; c < CB; c++) { float dv = row[c*WDIM + w] - mu; var += dv*dv; }
        var *= (1.0f/CB);
        s_mu[w] = mu; s_inv[w] = rsqrtf(var + 1e-5f);
    }
    __syncthreads();
    for (int i = threadIdx.x; i < CB*WDIM; i += blockDim.x) {
        int c = i / WDIM, w = i % WDIM;
        g_x2[base + (size_t)c*SP + w] =
            to_tf32((row[i] - s_mu[w]) * s_inv[w] * lw[c] + lb[c]);
    }
}

// ---------------- build effective conv weights (NAS fold, tf32-rounded) ------
__global__ void k_weff(const float* __restrict__ c3w, const float* __restrict__ c3b,
                       const float* __restrict__ c1w, const float* __restrict__ c1b,
                       const float* __restrict__ dww, const float* __restrict__ dwb,
                       const float* __restrict__ alpha) {
    float a[4]; float m = -1e30f;
    #pragma unroll
    for (int i = 0; i < 4; i++) { a[i] = alpha[i]; m = fmaxf(m, a[i]); }
    float s = 0.f;
    #pragma unroll
    for (int i = 0; i < 4; i++) { a[i] = __expf(a[i] - m); s += a[i]; }
    float inv = 1.f / s;
    #pragma unroll
    for (int i = 0; i < 4; i++) a[i] *= inv;
    int total = CB*CB*27;
    for (int idx = blockIdx.x*blockDim.x + threadIdx.x; idx < total; idx += gridDim.x*blockDim.x) {
        int t = idx % 27; int rest = idx / 27; int ci = rest % CB; int co = rest / CB;
        float val = a[0] * c3w[idx];
        if (t == 13)            val += a[1] * c1w[co*CB + ci];
        if (ci == co)           val += a[2] * dww[co*27 + t];
        if (t == 13 && ci == co) val += a[3];
        int tt = t / 3, tw = t % 3;
        g_weff[(((size_t)tt*CB + ci)*3 + tw)*CB + co] = to_tf32(val);
    }
    int gid = blockIdx.x*blockDim.x + threadIdx.x;
    if (gid < CB) g_beff[gid] = a[0]*c3b[gid] + a[1]*c1b[gid] + a[2]*dwb[gid];
}

// ---------------- FFN as tf32 implicit-GEMM mma + residual -------------------
#define KCH 32
#define AST 104
#define BST 232

__global__ void __launch_bounds__(256) k_ffn_mma(float* __restrict__ out) {
    __shared__ float As[KCH*AST];
    __shared__ float Bs[KCH*BST];

    int bid = blockIdx.x;
    int h4 = bid % 14; int t = bid / 14; int d = t & 7; int bb = t >> 3;
    int h0 = h4*4;
    int tid = threadIdx.x;
    int warp = tid >> 5, lane = tid & 31;
    int wm = warp >> 2, wn = warp & 3;
    int lg = lane >> 2, lq = lane & 3;

    float acc[3][7][4];
    #pragma unroll
    for (int mt = 0; mt < 3; mt++) {
        int m = wm*48 + mt*16 + lg;
        float b0 = g_beff[m], b8 = g_beff[m + 8];
        #pragma unroll
        for (int nt = 0; nt < 7; nt++) {
            acc[mt][nt][0] = b0; acc[mt][nt][1] = b0;
            acc[mt][nt][2] = b8; acc[mt][nt][3] = b8;
        }
    }

    int kk = tid >> 3, nlane = tid & 7;

    for (int kc = 0; kc < 81; kc++) {
        __syncthreads();
        #pragma unroll
        for (int s = 0; s < 12; s++) {
            int i = tid + s*256;
            int k = i / 96, co = i % 96;
            As[k*AST + co] = g_weff[(size_t)(kc*KCH + k)*CB + co];
        }
        {
            int kg = kc*KCH + kk;
            int tt = kg / 288; int r = kg % 288; int ci = r / 3; int tw = r % 3;
            int td = tt / 3, th = tt % 3;
            int sd = d + td - 1;
            bool dok = (unsigned)sd < 8u;
            const float* rowp[4]; bool rok[4];
            #pragma unroll
            for (int hr = 0; hr < 4; hr++) {
                int sh = h0 + hr + th - 1;
                rok[hr] = dok && (unsigned)sh < 56u;
                rowp[hr] = g_x2 + ((size_t)(bb*CB + ci)*DDIM + sd)*HWs + sh*WDIM + (tw - 1);
            }
            float* bdst = Bs + kk*BST;
            #pragma unroll
            for (int j = 0; j < 28; j++) {
                const int hr = (j*8) / 56;
                const int wb = (j*8) % 56;
                int w = wb + nlane;
                bool ok = rok[hr] && ((unsigned)(w + tw - 1) < 56u);
                bdst[j*8 + nlane] = ok ? rowp[hr][w] : 0.f;
            }
        }
        __syncthreads();
        #pragma unroll
        for (int k8 = 0; k8 < 4; k8++) {
            int kb = k8*8;
            unsigned a[3][4];
            #pragma unroll
            for (int mt = 0; mt < 3; mt++) {
                const float* ap = As + (kb + lq)*AST + wm*48 + mt*16 + lg;
                a[mt][0] = __float_as_uint(ap[0]);
                a[mt][1] = __float_as_uint(ap[8]);
                a[mt][2] = __float_as_uint(ap[4*AST]);
                a[mt][3] = __float_as_uint(ap[4*AST + 8]);
            }
            #pragma unroll
            for (int nt = 0; nt < 7; nt++) {
                const float* bp = Bs + (kb + lq)*BST + wn*56 + nt*8 + lg;
                unsigned b0 = __float_as_uint(bp[0]);
                unsigned b1 = __float_as_uint(bp[4*BST]);
                mma_tf32(acc[0][nt], a[0], b0, b1);
                mma_tf32(acc[1][nt], a[1], b0, b1);
                mma_tf32(acc[2][nt], a[2], b0, b1);
            }
        }
    }

    int hrow = h0 + wn;
    #pragma unroll
    for (int mt = 0; mt < 3; mt++) {
        int m = wm*48 + mt*16 + lg;
        size_t base = ((size_t)(bb*CB + m)*DDIM + d)*HWs + hrow*WDIM;
        #pragma unroll
        for (int nt = 0; nt < 7; nt++) {
            int w0 = nt*8 + lq*2;
            size_t i0 = base + w0;
            size_t i1 = i0 + (size_t)8*SP;
            float2 r0 = *(const float2*)(g_x1 + i0);
            float2 r1 = *(const float2*)(g_x1 + i1);
            float2 o0 = make_float2(r0.x + acc[mt][nt][0], r0.y + acc[mt][nt][1]);
            float2 o1 = make_float2(r1.x + acc[mt][nt][2], r1.y + acc[mt][nt][3]);
            *(float2*)(out + i0) = o0;
            *(float2*)(out + i1) = o1;
        }
    }
}

// ---------------- host launch ----------------
extern "C" void kernel_launch(void* const* d_in, const int* in_sizes, int n_in,
                              void* d_out, int out_size) {
    (void)in_sizes; (void)n_in; (void)out_size;
    const float* x      = (const float*)d_in[0];
    const float* ln1w   = (const float*)d_in[1];
    const float* ln1b   = (const float*)d_in[2];
    const float* ln2w   = (const float*)d_in[3];
    const float* ln2b   = (const float*)d_in[4];
    const float* qkvw0  = (const float*)d_in[5];
    const float* qkvb0  = (const float*)d_in[6];
    const float* projw0 = (const float*)d_in[7];
    const float* projb0 = (const float*)d_in[8];
    const float* rpb0   = (const float*)d_in[9];
    const float* qkvw1  = (const float*)d_in[10];
    const float* qkvb1  = (const float*)d_in[11];
    const float* projw1 = (const float*)d_in[12];
    const float* projb1 = (const float*)d_in[13];
    const float* rpb1   = (const float*)d_in[14];
    const float* alphaA = (const float*)d_in[15];
    const float* c3w    = (const float*)d_in[16];
    const float* c3b    = (const float*)d_in[17];
    const float* c1w    = (const float*)d_in[18];
    const float* c1b    = (const float*)d_in[19];
    const float* dww    = (const float*)d_in[20];
    const float* dwb    = (const float*)d_in[21];
    const float* alphaF = (const float*)d_in[22];
    float* out = (float*)d_out;

    float *p_xw, *p_q0, *p_q1, *p_o0, *p_o1, *p_p0, *p_p1;
    cudaGetSymbolAddress((void**)&p_xw, g_xw);
    cudaGetSymbolAddress((void**)&p_q0, g_qkv0);
    cudaGetSymbolAddress((void**)&p_q1, g_qkv1);
    cudaGetSymbolAddress((void**)&p_o0, g_o0);
    cudaGetSymbolAddress((void**)&p_o1, g_o1);
    cudaGetSymbolAddress((void**)&p_p0, g_p0);
    cudaGetSymbolAddress((void**)&p_p1, g_p1);

    // attention smem: Ksm + Vsm + Psm
    int smA0 = (32*408 + NTP*40 + 8*16*84) * 4;   // 159232 B
    int smA1 = (16*408 + NTP*24 + 8*16*84) * 4;   // 107520 B
    cudaFuncSetAttribute((const void*)k_attn_mma<32,3,0,1>,
                         cudaFuncAttributeMaxDynamicSharedMemorySize, smA0);
    cudaFuncSetAttribute((const void*)k_attn_mma<16,6,3,2>,
                         cudaFuncAttributeMaxDynamicSharedMemorySize, smA1);

    // 0) bias+mask table (depends only on rpb)
    k_bias<<<4*9*NTP, NTP>>>(rpb0, rpb1);

    // 1) LN1 + roll + window partition
    k_ln1<<<2*DDIM*HDIM, 256>>>(x, ln1w, ln1b);

    // 2) QKV GEMMs
    dim3 gq(NTOK/64, 3);
    k_gemm96<<<gq, 256>>>(p_xw, qkvw0, qkvb0, p_q0, 288);
    k_gemm96<<<gq, 256>>>(p_xw, qkvw1, qkvb1, p_q1, 288);

    // 3) windowed attention (tf32 mma, flash softmax)
    k_attn_mma<32,3,0,1><<<NWIN*3, 256, smA0>>>(p_q0, p_o0);
    k_attn_mma<16,6,3,2><<<NWIN*6, 256, smA1>>>(p_q1, p_o1);

    // 4) output projections
    dim3 gp(NTOK/64, 1);
    k_gemm96<<<gp, 256>>>(p_o0, projw0, projb0, p_p0, 96);
    k_gemm96<<<gp, 256>>>(p_o1, projw1, projb1, p_p1, 96);

    // 5) NAS mix + window reverse + un-roll + residual
    k_combine<<<NTOK, CB>>>(x, alphaA);

    // 6) LN2 (tf32-rounded output)
    k_ln2<<<2*DDIM*HDIM, 256>>>(ln2w, ln2b);

    // 7) effective conv weights (tf32) + tensor-core FFN + residual
    k_weff<<<128, 256>>>(c3w, c3b, c1w, c1b, dww, dwb, alphaF);
    k_ffn_mma<<<2*DDIM*(HDIM/4), 256>>>(out);
}

// round 10
// speedup vs baseline: 2.8210x; 1.2138x over previous
#include <cuda_runtime.h>
#include <cstdint>

#define CB 96
#define DDIM 8
#define HDIM 56
#define WDIM 56
#define SP   (DDIM*HDIM*WDIM)   // 25088
#define HWs  (HDIM*WDIM)        // 3136
#define NT   392                // tokens per window
#define NTP  400                // padded tokens
#define NWIN 128                // total windows (B=2, 64 per batch)
#define NTOK (NWIN*NT)          // 50176

typedef unsigned long long u64;

__device__ __forceinline__ float to_tf32(float x) {
    unsigned u;
    asm("cvt.rna.tf32.f32 %0, %1;" : "=r"(u) : "f"(x));
    return __uint_as_float(u);
}

__device__ __forceinline__ void mma_tf32(float* c, const unsigned* a, unsigned b0, unsigned b1) {
    asm volatile(
        "mma.sync.aligned.m16n8k8.row.col.f32.tf32.tf32.f32 "
        "{%0,%1,%2,%3}, {%4,%5,%6,%7}, {%8,%9}, {%0,%1,%2,%3};\n"
        : "+f"(c[0]), "+f"(c[1]), "+f"(c[2]), "+f"(c[3])
        : "r"(a[0]), "r"(a[1]), "r"(a[2]), "r"(a[3]), "r"(b0), "r"(b1));
}

// ---------------- scratch (device globals; no allocation) ----------------
__device__ float g_xw  [NTOK*CB];
__device__ float g_qkv0[NTOK*288];
__device__ float g_qkv1[NTOK*288];
__device__ float g_o0  [NTOK*CB];
__device__ float g_o1  [NTOK*CB];
__device__ float g_p0  [NTOK*CB];
__device__ float g_p1  [NTOK*CB];
__device__ float g_x1  [2*CB*SP];
__device__ float g_x2  [2*CB*SP];     // LN2(x1), tf32-rounded
__device__ float g_weff[9*CB*3*CB];   // [k][co], tf32-rounded
__device__ float g_beff[CB];
__device__ float g_bias[4*9*NTP*NTP]; // [class][head9][i][j]

// ---------------- LN1 + shift-roll + window partition ----------------
__global__ void k_ln1(const float* __restrict__ x,
                      const float* __restrict__ lw, const float* __restrict__ lb) {
    __shared__ float row[CB*WDIM];
    int bid = blockIdx.x;
    int h = bid % HDIM; int t = bid / HDIM; int d = t & 7; int bb = t >> 3;
    const float* base = x + (size_t)bb*CB*SP + d*HWs + h*WDIM;
    for (int i = threadIdx.x; i < CB*WDIM; i += blockDim.x) {
        int c = i / WDIM, w = i % WDIM;
        row[i] = base[(size_t)c*SP + w];
    }
    __syncthreads();
    if (threadIdx.x < WDIM) {
        int w = threadIdx.x;
        float mu = 0.f;
        for (int c = 0; c < CB; c++) mu += row[c*WDIM + w];
        mu *= (1.0f/CB);
        float var = 0.f;
        for (int c = 0; c < CB; c++) { float dv = row[c*WDIM + w] - mu; var += dv*dv; }
        var *= (1.0f/CB);
        float inv = rsqrtf(var + 1e-5f);
        int ds = (d + 4) & 7;
        int hs = h - 3; if (hs < 0) hs += HDIM;
        int ws = w - 3; if (ws < 0) ws += WDIM;
        int win = bb*64 + (hs/7)*8 + (ws/7);
        int n   = ds*49 + (hs%7)*7 + (ws%7);
        float* op = g_xw + ((size_t)win*NT + n)*CB;
        for (int c = 0; c < CB; c++)
            op[c] = (row[c*WDIM + w] - mu) * inv * lw[c] + lb[c];
    }
}

// ---------------- GEMM via tf32 mma: Out[M,Ntot] = A[M,96]*W[Ntot,96]^T + bias
// block: 128 M x 96 N; 8 warps, warp = one m16 row x 12 n8 tiles. K=96.
#define ASTG 100   // As [m][k] stride
#define WSTG 104   // Ws [k][n] stride
__global__ void __launch_bounds__(256) k_gemm_mma(const float* __restrict__ A,
                                                  const float* __restrict__ W,
                                                  const float* __restrict__ bias,
                                                  float* __restrict__ Out, int Ntot) {
    extern __shared__ float sm[];
    float* As = sm;                 // 128*ASTG
    float* Ws = sm + 128*ASTG;      // 96*WSTG
    int m0 = blockIdx.x * 128;
    int n0 = blockIdx.y * 96;
    int tid = threadIdx.x, warp = tid >> 5, lane = tid & 31;
    int lg = lane >> 2, lq = lane & 3;

    // stage A tile [m][k] (tf32), coalesced float4
    for (int i = tid; i < 128*24; i += 256) {
        int r = i / 24, c4 = i % 24;
        float4 v = *(const float4*)(A + (size_t)(m0 + r)*CB + c4*4);
        v.x = to_tf32(v.x); v.y = to_tf32(v.y); v.z = to_tf32(v.z); v.w = to_tf32(v.w);
        *(float4*)(As + r*ASTG + c4*4) = v;
    }
    // stage W chunk transposed: Ws[k][n] = W[n0+n][k] (tf32)
    for (int i = tid; i < 96*24; i += 256) {
        int n = i / 24, c4 = i % 24;
        float4 v = *(const float4*)(W + (size_t)(n0 + n)*CB + c4*4);
        Ws[(c4*4+0)*WSTG + n] = to_tf32(v.x);
        Ws[(c4*4+1)*WSTG + n] = to_tf32(v.y);
        Ws[(c4*4+2)*WSTG + n] = to_tf32(v.z);
        Ws[(c4*4+3)*WSTG + n] = to_tf32(v.w);
    }
    __syncthreads();

    float c[12][4];
    #pragma unroll
    for (int nt = 0; nt < 12; nt++) { c[nt][0]=0.f; c[nt][1]=0.f; c[nt][2]=0.f; c[nt][3]=0.f; }

    const float* apb = As + (warp*16 + lg)*ASTG + lq;
    #pragma unroll
    for (int ks = 0; ks < 12; ks++) {
        int kb = ks*8;
        unsigned a[4];
        a[0] = __float_as_uint(apb[kb]);
        a[1] = __float_as_uint(apb[kb + 8*ASTG]);
        a[2] = __float_as_uint(apb[kb + 4]);
        a[3] = __float_as_uint(apb[kb + 8*ASTG + 4]);
        #pragma unroll
        for (int nt = 0; nt < 12; nt++) {
            const float* bp = Ws + (kb + lq)*WSTG + nt*8 + lg;
            unsigned b0 = __float_as_uint(bp[0]);
            unsigned b1 = __float_as_uint(bp[4*WSTG]);
            mma_tf32(c[nt], a, b0, b1);
        }
    }

    // epilogue: bias + store
    int mr0 = m0 + warp*16 + lg;
    #pragma unroll
    for (int nt = 0; nt < 12; nt++) {
        int nc = n0 + nt*8 + lq*2;
        float2 bv = *(const float2*)(bias + nc);
        *(float2*)(Out + (size_t)mr0*Ntot + nc)
            = make_float2(c[nt][0] + bv.x, c[nt][1] + bv.y);
        *(float2*)(Out + (size_t)(mr0 + 8)*Ntot + nc)
            = make_float2(c[nt][2] + bv.x, c[nt][3] + bv.y);
    }
}

// ---------------- bias+mask table precompute ----------------
__global__ void k_bias(const float* __restrict__ rpb0, const float* __restrict__ rpb1) {
    int bid = blockIdx.x;
    int i = bid % NTP; int rest = bid / NTP;
    int head = rest % 9; int cls = rest / 9;
    int j = threadIdx.x;
    float v;
    if (i >= NT || j >= NT) {
        v = -1e9f;
    } else {
        int dzi = i/49, ri = i%49, hyi = ri/7, wli = ri%7;
        int dzj = j/49, rj = j%49, hyj = rj/7, wlj = rj%7;
        int idx = (dzi - dzj + 7)*169 + (hyi - hyj + 6)*13 + (wli - wlj + 6);
        float b = (head < 3) ? rpb0[idx*3 + head] : rpb1[idx*6 + head - 3];
        int ha = cls >> 1, wa = cls & 1;
        int hri = ha ? (hyi < 4 ? 1 : 2) : 0;
        int wri = wa ? (wli < 4 ? 1 : 2) : 0;
        int hrj = ha ? (hyj < 4 ? 1 : 2) : 0;
        int wrj = wa ? (wlj < 4 ? 1 : 2) : 0;
        int li = (dzi < 4 ? 0 : 1)*9 + hri*3 + wri;
        int lj = (dzj < 4 ? 0 : 1)*9 + hrj*3 + wrj;
        v = b + ((li != lj) ? -100.f : 0.f);
    }
    g_bias[((size_t)(cls*9 + head)*NTP + i)*NTP + j] = v;
}

// ---------------- windowed attention: tf32 mma + flash softmax ---------------
template<int DH, int NH, int HOFF, int MAXB>
__global__ void __launch_bounds__(256, MAXB) k_attn_mma(const float* __restrict__ qkv,
                                                        float* __restrict__ outp) {
    constexpr int KST = 408;
    constexpr int VST = (DH == 32) ? 40 : 24;
    constexpr int PST = 84;
    constexpr int NKS = DH/8;
    constexpr int NVT = DH/8;
    extern __shared__ float sm[];
    float* Ksm = sm;
    float* Vsm = Ksm + DH*KST;
    float* Psm = Vsm + NTP*VST;

    int win = blockIdx.x / NH, hd = blockIdx.x % NH;
    const float* qb = qkv + (size_t)win*NT*288;
    int tid = threadIdx.x, warp = tid >> 5, lane = tid & 31;
    int lg = lane >> 2, lq = lane & 3;
    const float scale = rsqrtf((float)DH);

    for (int idx = tid; idx < NTP*(DH/4); idx += 256) {
        int n = idx / (DH/4), d4 = (idx % (DH/4))*4;
        if (n < NT) {
            float4 kv = *(const float4*)(qb + (size_t)n*288 + 96 + hd*DH + d4);
            Ksm[(d4+0)*KST + n] = to_tf32(kv.x);
            Ksm[(d4+1)*KST + n] = to_tf32(kv.y);
            Ksm[(d4+2)*KST + n] = to_tf32(kv.z);
            Ksm[(d4+3)*KST + n] = to_tf32(kv.w);
        } else {
            Ksm[(d4+0)*KST + n] = 0.f;
            Ksm[(d4+1)*KST + n] = 0.f;
            Ksm[(d4+2)*KST + n] = 0.f;
            Ksm[(d4+3)*KST + n] = 0.f;
        }
    }
    for (int idx = tid; idx < NTP*(DH/4); idx += 256) {
        int j = idx / (DH/4), d4 = (idx % (DH/4))*4;
        float4 vv = make_float4(0.f, 0.f, 0.f, 0.f);
        if (j < NT) {
            float4 t4 = *(const float4*)(qb + (size_t)j*288 + 192 + hd*DH + d4);
            vv = make_float4(to_tf32(t4.x), to_tf32(t4.y), to_tf32(t4.z), to_tf32(t4.w));
        }
        *(float4*)(Vsm + j*VST + d4) = vv;
    }
    __syncthreads();

    int cls = ((((win & 63) >> 3) == 7) ? 2 : 0) | (((win & 7) == 7) ? 1 : 0);
    const float* bias = g_bias + (size_t)(cls*9 + HOFF + hd)*(NTP*NTP);
    float* pwarp = Psm + warp*(16*PST);

    for (int tr = warp; tr < 25; tr += 8) {
        int i0 = tr*16;
        int r0 = i0 + lg;
        int r1 = min(i0 + lg + 8, NT - 1);
        unsigned qa[NKS][4];
        #pragma unroll
        for (int ks = 0; ks < NKS; ks++) {
            int d = ks*8 + lq;
            qa[ks][0] = __float_as_uint(to_tf32(qb[(size_t)r0*288 + hd*DH + d]     * scale));
            qa[ks][1] = __float_as_uint(to_tf32(qb[(size_t)r1*288 + hd*DH + d]     * scale));
            qa[ks][2] = __float_as_uint(to_tf32(qb[(size_t)r0*288 + hd*DH + d + 4] * scale));
            qa[ks][3] = __float_as_uint(to_tf32(qb[(size_t)r1*288 + hd*DH + d + 4] * scale));
        }
        float m0 = -1e30f, m1 = -1e30f, l0 = 0.f, l1 = 0.f;
        float O[NVT][4];
        #pragma unroll
        for (int nt = 0; nt < NVT; nt++) { O[nt][0]=0.f; O[nt][1]=0.f; O[nt][2]=0.f; O[nt][3]=0.f; }

        #pragma unroll
        for (int ch = 0; ch < 5; ch++) {
            int j0 = ch*80;
            float c[10][4];
            #pragma unroll
            for (int nt = 0; nt < 10; nt++) { c[nt][0]=0.f; c[nt][1]=0.f; c[nt][2]=0.f; c[nt][3]=0.f; }
            #pragma unroll
            for (int ks = 0; ks < NKS; ks++) {
                #pragma unroll
                for (int nt = 0; nt < 10; nt++) {
                    const float* bp = Ksm + (ks*8 + lq)*KST + j0 + nt*8 + lg;
                    unsigned b0 = __float_as_uint(bp[0]);
                    unsigned b1 = __float_as_uint(bp[4*KST]);
                    mma_tf32(c[nt], qa[ks], b0, b1);
                }
            }
            #pragma unroll
            for (int nt = 0; nt < 10; nt++) {
                const float* br0 = bias + (size_t)(i0 + lg)*NTP + j0 + nt*8 + lq*2;
                float2 b0v = *(const float2*)br0;
                float2 b1v = *(const float2*)(br0 + 8*NTP);
                c[nt][0] += b0v.x; c[nt][1] += b0v.y;
                c[nt][2] += b1v.x; c[nt][3] += b1v.y;
            }
            float cm0 = -1e30f, cm1 = -1e30f;
            #pragma unroll
            for (int nt = 0; nt < 10; nt++) {
                cm0 = fmaxf(cm0, fmaxf(c[nt][0], c[nt][1]));
                cm1 = fmaxf(cm1, fmaxf(c[nt][2], c[nt][3]));
            }
            cm0 = fmaxf(cm0, __shfl_xor_sync(0xffffffffu, cm0, 1));
            cm0 = fmaxf(cm0, __shfl_xor_sync(0xffffffffu, cm0, 2));
            cm1 = fmaxf(cm1, __shfl_xor_sync(0xffffffffu, cm1, 1));
            cm1 = fmaxf(cm1, __shfl_xor_sync(0xffffffffu, cm1, 2));
            float mn0 = fmaxf(m0, cm0), mn1 = fmaxf(m1, cm1);
            float s0 = __expf(m0 - mn0), s1 = __expf(m1 - mn1);
            m0 = mn0; m1 = mn1;
            l0 *= s0; l1 *= s1;
            #pragma unroll
            for (int nt = 0; nt < NVT; nt++) {
                O[nt][0] *= s0; O[nt][1] *= s0;
                O[nt][2] *= s1; O[nt][3] *= s1;
            }
            float sum0 = 0.f, sum1 = 0.f;
            #pragma unroll
            for (int nt = 0; nt < 10; nt++) {
                c[nt][0] = to_tf32(__expf(c[nt][0] - m0)); sum0 += c[nt][0];
                c[nt][1] = to_tf32(__expf(c[nt][1] - m0)); sum0 += c[nt][1];
                c[nt][2] = to_tf32(__expf(c[nt][2] - m1)); sum1 += c[nt][2];
                c[nt][3] = to_tf32(__expf(c[nt][3] - m1)); sum1 += c[nt][3];
            }
            sum0 += __shfl_xor_sync(0xffffffffu, sum0, 1);
            sum0 += __shfl_xor_sync(0xffffffffu, sum0, 2);
            sum1 += __shfl_xor_sync(0xffffffffu, sum1, 1);
            sum1 += __shfl_xor_sync(0xffffffffu, sum1, 2);
            l0 += sum0; l1 += sum1;
            #pragma unroll
            for (int nt = 0; nt < 10; nt++) {
                int jl = nt*8 + lq*2;
                *(float2*)(pwarp + lg*PST + jl)     = make_float2(c[nt][0], c[nt][1]);
                *(float2*)(pwarp + (lg+8)*PST + jl) = make_float2(c[nt][2], c[nt][3]);
            }
            __syncwarp();
            #pragma unroll
            for (int ks = 0; ks < 10; ks++) {
                unsigned pa[4];
                const float* pp = pwarp + lg*PST + ks*8 + lq;
                pa[0] = __float_as_uint(pp[0]);
                pa[1] = __float_as_uint(pp[8*PST]);
                pa[2] = __float_as_uint(pp[4]);
                pa[3] = __float_as_uint(pp[8*PST + 4]);
                #pragma unroll
                for (int nt = 0; nt < NVT; nt++) {
                    const float* vp = Vsm + (j0 + ks*8 + lq)*VST + nt*8 + lg;
                    unsigned b0 = __float_as_uint(vp[0]);
                    unsigned b1 = __float_as_uint(vp[4*VST]);
                    mma_tf32(O[nt], pa, b0, b1);
                }
            }
            __syncwarp();
        }
        float li0 = 1.f / l0, li1 = 1.f / l1;
        int ir0 = i0 + lg, ir1 = i0 + lg + 8;
        #pragma unroll
        for (int nt = 0; nt < NVT; nt++) {
            *(float2*)(outp + ((size_t)win*NT + ir0)*CB + hd*DH + nt*8 + lq*2)
                = make_float2(O[nt][0]*li0, O[nt][1]*li0);
            if (ir1 < NT)
                *(float2*)(outp + ((size_t)win*NT + ir1)*CB + hd*DH + nt*8 + lq*2)
                    = make_float2(O[nt][2]*li1, O[nt][3]*li1);
        }
    }
}

// ---------------- NAS mix + window reverse + unroll + residual ----------------
__global__ void k_combine(const float* __restrict__ x, const float* __restrict__ alpha) {
    int tok = blockIdx.x, c = threadIdx.x;
    float a0 = alpha[0], a1 = alpha[1];
    float m  = fmaxf(a0, a1);
    float e0 = __expf(a0 - m), e1 = __expf(a1 - m);
    float inv = 1.f / (e0 + e1);
    float aw0 = e0*inv, aw1 = e1*inv;
    int win = tok / NT, n = tok % NT;
    int bb = win >> 6; int whi = (win & 63) >> 3, wwi = win & 7;
    int dz = n/49, r = n%49, hy = r/7, wl = r%7;
    int hs = whi*7 + hy, ws = wwi*7 + wl;
    int d0 = (dz + 4) & 7;
    int h0 = hs + 3; if (h0 >= HDIM) h0 -= HDIM;
    int w0 = ws + 3; if (w0 >= WDIM) w0 -= WDIM;
    size_t oi = ((size_t)(bb*CB + c)*DDIM + d0)*HWs + h0*WDIM + w0;
    size_t ti = (size_t)tok*CB + c;
    g_x1[oi] = x[oi] + aw0*g_p0[ti] + aw1*g_p1[ti];
}

// ---------------- LN2 (writes tf32-rounded x2) ----------------
__global__ void k_ln2(const float* __restrict__ lw, const float* __restrict__ lb) {
    __shared__ float row[CB*WDIM];
    __shared__ float s_mu[WDIM], s_inv[WDIM];
    int bid = blockIdx.x;
    int h = bid % HDIM; int t = bid / HDIM; int d = t & 7; int bb = t >> 3;
    size_t base = (size_t)bb*CB*SP + d*HWs + h*WDIM;
    for (int i = threadIdx.x; i < CB*WDIM; i += blockDim.x)
        row[i] = g_x1[base + (size_t)(i/WDIM)*SP + (i%WDIM)];
    __syncthreads();
    if (threadIdx.x < WDIM) {
        int w = threadIdx.x;
        float mu = 0.f;
        for (int c = 0; c < CB; c++) mu += row[c*WDIM + w];
        mu *= (1.0f/CB);
        float var = 0.f;
        for (int c = 0; c < CB; c++) { float dv = row[c*WDIM + w] - mu; var += dv*dv; }
        var *= (1.0f/CB);
        s_mu[w] = mu; s_inv[w] = rsqrtf(var + 1e-5f);
    }
    __syncthreads();
    for (int i = threadIdx.x; i < CB*WDIM; i += blockDim.x) {
        int c = i / WDIM, w = i % WDIM;
        g_x2[base + (size_t)c*SP + w] =
            to_tf32((row[i] - s_mu[w]) * s_inv[w] * lw[c] + lb[c]);
    }
}

// ---------------- build effective conv weights (NAS fold, tf32-rounded) ------
__global__ void k_weff(const float* __restrict__ c3w, const float* __restrict__ c3b,
                       const float* __restrict__ c1w, const float* __restrict__ c1b,
                       const float* __restrict__ dww, const float* __restrict__ dwb,
                       const float* __restrict__ alpha) {
    float a[4]; float m = -1e30f;
    #pragma unroll
    for (int i = 0; i < 4; i++) { a[i] = alpha[i]; m = fmaxf(m, a[i]); }
    float s = 0.f;
    #pragma unroll
    for (int i = 0; i < 4; i++) { a[i] = __expf(a[i] - m); s += a[i]; }
    float inv = 1.f / s;
    #pragma unroll
    for (int i = 0; i < 4; i++) a[i] *= inv;
    int total = CB*CB*27;
    for (int idx = blockIdx.x*blockDim.x + threadIdx.x; idx < total; idx += gridDim.x*blockDim.x) {
        int t = idx % 27; int rest = idx / 27; int ci = rest % CB; int co = rest / CB;
        float val = a[0] * c3w[idx];
        if (t == 13)            val += a[1] * c1w[co*CB + ci];
        if (ci == co)           val += a[2] * dww[co*27 + t];
        if (t == 13 && ci == co) val += a[3];
        int tt = t / 3, tw = t % 3;
        g_weff[(((size_t)tt*CB + ci)*3 + tw)*CB + co] = to_tf32(val);
    }
    int gid = blockIdx.x*blockDim.x + threadIdx.x;
    if (gid < CB) g_beff[gid] = a[0]*c3b[gid] + a[1]*c1b[gid] + a[2]*dwb[gid];
}

// ---------------- FFN as tf32 implicit-GEMM mma + residual -------------------
#define KCH 32
#define AST 104
#define BST 232

__global__ void __launch_bounds__(256) k_ffn_mma(float* __restrict__ out) {
    __shared__ float As[KCH*AST];
    __shared__ float Bs[KCH*BST];

    int bid = blockIdx.x;
    int h4 = bid % 14; int t = bid / 14; int d = t & 7; int bb = t >> 3;
    int h0 = h4*4;
    int tid = threadIdx.x;
    int warp = tid >> 5, lane = tid & 31;
    int wm = warp >> 2, wn = warp & 3;
    int lg = lane >> 2, lq = lane & 3;

    float acc[3][7][4];
    #pragma unroll
    for (int mt = 0; mt < 3; mt++) {
        int m = wm*48 + mt*16 + lg;
        float b0 = g_beff[m], b8 = g_beff[m + 8];
        #pragma unroll
        for (int nt = 0; nt < 7; nt++) {
            acc[mt][nt][0] = b0; acc[mt][nt][1] = b0;
            acc[mt][nt][2] = b8; acc[mt][nt][3] = b8;
        }
    }

    int kk = tid >> 3, nlane = tid & 7;

    for (int kc = 0; kc < 81; kc++) {
        __syncthreads();
        #pragma unroll
        for (int s = 0; s < 12; s++) {
            int i = tid + s*256;
            int k = i / 96, co = i % 96;
            As[k*AST + co] = g_weff[(size_t)(kc*KCH + k)*CB + co];
        }
        {
            int kg = kc*KCH + kk;
            int tt = kg / 288; int r = kg % 288; int ci = r / 3; int tw = r % 3;
            int td = tt / 3, th = tt % 3;
            int sd = d + td - 1;
            bool dok = (unsigned)sd < 8u;
            const float* rowp[4]; bool rok[4];
            #pragma unroll
            for (int hr = 0; hr < 4; hr++) {
                int sh = h0 + hr + th - 1;
                rok[hr] = dok && (unsigned)sh < 56u;
                rowp[hr] = g_x2 + ((size_t)(bb*CB + ci)*DDIM + sd)*HWs + sh*WDIM + (tw - 1);
            }
            float* bdst = Bs + kk*BST;
            #pragma unroll
            for (int j = 0; j < 28; j++) {
                const int hr = (j*8) / 56;
                const int wb = (j*8) % 56;
                int w = wb + nlane;
                bool ok = rok[hr] && ((unsigned)(w + tw - 1) < 56u);
                bdst[j*8 + nlane] = ok ? rowp[hr][w] : 0.f;
            }
        }
        __syncthreads();
        #pragma unroll
        for (int k8 = 0; k8 < 4; k8++) {
            int kb = k8*8;
            unsigned a[3][4];
            #pragma unroll
            for (int mt = 0; mt < 3; mt++) {
                const float* ap = As + (kb + lq)*AST + wm*48 + mt*16 + lg;
                a[mt][0] = __float_as_uint(ap[0]);
                a[mt][1] = __float_as_uint(ap[8]);
                a[mt][2] = __float_as_uint(ap[4*AST]);
                a[mt][3] = __float_as_uint(ap[4*AST + 8]);
            }
            #pragma unroll
            for (int nt = 0; nt < 7; nt++) {
                const float* bp = Bs + (kb + lq)*BST + wn*56 + nt*8 + lg;
                unsigned b0 = __float_as_uint(bp[0]);
                unsigned b1 = __float_as_uint(bp[4*BST]);
                mma_tf32(acc[0][nt], a[0], b0, b1);
                mma_tf32(acc[1][nt], a[1], b0, b1);
                mma_tf32(acc[2][nt], a[2], b0, b1);
            }
        }
    }

    int hrow = h0 + wn;
    #pragma unroll
    for (int mt = 0; mt < 3; mt++) {
        int m = wm*48 + mt*16 + lg;
        size_t base = ((size_t)(bb*CB + m)*DDIM + d)*HWs + hrow*WDIM;
        #pragma unroll
        for (int nt = 0; nt < 7; nt++) {
            int w0 = nt*8 + lq*2;
            size_t i0 = base + w0;
            size_t i1 = i0 + (size_t)8*SP;
            float2 r0 = *(const float2*)(g_x1 + i0);
            float2 r1 = *(const float2*)(g_x1 + i1);
            float2 o0 = make_float2(r0.x + acc[mt][nt][0], r0.y + acc[mt][nt][1]);
            float2 o1 = make_float2(r1.x + acc[mt][nt][2], r1.y + acc[mt][nt][3]);
            *(float2*)(out + i0) = o0;
            *(float2*)(out + i1) = o1;
        }
    }
}

// ---------------- host launch ----------------
extern "C" void kernel_launch(void* const* d_in, const int* in_sizes, int n_in,
                              void* d_out, int out_size) {
    (void)in_sizes; (void)n_in; (void)out_size;
    const float* x      = (const float*)d_in[0];
    const float* ln1w   = (const float*)d_in[1];
    const float* ln1b   = (const float*)d_in[2];
    const float* ln2w   = (const float*)d_in[3];
    const float* ln2b   = (const float*)d_in[4];
    const float* qkvw0  = (const float*)d_in[5];
    const float* qkvb0  = (const float*)d_in[6];
    const float* projw0 = (const float*)d_in[7];
    const float* projb0 = (const float*)d_in[8];
    const float* rpb0   = (const float*)d_in[9];
    const float* qkvw1  = (const float*)d_in[10];
    const float* qkvb1  = (const float*)d_in[11];
    const float* projw1 = (const float*)d_in[12];
    const float* projb1 = (const float*)d_in[13];
    const float* rpb1   = (const float*)d_in[14];
    const float* alphaA = (const float*)d_in[15];
    const float* c3w    = (const float*)d_in[16];
    const float* c3b    = (const float*)d_in[17];
    const float* c1w    = (const float*)d_in[18];
    const float* c1b    = (const float*)d_in[19];
    const float* dww    = (const float*)d_in[20];
    const float* dwb    = (const float*)d_in[21];
    const float* alphaF = (const float*)d_in[22];
    float* out = (float*)d_out;

    float *p_xw, *p_q0, *p_q1, *p_o0, *p_o1, *p_p0, *p_p1;
    cudaGetSymbolAddress((void**)&p_xw, g_xw);
    cudaGetSymbolAddress((void**)&p_q0, g_qkv0);
    cudaGetSymbolAddress((void**)&p_q1, g_qkv1);
    cudaGetSymbolAddress((void**)&p_o0, g_o0);
    cudaGetSymbolAddress((void**)&p_o1, g_o1);
    cudaGetSymbolAddress((void**)&p_p0, g_p0);
    cudaGetSymbolAddress((void**)&p_p1, g_p1);

    int smG  = (128*ASTG + 96*WSTG) * 4;          // 91136 B
    int smA0 = (32*408 + NTP*40 + 8*16*84) * 4;   // 159232 B
    int smA1 = (16*408 + NTP*24 + 8*16*84) * 4;   // 107520 B
    cudaFuncSetAttribute((const void*)k_gemm_mma,
                         cudaFuncAttributeMaxDynamicSharedMemorySize, smG);
    cudaFuncSetAttribute((const void*)k_attn_mma<32,3,0,1>,
                         cudaFuncAttributeMaxDynamicSharedMemorySize, smA0);
    cudaFuncSetAttribute((const void*)k_attn_mma<16,6,3,2>,
                         cudaFuncAttributeMaxDynamicSharedMemorySize, smA1);

    // 0) bias+mask table
    k_bias<<<4*9*NTP, NTP>>>(rpb0, rpb1);

    // 1) LN1 + roll + window partition
    k_ln1<<<2*DDIM*HDIM, 256>>>(x, ln1w, ln1b);

    // 2) QKV GEMMs (tf32 mma)
    dim3 gq(NTOK/128, 3);
    k_gemm_mma<<<gq, 256, smG>>>(p_xw, qkvw0, qkvb0, p_q0, 288);
    k_gemm_mma<<<gq, 256, smG>>>(p_xw, qkvw1, qkvb1, p_q1, 288);

    // 3) windowed attention (tf32 mma, flash softmax)
    k_attn_mma<32,3,0,1><<<NWIN*3, 256, smA0>>>(p_q0, p_o0);
    k_attn_mma<16,6,3,2><<<NWIN*6, 256, smA1>>>(p_q1, p_o1);

    // 4) output projections (tf32 mma)
    dim3 gp(NTOK/128, 1);
    k_gemm_mma<<<gp, 256, smG>>>(p_o0, projw0, projb0, p_p0, 96);
    k_gemm_mma<<<gp, 256, smG>>>(p_o1, projw1, projb1, p_p1, 96);

    // 5) NAS mix + window reverse + un-roll + residual
    k_combine<<<NTOK, CB>>>(x, alphaA);

    // 6) LN2 (tf32-rounded output)
    k_ln2<<<2*DDIM*HDIM, 256>>>(ln2w, ln2b);

    // 7) effective conv weights (tf32) + tensor-core FFN + residual
    k_weff<<<128, 256>>>(c3w, c3b, c1w, c1b, dww, dwb, alphaF);
    k_ffn_mma<<<2*DDIM*(HDIM/4), 256>>>(out);
}

// round 11
// speedup vs baseline: 3.1142x; 1.1039x over previous
#include <cuda_runtime.h>
#include <cstdint>

#define CB 96
#define DDIM 8
#define HDIM 56
#define WDIM 56
#define SP   (DDIM*HDIM*WDIM)   // 25088
#define HWs  (HDIM*WDIM)        // 3136
#define NT   392                // tokens per window
#define NTP  400                // padded tokens
#define NWIN 128                // total windows (B=2, 64 per batch)
#define NTOK (NWIN*NT)          // 50176

__device__ __forceinline__ float to_tf32(float x) {
    unsigned u;
    asm("cvt.rna.tf32.f32 %0, %1;" : "=r"(u) : "f"(x));
    return __uint_as_float(u);
}

__device__ __forceinline__ void mma_tf32(float* c, const unsigned* a, unsigned b0, unsigned b1) {
    asm volatile(
        "mma.sync.aligned.m16n8k8.row.col.f32.tf32.tf32.f32 "
        "{%0,%1,%2,%3}, {%4,%5,%6,%7}, {%8,%9}, {%0,%1,%2,%3};\n"
        : "+f"(c[0]), "+f"(c[1]), "+f"(c[2]), "+f"(c[3])
        : "r"(a[0]), "r"(a[1]), "r"(a[2]), "r"(a[3]), "r"(b0), "r"(b1));
}

// token id -> spatial base offset (window reverse + un-roll), channel 0
__device__ __forceinline__ size_t tok_to_spatial(int t) {
    int win = t / NT, n = t % NT;
    int bb = win >> 6; int whi = (win & 63) >> 3, wwi = win & 7;
    int dz = n/49, r = n%49, hy = r/7, wl = r%7;
    int hs = whi*7 + hy, ws = wwi*7 + wl;
    int d0 = (dz + 4) & 7;
    int h0 = hs + 3; if (h0 >= HDIM) h0 -= HDIM;
    int w0 = ws + 3; if (w0 >= WDIM) w0 -= WDIM;
    return (size_t)bb*CB*SP + (size_t)d0*HWs + h0*WDIM + w0;
}

// ---------------- scratch (device globals; no allocation) ----------------
__device__ float g_xw  [NTOK*CB];
__device__ float g_qkv0[NTOK*288];
__device__ float g_qkv1[NTOK*288];
__device__ float g_o0  [NTOK*CB];
__device__ float g_o1  [NTOK*CB];
__device__ float g_x1  [2*CB*SP];
__device__ float g_x2  [2*CB*SP];     // LN2(x1), tf32-rounded
__device__ float g_weff[9*CB*3*CB];   // [k][co], tf32-rounded
__device__ float g_beff[CB];
__device__ float g_bias[4*9*NTP*NTP]; // [class][head9][i][j]

// ---------------- LN1 + shift-roll + window partition (v2) ----------------
__global__ void k_ln1(const float* __restrict__ x,
                      const float* __restrict__ lw, const float* __restrict__ lb) {
    __shared__ float row[WDIM*97];
    __shared__ float s_mu[WDIM], s_ri[WDIM];
    int bid = blockIdx.x;
    int h = bid % HDIM; int t = bid / HDIM; int d = t & 7; int bb = t >> 3;
    const float* base = x + (size_t)bb*CB*SP + d*HWs + h*WDIM;
    // phase 1: load transposed [w][c]
    for (int i = threadIdx.x; i < CB*WDIM; i += 256) {
        int c = i / WDIM, w = i % WDIM;
        row[w*97 + c] = base[(size_t)c*SP + w];
    }
    __syncthreads();
    // phase 2: per-w stats, quad-parallel
    if (threadIdx.x < 4*WDIM) {
        int w = threadIdx.x >> 2, part = threadIdx.x & 3;
        float s = 0.f, s2 = 0.f;
        const float* rp = row + w*97 + part*24;
        #pragma unroll 6
        for (int k = 0; k < 24; k++) { float v = rp[k]; s += v; s2 += v*v; }
        s  += __shfl_xor_sync(0xffffffffu, s, 1);  s  += __shfl_xor_sync(0xffffffffu, s, 2);
        s2 += __shfl_xor_sync(0xffffffffu, s2, 1); s2 += __shfl_xor_sync(0xffffffffu, s2, 2);
        if (part == 0) {
            float mu = s * (1.0f/CB);
            s_mu[w] = mu;
            s_ri[w] = rsqrtf(s2 * (1.0f/CB) - mu*mu + 1e-5f);
        }
    }
    __syncthreads();
    // phase 3: token-major coalesced write
    int ds = (d + 4) & 7;
    for (int i = threadIdx.x; i < CB*WDIM; i += 256) {
        int w = i / CB, c = i % CB;
        int hs = h - 3; if (hs < 0) hs += HDIM;
        int ws = w - 3; if (ws < 0) ws += WDIM;
        int win = bb*64 + (hs/7)*8 + (ws/7);
        int n   = ds*49 + (hs%7)*7 + (ws%7);
        g_xw[((size_t)win*NT + n)*CB + c] =
            (row[w*97 + c] - s_mu[w]) * s_ri[w] * lw[c] + lb[c];
    }
}

// ---------------- GEMM via tf32 mma (v2: A direct from global) --------------
// block: 128 M x 96 N; 8 warps; warp = m16 row x 12 n8 tiles. K=96.
#define WSTG 104   // Ws [k][n] stride
__global__ void __launch_bounds__(256) k_gemm_mma(const float* __restrict__ A,
                                                  const float* __restrict__ W,
                                                  const float* __restrict__ bias,
                                                  float* __restrict__ Out, int Ntot) {
    extern __shared__ float sm[];
    float* Ws = sm;                 // 96*WSTG
    int m0 = blockIdx.x * 128;
    int n0 = blockIdx.y * 96;
    int tid = threadIdx.x, warp = tid >> 5, lane = tid & 31;
    int lg = lane >> 2, lq = lane & 3;

    for (int i = tid; i < 96*24; i += 256) {
        int n = i / 24, c4 = i % 24;
        float4 v = *(const float4*)(W + (size_t)(n0 + n)*CB + c4*4);
        Ws[(c4*4+0)*WSTG + n] = to_tf32(v.x);
        Ws[(c4*4+1)*WSTG + n] = to_tf32(v.y);
        Ws[(c4*4+2)*WSTG + n] = to_tf32(v.z);
        Ws[(c4*4+3)*WSTG + n] = to_tf32(v.w);
    }
    __syncthreads();

    float c[12][4];
    #pragma unroll
    for (int nt = 0; nt < 12; nt++) { c[nt][0]=0.f; c[nt][1]=0.f; c[nt][2]=0.f; c[nt][3]=0.f; }

    int r0 = m0 + warp*16 + lg;
    const float* ap0 = A + (size_t)r0*CB + lq;
    const float* ap1 = ap0 + 8*CB;
    #pragma unroll
    for (int ks = 0; ks < 12; ks++) {
        int kb = ks*8;
        unsigned a[4];
        a[0] = __float_as_uint(to_tf32(ap0[kb]));
        a[1] = __float_as_uint(to_tf32(ap1[kb]));
        a[2] = __float_as_uint(to_tf32(ap0[kb + 4]));
        a[3] = __float_as_uint(to_tf32(ap1[kb + 4]));
        #pragma unroll
        for (int nt = 0; nt < 12; nt++) {
            const float* bp = Ws + (kb + lq)*WSTG + nt*8 + lg;
            unsigned b0 = __float_as_uint(bp[0]);
            unsigned b1 = __float_as_uint(bp[4*WSTG]);
            mma_tf32(c[nt], a, b0, b1);
        }
    }

    #pragma unroll
    for (int nt = 0; nt < 12; nt++) {
        int nc = n0 + nt*8 + lq*2;
        float2 bv = *(const float2*)(bias + nc);
        *(float2*)(Out + (size_t)r0*Ntot + nc)
            = make_float2(c[nt][0] + bv.x, c[nt][1] + bv.y);
        *(float2*)(Out + (size_t)(r0 + 8)*Ntot + nc)
            = make_float2(c[nt][2] + bv.x, c[nt][3] + bv.y);
    }
}

// ---------------- bias+mask table precompute ----------------
__global__ void k_bias(const float* __restrict__ rpb0, const float* __restrict__ rpb1) {
    int bid = blockIdx.x;
    int i = bid % NTP; int rest = bid / NTP;
    int head = rest % 9; int cls = rest / 9;
    int j = threadIdx.x;
    float v;
    if (i >= NT || j >= NT) {
        v = -1e9f;
    } else {
        int dzi = i/49, ri = i%49, hyi = ri/7, wli = ri%7;
        int dzj = j/49, rj = j%49, hyj = rj/7, wlj = rj%7;
        int idx = (dzi - dzj + 7)*169 + (hyi - hyj + 6)*13 + (wli - wlj + 6);
        float b = (head < 3) ? rpb0[idx*3 + head] : rpb1[idx*6 + head - 3];
        int ha = cls >> 1, wa = cls & 1;
        int hri = ha ? (hyi < 4 ? 1 : 2) : 0;
        int wri = wa ? (wli < 4 ? 1 : 2) : 0;
        int hrj = ha ? (hyj < 4 ? 1 : 2) : 0;
        int wrj = wa ? (wlj < 4 ? 1 : 2) : 0;
        int li = (dzi < 4 ? 0 : 1)*9 + hri*3 + wri;
        int lj = (dzj < 4 ? 0 : 1)*9 + hrj*3 + wrj;
        v = b + ((li != lj) ? -100.f : 0.f);
    }
    g_bias[((size_t)(cls*9 + head)*NTP + i)*NTP + j] = v;
}

// ---------------- windowed attention: tf32 mma + flash softmax ---------------
template<int DH, int NH, int HOFF, int MAXB>
__global__ void __launch_bounds__(256, MAXB) k_attn_mma(const float* __restrict__ qkv,
                                                        float* __restrict__ outp) {
    constexpr int KST = 408;
    constexpr int VST = (DH == 32) ? 40 : 24;
    constexpr int PST = 84;
    constexpr int NKS = DH/8;
    constexpr int NVT = DH/8;
    extern __shared__ float sm[];
    float* Ksm = sm;
    float* Vsm = Ksm + DH*KST;
    float* Psm = Vsm + NTP*VST;

    int win = blockIdx.x / NH, hd = blockIdx.x % NH;
    const float* qb = qkv + (size_t)win*NT*288;
    int tid = threadIdx.x, warp = tid >> 5, lane = tid & 31;
    int lg = lane >> 2, lq = lane & 3;
    const float scale = rsqrtf((float)DH);

    for (int idx = tid; idx < NTP*(DH/4); idx += 256) {
        int n = idx / (DH/4), d4 = (idx % (DH/4))*4;
        if (n < NT) {
            float4 kv = *(const float4*)(qb + (size_t)n*288 + 96 + hd*DH + d4);
            Ksm[(d4+0)*KST + n] = to_tf32(kv.x);
            Ksm[(d4+1)*KST + n] = to_tf32(kv.y);
            Ksm[(d4+2)*KST + n] = to_tf32(kv.z);
            Ksm[(d4+3)*KST + n] = to_tf32(kv.w);
        } else {
            Ksm[(d4+0)*KST + n] = 0.f;
            Ksm[(d4+1)*KST + n] = 0.f;
            Ksm[(d4+2)*KST + n] = 0.f;
            Ksm[(d4+3)*KST + n] = 0.f;
        }
    }
    for (int idx = tid; idx < NTP*(DH/4); idx += 256) {
        int j = idx / (DH/4), d4 = (idx % (DH/4))*4;
        float4 vv = make_float4(0.f, 0.f, 0.f, 0.f);
        if (j < NT) {
            float4 t4 = *(const float4*)(qb + (size_t)j*288 + 192 + hd*DH + d4);
            vv = make_float4(to_tf32(t4.x), to_tf32(t4.y), to_tf32(t4.z), to_tf32(t4.w));
        }
        *(float4*)(Vsm + j*VST + d4) = vv;
    }
    __syncthreads();

    int cls = ((((win & 63) >> 3) == 7) ? 2 : 0) | (((win & 7) == 7) ? 1 : 0);
    const float* bias = g_bias + (size_t)(cls*9 + HOFF + hd)*(NTP*NTP);
    float* pwarp = Psm + warp*(16*PST);

    for (int tr = warp; tr < 25; tr += 8) {
        int i0 = tr*16;
        int r0 = i0 + lg;
        int r1 = min(i0 + lg + 8, NT - 1);
        unsigned qa[NKS][4];
        #pragma unroll
        for (int ks = 0; ks < NKS; ks++) {
            int d = ks*8 + lq;
            qa[ks][0] = __float_as_uint(to_tf32(qb[(size_t)r0*288 + hd*DH + d]     * scale));
            qa[ks][1] = __float_as_uint(to_tf32(qb[(size_t)r1*288 + hd*DH + d]     * scale));
            qa[ks][2] = __float_as_uint(to_tf32(qb[(size_t)r0*288 + hd*DH + d + 4] * scale));
            qa[ks][3] = __float_as_uint(to_tf32(qb[(size_t)r1*288 + hd*DH + d + 4] * scale));
        }
        float m0 = -1e30f, m1 = -1e30f, l0 = 0.f, l1 = 0.f;
        float O[NVT][4];
        #pragma unroll
        for (int nt = 0; nt < NVT; nt++) { O[nt][0]=0.f; O[nt][1]=0.f; O[nt][2]=0.f; O[nt][3]=0.f; }

        #pragma unroll
        for (int ch = 0; ch < 5; ch++) {
            int j0 = ch*80;
            float c[10][4];
            #pragma unroll
            for (int nt = 0; nt < 10; nt++) { c[nt][0]=0.f; c[nt][1]=0.f; c[nt][2]=0.f; c[nt][3]=0.f; }
            #pragma unroll
            for (int ks = 0; ks < NKS; ks++) {
                #pragma unroll
                for (int nt = 0; nt < 10; nt++) {
                    const float* bp = Ksm + (ks*8 + lq)*KST + j0 + nt*8 + lg;
                    unsigned b0 = __float_as_uint(bp[0]);
                    unsigned b1 = __float_as_uint(bp[4*KST]);
                    mma_tf32(c[nt], qa[ks], b0, b1);
                }
            }
            #pragma unroll
            for (int nt = 0; nt < 10; nt++) {
                const float* br0 = bias + (size_t)(i0 + lg)*NTP + j0 + nt*8 + lq*2;
                float2 b0v = *(const float2*)br0;
                float2 b1v = *(const float2*)(br0 + 8*NTP);
                c[nt][0] += b0v.x; c[nt][1] += b0v.y;
                c[nt][2] += b1v.x; c[nt][3] += b1v.y;
            }
            float cm0 = -1e30f, cm1 = -1e30f;
            #pragma unroll
            for (int nt = 0; nt < 10; nt++) {
                cm0 = fmaxf(cm0, fmaxf(c[nt][0], c[nt][1]));
                cm1 = fmaxf(cm1, fmaxf(c[nt][2], c[nt][3]));
            }
            cm0 = fmaxf(cm0, __shfl_xor_sync(0xffffffffu, cm0, 1));
            cm0 = fmaxf(cm0, __shfl_xor_sync(0xffffffffu, cm0, 2));
            cm1 = fmaxf(cm1, __shfl_xor_sync(0xffffffffu, cm1, 1));
            cm1 = fmaxf(cm1, __shfl_xor_sync(0xffffffffu, cm1, 2));
            float mn0 = fmaxf(m0, cm0), mn1 = fmaxf(m1, cm1);
            float s0 = __expf(m0 - mn0), s1 = __expf(m1 - mn1);
            m0 = mn0; m1 = mn1;
            l0 *= s0; l1 *= s1;
            #pragma unroll
            for (int nt = 0; nt < NVT; nt++) {
                O[nt][0] *= s0; O[nt][1] *= s0;
                O[nt][2] *= s1; O[nt][3] *= s1;
            }
            float sum0 = 0.f, sum1 = 0.f;
            #pragma unroll
            for (int nt = 0; nt < 10; nt++) {
                c[nt][0] = to_tf32(__expf(c[nt][0] - m0)); sum0 += c[nt][0];
                c[nt][1] = to_tf32(__expf(c[nt][1] - m0)); sum0 += c[nt][1];
                c[nt][2] = to_tf32(__expf(c[nt][2] - m1)); sum1 += c[nt][2];
                c[nt][3] = to_tf32(__expf(c[nt][3] - m1)); sum1 += c[nt][3];
            }
            sum0 += __shfl_xor_sync(0xffffffffu, sum0, 1);
            sum0 += __shfl_xor_sync(0xffffffffu, sum0, 2);
            sum1 += __shfl_xor_sync(0xffffffffu, sum1, 1);
            sum1 += __shfl_xor_sync(0xffffffffu, sum1, 2);
            l0 += sum0; l1 += sum1;
            #pragma unroll
            for (int nt = 0; nt < 10; nt++) {
                int jl = nt*8 + lq*2;
                *(float2*)(pwarp + lg*PST + jl)     = make_float2(c[nt][0], c[nt][1]);
                *(float2*)(pwarp + (lg+8)*PST + jl) = make_float2(c[nt][2], c[nt][3]);
            }
            __syncwarp();
            #pragma unroll
            for (int ks = 0; ks < 10; ks++) {
                unsigned pa[4];
                const float* pp = pwarp + lg*PST + ks*8 + lq;
                pa[0] = __float_as_uint(pp[0]);
                pa[1] = __float_as_uint(pp[8*PST]);
                pa[2] = __float_as_uint(pp[4]);
                pa[3] = __float_as_uint(pp[8*PST + 4]);
                #pragma unroll
                for (int nt = 0; nt < NVT; nt++) {
                    const float* vp = Vsm + (j0 + ks*8 + lq)*VST + nt*8 + lg;
                    unsigned b0 = __float_as_uint(vp[0]);
                    unsigned b1 = __float_as_uint(vp[4*VST]);
                    mma_tf32(O[nt], pa, b0, b1);
                }
            }
            __syncwarp();
        }
        float li0 = 1.f / l0, li1 = 1.f / l1;
        int ir0 = i0 + lg, ir1 = i0 + lg + 8;
        #pragma unroll
        for (int nt = 0; nt < NVT; nt++) {
            *(float2*)(outp + ((size_t)win*NT + ir0)*CB + hd*DH + nt*8 + lq*2)
                = make_float2(O[nt][0]*li0, O[nt][1]*li0);
            if (ir1 < NT)
                *(float2*)(outp + ((size_t)win*NT + ir1)*CB + hd*DH + nt*8 + lq*2)
                    = make_float2(O[nt][2]*li1, O[nt][3]*li1);
        }
    }
}

// ---------------- fused proj0+proj1 + NAS mix + reverse + residual + LN2 -----
// block: 128 tokens; 8 warps, warp = m16 rows x 12 n8 tiles (all 96 channels).
__global__ void __launch_bounds__(256) k_projmix(
    const float* __restrict__ o0, const float* __restrict__ o1,
    const float* __restrict__ pw0, const float* __restrict__ pb0,
    const float* __restrict__ pw1, const float* __restrict__ pb1,
    const float* __restrict__ lnw, const float* __restrict__ lnb,
    const float* __restrict__ alpha, const float* __restrict__ x) {
    extern __shared__ float sm[];
    float* Ws0 = sm;                 // 96*WSTG
    float* Ws1 = sm + 96*WSTG;
    int m0 = blockIdx.x * 128;
    int tid = threadIdx.x, warp = tid >> 5, lane = tid & 31;
    int lg = lane >> 2, lq = lane & 3;

    for (int i = tid; i < 96*24; i += 256) {
        int n = i / 24, c4 = i % 24;
        float4 v0 = *(const float4*)(pw0 + (size_t)n*CB + c4*4);
        Ws0[(c4*4+0)*WSTG + n] = to_tf32(v0.x);
        Ws0[(c4*4+1)*WSTG + n] = to_tf32(v0.y);
        Ws0[(c4*4+2)*WSTG + n] = to_tf32(v0.z);
        Ws0[(c4*4+3)*WSTG + n] = to_tf32(v0.w);
        float4 v1 = *(const float4*)(pw1 + (size_t)n*CB + c4*4);
        Ws1[(c4*4+0)*WSTG + n] = to_tf32(v1.x);
        Ws1[(c4*4+1)*WSTG + n] = to_tf32(v1.y);
        Ws1[(c4*4+2)*WSTG + n] = to_tf32(v1.z);
        Ws1[(c4*4+3)*WSTG + n] = to_tf32(v1.w);
    }
    __syncthreads();

    float c0[12][4], c1[12][4];
    #pragma unroll
    for (int nt = 0; nt < 12; nt++) {
        c0[nt][0]=0.f; c0[nt][1]=0.f; c0[nt][2]=0.f; c0[nt][3]=0.f;
        c1[nt][0]=0.f; c1[nt][1]=0.f; c1[nt][2]=0.f; c1[nt][3]=0.f;
    }

    int t0 = m0 + warp*16 + lg, t1 = t0 + 8;
    const float* a00 = o0 + (size_t)t0*CB + lq;
    const float* a01 = o0 + (size_t)t1*CB + lq;
    const float* a10 = o1 + (size_t)t0*CB + lq;
    const float* a11 = o1 + (size_t)t1*CB + lq;
    #pragma unroll
    for (int ks = 0; ks < 12; ks++) {
        int kb = ks*8;
        unsigned aA[4], aB[4];
        aA[0] = __float_as_uint(to_tf32(a00[kb]));
        aA[1] = __float_as_uint(to_tf32(a01[kb]));
        aA[2] = __float_as_uint(to_tf32(a00[kb + 4]));
        aA[3] = __float_as_uint(to_tf32(a01[kb + 4]));
        aB[0] = __float_as_uint(to_tf32(a10[kb]));
        aB[1] = __float_as_uint(to_tf32(a11[kb]));
        aB[2] = __float_as_uint(to_tf32(a10[kb + 4]));
        aB[3] = __float_as_uint(to_tf32(a11[kb + 4]));
        #pragma unroll
        for (int nt = 0; nt < 12; nt++) {
            const float* bp0 = Ws0 + (kb + lq)*WSTG + nt*8 + lg;
            mma_tf32(c0[nt], aA, __float_as_uint(bp0[0]), __float_as_uint(bp0[4*WSTG]));
            const float* bp1 = Ws1 + (kb + lq)*WSTG + nt*8 + lg;
            mma_tf32(c1[nt], aB, __float_as_uint(bp1[0]), __float_as_uint(bp1[4*WSTG]));
        }
    }

    // NAS attn mixture weights
    float al0 = alpha[0], al1 = alpha[1];
    float am = fmaxf(al0, al1);
    float e0 = __expf(al0 - am), e1 = __expf(al1 - am);
    float ai = 1.f / (e0 + e1);
    float aw0 = e0*ai, aw1 = e1*ai;

    // mix + proj bias -> c0 holds x_attn contribution
    #pragma unroll
    for (int nt = 0; nt < 12; nt++) {
        int cch = nt*8 + lq*2;
        float2 b0v = *(const float2*)(pb0 + cch);
        float2 b1v = *(const float2*)(pb1 + cch);
        c0[nt][0] = aw0*(c0[nt][0] + b0v.x) + aw1*(c1[nt][0] + b1v.x);
        c0[nt][1] = aw0*(c0[nt][1] + b0v.y) + aw1*(c1[nt][1] + b1v.y);
        c0[nt][2] = aw0*(c0[nt][2] + b0v.x) + aw1*(c1[nt][2] + b1v.x);
        c0[nt][3] = aw0*(c0[nt][3] + b0v.y) + aw1*(c1[nt][3] + b1v.y);
    }

    // residual: gather x at spatial positions
    size_t sb0 = tok_to_spatial(t0);
    size_t sb1 = tok_to_spatial(t1);
    #pragma unroll
    for (int nt = 0; nt < 12; nt++) {
        int cch = nt*8 + lq*2;
        c0[nt][0] += x[sb0 + (size_t)cch*SP];
        c0[nt][1] += x[sb0 + (size_t)(cch+1)*SP];
        c0[nt][2] += x[sb1 + (size_t)cch*SP];
        c0[nt][3] += x[sb1 + (size_t)(cch+1)*SP];
    }

    // LN2 stats over 96 channels per row (quad shfl reduce)
    float s0 = 0.f, q0 = 0.f, s1 = 0.f, q1 = 0.f;
    #pragma unroll
    for (int nt = 0; nt < 12; nt++) {
        s0 += c0[nt][0] + c0[nt][1];
        q0 += c0[nt][0]*c0[nt][0] + c0[nt][1]*c0[nt][1];
        s1 += c0[nt][2] + c0[nt][3];
        q1 += c0[nt][2]*c0[nt][2] + c0[nt][3]*c0[nt][3];
    }
    s0 += __shfl_xor_sync(0xffffffffu, s0, 1); s0 += __shfl_xor_sync(0xffffffffu, s0, 2);
    q0 += __shfl_xor_sync(0xffffffffu, q0, 1); q0 += __shfl_xor_sync(0xffffffffu, q0, 2);
    s1 += __shfl_xor_sync(0xffffffffu, s1, 1); s1 += __shfl_xor_sync(0xffffffffu, s1, 2);
    q1 += __shfl_xor_sync(0xffffffffu, q1, 1); q1 += __shfl_xor_sync(0xffffffffu, q1, 2);
    float mu0 = s0 * (1.0f/CB), mu1 = s1 * (1.0f/CB);
    float ri0 = rsqrtf(q0 * (1.0f/CB) - mu0*mu0 + 1e-5f);
    float ri1 = rsqrtf(q1 * (1.0f/CB) - mu1*mu1 + 1e-5f);

    // write x1 (pre-LN) and x2 (LN, tf32)
    #pragma unroll
    for (int nt = 0; nt < 12; nt++) {
        int cch = nt*8 + lq*2;
        float w0 = lnw[cch], w1 = lnw[cch+1];
        float b0 = lnb[cch], b1 = lnb[cch+1];
        g_x1[sb0 + (size_t)cch*SP]     = c0[nt][0];
        g_x1[sb0 + (size_t)(cch+1)*SP] = c0[nt][1];
        g_x1[sb1 + (size_t)cch*SP]     = c0[nt][2];
        g_x1[sb1 + (size_t)(cch+1)*SP] = c0[nt][3];
        g_x2[sb0 + (size_t)cch*SP]     = to_tf32((c0[nt][0] - mu0)*ri0*w0 + b0);
        g_x2[sb0 + (size_t)(cch+1)*SP] = to_tf32((c0[nt][1] - mu0)*ri0*w1 + b1);
        g_x2[sb1 + (size_t)cch*SP]     = to_tf32((c0[nt][2] - mu1)*ri1*w0 + b0);
        g_x2[sb1 + (size_t)(cch+1)*SP] = to_tf32((c0[nt][3] - mu1)*ri1*w1 + b1);
    }
}

// ---------------- build effective conv weights (NAS fold, tf32-rounded) ------
__global__ void k_weff(const float* __restrict__ c3w, const float* __restrict__ c3b,
                       const float* __restrict__ c1w, const float* __restrict__ c1b,
                       const float* __restrict__ dww, const float* __restrict__ dwb,
                       const float* __restrict__ alpha) {
    float a[4]; float m = -1e30f;
    #pragma unroll
    for (int i = 0; i < 4; i++) { a[i] = alpha[i]; m = fmaxf(m, a[i]); }
    float s = 0.f;
    #pragma unroll
    for (int i = 0; i < 4; i++) { a[i] = __expf(a[i] - m); s += a[i]; }
    float inv = 1.f / s;
    #pragma unroll
    for (int i = 0; i < 4; i++) a[i] *= inv;
    int total = CB*CB*27;
    for (int idx = blockIdx.x*blockDim.x + threadIdx.x; idx < total; idx += gridDim.x*blockDim.x) {
        int t = idx % 27; int rest = idx / 27; int ci = rest % CB; int co = rest / CB;
        float val = a[0] * c3w[idx];
        if (t == 13)            val += a[1] * c1w[co*CB + ci];
        if (ci == co)           val += a[2] * dww[co*27 + t];
        if (t == 13 && ci == co) val += a[3];
        int tt = t / 3, tw = t % 3;
        g_weff[(((size_t)tt*CB + ci)*3 + tw)*CB + co] = to_tf32(val);
    }
    int gid = blockIdx.x*blockDim.x + threadIdx.x;
    if (gid < CB) g_beff[gid] = a[0]*c3b[gid] + a[1]*c1b[gid] + a[2]*dwb[gid];
}

// ---------------- FFN as tf32 implicit-GEMM mma + residual -------------------
#define KCH 32
#define AST 104
#define BST 232

__global__ void __launch_bounds__(256) k_ffn_mma(float* __restrict__ out) {
    __shared__ float As[KCH*AST];
    __shared__ float Bs[KCH*BST];

    int bid = blockIdx.x;
    int h4 = bid % 14; int t = bid / 14; int d = t & 7; int bb = t >> 3;
    int h0 = h4*4;
    int tid = threadIdx.x;
    int warp = tid >> 5, lane = tid & 31;
    int wm = warp >> 2, wn = warp & 3;
    int lg = lane >> 2, lq = lane & 3;

    float acc[3][7][4];
    #pragma unroll
    for (int mt = 0; mt < 3; mt++) {
        int m = wm*48 + mt*16 + lg;
        float b0 = g_beff[m], b8 = g_beff[m + 8];
        #pragma unroll
        for (int nt = 0; nt < 7; nt++) {
            acc[mt][nt][0] = b0; acc[mt][nt][1] = b0;
            acc[mt][nt][2] = b8; acc[mt][nt][3] = b8;
        }
    }

    int kk = tid >> 3, nlane = tid & 7;

    for (int kc = 0; kc < 81; kc++) {
        __syncthreads();
        #pragma unroll
        for (int s = 0; s < 12; s++) {
            int i = tid + s*256;
            int k = i / 96, co = i % 96;
            As[k*AST + co] = g_weff[(size_t)(kc*KCH + k)*CB + co];
        }
        {
            int kg = kc*KCH + kk;
            int tt = kg / 288; int r = kg % 288; int ci = r / 3; int tw = r % 3;
            int td = tt / 3, th = tt % 3;
            int sd = d + td - 1;
            bool dok = (unsigned)sd < 8u;
            const float* rowp[4]; bool rok[4];
            #pragma unroll
            for (int hr = 0; hr < 4; hr++) {
                int sh = h0 + hr + th - 1;
                rok[hr] = dok && (unsigned)sh < 56u;
                rowp[hr] = g_x2 + ((size_t)(bb*CB + ci)*DDIM + sd)*HWs + sh*WDIM + (tw - 1);
            }
            float* bdst = Bs + kk*BST;
            #pragma unroll
            for (int j = 0; j < 28; j++) {
                const int hr = (j*8) / 56;
                const int wb = (j*8) % 56;
                int w = wb + nlane;
                bool ok = rok[hr] && ((unsigned)(w + tw - 1) < 56u);
                bdst[j*8 + nlane] = ok ? rowp[hr][w] : 0.f;
            }
        }
        __syncthreads();
        #pragma unroll
        for (int k8 = 0; k8 < 4; k8++) {
            int kb = k8*8;
            unsigned a[3][4];
            #pragma unroll
            for (int mt = 0; mt < 3; mt++) {
                const float* ap = As + (kb + lq)*AST + wm*48 + mt*16 + lg;
                a[mt][0] = __float_as_uint(ap[0]);
                a[mt][1] = __float_as_uint(ap[8]);
                a[mt][2] = __float_as_uint(ap[4*AST]);
                a[mt][3] = __float_as_uint(ap[4*AST + 8]);
            }
            #pragma unroll
            for (int nt = 0; nt < 7; nt++) {
                const float* bp = Bs + (kb + lq)*BST + wn*56 + nt*8 + lg;
                unsigned b0 = __float_as_uint(bp[0]);
                unsigned b1 = __float_as_uint(bp[4*BST]);
                mma_tf32(acc[0][nt], a[0], b0, b1);
                mma_tf32(acc[1][nt], a[1], b0, b1);
                mma_tf32(acc[2][nt], a[2], b0, b1);
            }
        }
    }

    int hrow = h0 + wn;
    #pragma unroll
    for (int mt = 0; mt < 3; mt++) {
        int m = wm*48 + mt*16 + lg;
        size_t base = ((size_t)(bb*CB + m)*DDIM + d)*HWs + hrow*WDIM;
        #pragma unroll
        for (int nt = 0; nt < 7; nt++) {
            int w0 = nt*8 + lq*2;
            size_t i0 = base + w0;
            size_t i1 = i0 + (size_t)8*SP;
            float2 r0 = *(const float2*)(g_x1 + i0);
            float2 r1 = *(const float2*)(g_x1 + i1);
            float2 o0 = make_float2(r0.x + acc[mt][nt][0], r0.y + acc[mt][nt][1]);
            float2 o1 = make_float2(r1.x + acc[mt][nt][2], r1.y + acc[mt][nt][3]);
            *(float2*)(out + i0) = o0;
            *(float2*)(out + i1) = o1;
        }
    }
}

// ---------------- host launch ----------------
extern "C" void kernel_launch(void* const* d_in, const int* in_sizes, int n_in,
                              void* d_out, int out_size) {
    (void)in_sizes; (void)n_in; (void)out_size;
    const float* x      = (const float*)d_in[0];
    const float* ln1w   = (const float*)d_in[1];
    const float* ln1b   = (const float*)d_in[2];
    const float* ln2w   = (const float*)d_in[3];
    const float* ln2b   = (const float*)d_in[4];
    const float* qkvw0  = (const float*)d_in[5];
    const float* qkvb0  = (const float*)d_in[6];
    const float* projw0 = (const float*)d_in[7];
    const float* projb0 = (const float*)d_in[8];
    const float* rpb0   = (const float*)d_in[9];
    const float* qkvw1  = (const float*)d_in[10];
    const float* qkvb1  = (const float*)d_in[11];
    const float* projw1 = (const float*)d_in[12];
    const float* projb1 = (const float*)d_in[13];
    const float* rpb1   = (const float*)d_in[14];
    const float* alphaA = (const float*)d_in[15];
    const float* c3w    = (const float*)d_in[16];
    const float* c3b    = (const float*)d_in[17];
    const float* c1w    = (const float*)d_in[18];
    const float* c1b    = (const float*)d_in[19];
    const float* dww    = (const float*)d_in[20];
    const float* dwb    = (const float*)d_in[21];
    const float* alphaF = (const float*)d_in[22];
    float* out = (float*)d_out;

    float *p_xw, *p_q0, *p_q1, *p_o0, *p_o1;
    cudaGetSymbolAddress((void**)&p_xw, g_xw);
    cudaGetSymbolAddress((void**)&p_q0, g_qkv0);
    cudaGetSymbolAddress((void**)&p_q1, g_qkv1);
    cudaGetSymbolAddress((void**)&p_o0, g_o0);
    cudaGetSymbolAddress((void**)&p_o1, g_o1);

    int smG  = (96*WSTG) * 4;                     // 39936 B
    int smP  = (2*96*WSTG) * 4;                   // 79872 B
    int smA0 = (32*408 + NTP*40 + 8*16*84) * 4;   // 159232 B
    int smA1 = (16*408 + NTP*24 + 8*16*84) * 4;   // 107520 B
    cudaFuncSetAttribute((const void*)k_gemm_mma,
                         cudaFuncAttributeMaxDynamicSharedMemorySize, smG);
    cudaFuncSetAttribute((const void*)k_projmix,
                         cudaFuncAttributeMaxDynamicSharedMemorySize, smP);
    cudaFuncSetAttribute((const void*)k_attn_mma<32,3,0,1>,
                         cudaFuncAttributeMaxDynamicSharedMemorySize, smA0);
    cudaFuncSetAttribute((const void*)k_attn_mma<16,6,3,2>,
                         cudaFuncAttributeMaxDynamicSharedMemorySize, smA1);

    // 0) bias+mask table
    k_bias<<<4*9*NTP, NTP>>>(rpb0, rpb1);

    // 1) LN1 + roll + window partition
    k_ln1<<<2*DDIM*HDIM, 256>>>(x, ln1w, ln1b);

    // 2) QKV GEMMs (tf32 mma, A direct)
    dim3 gq(NTOK/128, 3);
    k_gemm_mma<<<gq, 256, smG>>>(p_xw, qkvw0, qkvb0, p_q0, 288);
    k_gemm_mma<<<gq, 256, smG>>>(p_xw, qkvw1, qkvb1, p_q1, 288);

    // 3) windowed attention (tf32 mma, flash softmax)
    k_attn_mma<32,3,0,1><<<NWIN*3, 256, smA0>>>(p_q0, p_o0);
    k_attn_mma<16,6,3,2><<<NWIN*6, 256, smA1>>>(p_q1, p_o1);

    // 4) fused proj + mix + reverse + residual + LN2
    k_projmix<<<NTOK/128, 256, smP>>>(p_o0, p_o1, projw0, projb0, projw1, projb1,
                                      ln2w, ln2b, alphaA, x);

    // 5) effective conv weights (tf32) + tensor-core FFN + residual
    k_weff<<<128, 256>>>(c3w, c3b, c1w, c1b, dww, dwb, alphaF);
    k_ffn_mma<<<2*DDIM*(HDIM/4), 256>>>(out);
}